// round 1
// baseline (speedup 1.0000x reference)
#include <cuda_runtime.h>
#include <math.h>

#define NN 16384
#define EE 131072
#define GG 32
#define BN_EPS 1e-5f

// ---------------- scratch (device globals: no allocation allowed) ----------
__device__ float g_bufA[NN * 1024];   // GAT hidden hg [N,1024]  (64 MB)
__device__ float g_bufB[NN * 512];    // xw / agg buffers        (32 MB)
__device__ float g_bufC[NN * 512];    // pre-BN buffers          (32 MB)
__device__ float g_bufD[NN * 512];    // post-BN (layer output)  (32 MB)
__device__ float g_es[NN * 4];
__device__ float g_ed[NN * 4];
__device__ int   g_deg[NN];
__device__ int   g_rowptr[NN + 1];
__device__ int   g_cursor[NN];
__device__ int   g_csr[EE];
__device__ float g_dis[NN];
__device__ float g_bnsum[512];
__device__ float g_bnsq[512];
__device__ float g_pooled[GG * 1024];
__device__ int   g_gstart[GG + 1];

// ---------------- graph building -------------------------------------------
__global__ void k_zero_setup() {
    int i = blockIdx.x * blockDim.x + threadIdx.x;
    if (i < NN) { g_deg[i] = 0; g_cursor[i] = 0; }
}

__global__ void k_deg(const int* __restrict__ dst) {
    int e = blockIdx.x * blockDim.x + threadIdx.x;
    if (e < EE) atomicAdd(&g_deg[dst[e]], 1);
}

// exclusive scan of g_deg (16384 = 512 threads * 32) -> g_rowptr
__global__ void k_scan() {
    __shared__ int sh[512];
    int tid = threadIdx.x;
    int base = tid * 32;
    int s = 0;
    for (int i = 0; i < 32; i++) s += g_deg[base + i];
    sh[tid] = s;
    __syncthreads();
    for (int off = 1; off < 512; off <<= 1) {
        int v = (tid >= off) ? sh[tid - off] : 0;
        __syncthreads();
        sh[tid] += v;
        __syncthreads();
    }
    int run = sh[tid] - s;  // exclusive prefix for this chunk
    for (int i = 0; i < 32; i++) {
        g_rowptr[base + i] = run;
        run += g_deg[base + i];
    }
    if (tid == 511) g_rowptr[NN] = sh[511];
}

__global__ void k_csr_fill(const int* __restrict__ src, const int* __restrict__ dst) {
    int e = blockIdx.x * blockDim.x + threadIdx.x;
    if (e < EE) {
        int d = dst[e];
        int pos = g_rowptr[d] + atomicAdd(&g_cursor[d], 1);
        g_csr[pos] = src[e];
    }
}

__global__ void k_dis() {
    int i = blockIdx.x * blockDim.x + threadIdx.x;
    if (i < NN) g_dis[i] = rsqrtf((float)g_deg[i] + 1.0f);  // +1 self loop
}

// ---------------- generic fp32 tiled GEMM: C = A[M,K] @ W[K,N] (+bias/acc) --
#define BM 128
#define BNT 128
#define BK 8
__global__ __launch_bounds__(256) void k_gemm(
    const float* __restrict__ A, const float* __restrict__ W,
    const float* __restrict__ bias, float* __restrict__ C,
    int M, int K, int Nn, int acc_flag)
{
    __shared__ float As[BK][BM];
    __shared__ float Bs[BK][BNT];
    int tid = threadIdx.x;
    int tx = tid & 15, ty = tid >> 4;
    int row0 = blockIdx.y * BM, col0 = blockIdx.x * BNT;
    float accum[8][8];
#pragma unroll
    for (int i = 0; i < 8; i++)
#pragma unroll
        for (int j = 0; j < 8; j++) accum[i][j] = 0.f;

    int arow = tid >> 1, acol0 = (tid & 1) * 4;   // A: 128 rows x 8 k
    int brow = tid >> 5, bcol0 = (tid & 31) * 4;  // B: 8 k x 128 cols

    for (int k0 = 0; k0 < K; k0 += BK) {
#pragma unroll
        for (int i = 0; i < 4; i++) {
            int kk = k0 + acol0 + i;
            As[acol0 + i][arow] = (kk < K) ? A[(size_t)(row0 + arow) * K + kk] : 0.f;
        }
#pragma unroll
        for (int i = 0; i < 4; i++) {
            int col = col0 + bcol0 + i;
            int kk = k0 + brow;
            Bs[brow][bcol0 + i] = (kk < K && col < Nn) ? W[(size_t)kk * Nn + col] : 0.f;
        }
        __syncthreads();
#pragma unroll
        for (int kk = 0; kk < BK; kk++) {
            float ra[8], rb[8];
#pragma unroll
            for (int i = 0; i < 8; i++) ra[i] = As[kk][ty * 8 + i];
#pragma unroll
            for (int j = 0; j < 8; j++) rb[j] = Bs[kk][tx * 8 + j];
#pragma unroll
            for (int i = 0; i < 8; i++)
#pragma unroll
                for (int j = 0; j < 8; j++) accum[i][j] += ra[i] * rb[j];
        }
        __syncthreads();
    }
#pragma unroll
    for (int i = 0; i < 8; i++) {
        int r = row0 + ty * 8 + i;
#pragma unroll
        for (int j = 0; j < 8; j++) {
            int cc = col0 + tx * 8 + j;
            if (cc < Nn) {
                float v = accum[i][j];
                if (bias) v += bias[cc];
                if (acc_flag) C[(size_t)r * Nn + cc] += v;
                else         C[(size_t)r * Nn + cc] = v;
            }
        }
    }
}

// ---------------- GCN aggregation: out[d] = dis_d*(sum dis_s*xw[s] + dis_d*xw[d]) + b
__global__ void k_gcn_agg(const float* __restrict__ xw, const float* __restrict__ bias,
                          float* __restrict__ out, int C)
{
    int d = blockIdx.x;
    int tid = threadIdx.x;
    int B = blockDim.x;
    int st = g_rowptr[d], deg = g_rowptr[d + 1] - st;
    __shared__ int   ssrc[256];
    __shared__ float swgt[256];
    float disd = g_dis[d];
    int c0 = tid, c1 = tid + B;
    bool has1 = (c1 < C);
    float a0 = 0.f, a1 = 0.f;
    for (int base = 0; base < deg; base += B) {
        int n = min(B, deg - base);
        if (tid < n) {
            int s = g_csr[st + base + tid];
            ssrc[tid] = s;
            swgt[tid] = g_dis[s];
        }
        __syncthreads();
        for (int i = 0; i < n; i++) {
            size_t b = (size_t)ssrc[i] * C;
            float w = swgt[i];
            a0 += xw[b + c0] * w;
            if (has1) a1 += xw[b + c1] * w;
        }
        __syncthreads();
    }
    size_t bd = (size_t)d * C;
    a0 += xw[bd + c0] * disd;
    out[bd + c0] = a0 * disd + bias[c0];
    if (has1) {
        a1 += xw[bd + c1] * disd;
        out[bd + c1] = a1 * disd + bias[c1];
    }
}

// ---------------- SAGE mean aggregation (64 channels) ----------------------
__global__ void k_sage_agg(const float* __restrict__ h, float* __restrict__ out) {
    int d = blockIdx.x;
    int tid = threadIdx.x;  // blockDim = 64
    int st = g_rowptr[d], deg = g_rowptr[d + 1] - st;
    __shared__ int ssrc[64];
    float a = 0.f;
    for (int base = 0; base < deg; base += 64) {
        int n = min(64, deg - base);
        if (tid < n) ssrc[tid] = g_csr[st + base + tid];
        __syncthreads();
        for (int i = 0; i < n; i++) a += h[(size_t)ssrc[i] * 64 + tid];
        __syncthreads();
    }
    out[(size_t)d * 64 + tid] = a / (float)max(deg, 1);
}

// ---------------- BatchNorm ------------------------------------------------
__global__ void k_zero_bn() {
    int i = threadIdx.x;
    g_bnsum[i] = 0.f;
    g_bnsq[i] = 0.f;
}

__global__ void k_bn_stats(const float* __restrict__ X, int C) {
    int c = threadIdx.x;  // blockDim = C
    int r0 = blockIdx.x * 64;
    float s = 0.f, q = 0.f;
    for (int r = 0; r < 64; r++) {
        float v = X[(size_t)(r0 + r) * C + c];
        s += v;
        q += v * v;
    }
    atomicAdd(&g_bnsum[c], s);
    atomicAdd(&g_bnsq[c], q);
}

__global__ void k_bn_apply(const float* __restrict__ in, const float* __restrict__ gam,
                           const float* __restrict__ bet, float* __restrict__ out, int C)
{
    int idx = blockIdx.x * blockDim.x + threadIdx.x;
    int c = idx % C;
    float inv_n = 1.0f / (float)NN;
    float mean = g_bnsum[c] * inv_n;
    float var = g_bnsq[c] * inv_n - mean * mean;
    float y = (in[idx] - mean) * rsqrtf(var + BN_EPS) * gam[c] + bet[c];
    out[idx] = fmaxf(y, 0.f);
}

// ---------------- GAT ------------------------------------------------------
// es/ed per node per head from hg [N,4,256]
__global__ void k_gat_scores(const float* __restrict__ hg,
                             const float* __restrict__ asrc, const float* __restrict__ adst)
{
    int n = blockIdx.x;
    int tid = threadIdx.x;  // 128 threads
    int h = tid >> 5, lane = tid & 31;
    float ps = 0.f, pd = 0.f;
    size_t b = (size_t)n * 1024 + h * 256;
    for (int c = lane; c < 256; c += 32) {
        float v = hg[b + c];
        ps += v * asrc[h * 256 + c];
        pd += v * adst[h * 256 + c];
    }
#pragma unroll
    for (int o = 16; o > 0; o >>= 1) {
        ps += __shfl_xor_sync(0xffffffffu, ps, o);
        pd += __shfl_xor_sync(0xffffffffu, pd, o);
    }
    if (lane == 0) {
        g_es[n * 4 + h] = ps;
        g_ed[n * 4 + h] = pd;
    }
}

__device__ __forceinline__ float leaky02(float x) { return x > 0.f ? x : 0.2f * x; }

// per-node softmax attention + weighted gather; out [N,256] (head-mean) + bias
__global__ void k_gat_node(const float* __restrict__ hg, const float* __restrict__ bias,
                           float* __restrict__ out)
{
    int d = blockIdx.x;
    int tid = threadIdx.x;  // 256 threads = 256 output channels
    int st = g_rowptr[d], deg = g_rowptr[d + 1] - st;
    __shared__ float s_m[4], s_z[4], s_ed[4], s_esf[4];
    __shared__ int   s_src[128];
    __shared__ float s_alpha[128][4];
    if (tid < 4) { s_ed[tid] = g_ed[d * 4 + tid]; s_esf[tid] = g_es[d * 4 + tid]; }
    __syncthreads();
    int warp = tid >> 5, lane = tid & 31;
    if (warp < 4) {
        int h = warp;
        float edv = s_ed[h];
        float eself = leaky02(s_esf[h] + edv);
        float m = eself;
        for (int i = lane; i < deg; i += 32)
            m = fmaxf(m, leaky02(g_es[g_csr[st + i] * 4 + h] + edv));
#pragma unroll
        for (int o = 16; o > 0; o >>= 1) m = fmaxf(m, __shfl_xor_sync(0xffffffffu, m, o));
        float z = (lane == 0) ? __expf(eself - m) : 0.f;
        for (int i = lane; i < deg; i += 32)
            z += __expf(leaky02(g_es[g_csr[st + i] * 4 + h] + edv) - m);
#pragma unroll
        for (int o = 16; o > 0; o >>= 1) z += __shfl_xor_sync(0xffffffffu, z, o);
        if (lane == 0) { s_m[h] = m; s_z[h] = z; }
    }
    __syncthreads();
    float acc = 0.f;
    int tot = deg + 1;  // + self loop at index deg
    for (int base = 0; base < tot; base += 128) {
        int n = min(128, tot - base);
        if (tid < n) {
            int idx = base + tid;
            int s = (idx < deg) ? g_csr[st + idx] : d;
            s_src[tid] = s;
#pragma unroll
            for (int h = 0; h < 4; h++) {
                float e = leaky02(g_es[s * 4 + h] + s_ed[h]);
                s_alpha[tid][h] = __expf(e - s_m[h]) / s_z[h];
            }
        }
        __syncthreads();
        for (int i = 0; i < n; i++) {
            size_t b = (size_t)s_src[i] * 1024 + tid;
            acc += s_alpha[i][0] * hg[b]
                 + s_alpha[i][1] * hg[b + 256]
                 + s_alpha[i][2] * hg[b + 512]
                 + s_alpha[i][3] * hg[b + 768];
        }
        __syncthreads();
    }
    out[(size_t)d * 256 + tid] = 0.25f * acc + bias[tid];
}

// ---------------- pooling + FC ---------------------------------------------
__global__ void k_gstart(const int* __restrict__ batch) {
    int g = threadIdx.x;
    if (g <= GG) {
        int lo = 0, hi = NN;
        while (lo < hi) {
            int mid = (lo + hi) >> 1;
            if (batch[mid] < g) lo = mid + 1;
            else hi = mid;
        }
        g_gstart[g] = lo;
    }
}

__global__ void k_pool() {
    int g = blockIdx.x;
    int c = blockIdx.y * 256 + threadIdx.x;  // 512 channels over 2 y-blocks
    int st = g_gstart[g], en = g_gstart[g + 1];
    int cnt = en - st;
    float s = 0.f, m = -3.4e38f;
    for (int i = st; i < en; i++) {
        float v = g_bufD[(size_t)i * 512 + c];
        s += v;
        m = fmaxf(m, v);
    }
    g_pooled[g * 1024 + c] = s / (float)max(cnt, 1);
    g_pooled[g * 1024 + 512 + c] = (cnt > 0) ? m : 0.f;
}

__global__ void k_fc(const float* __restrict__ W, const float* __restrict__ bias,
                     float* __restrict__ out)
{
    int tid = threadIdx.x;                 // 128 threads
    int j = blockIdx.x * 128 + tid;        // output channel
    __shared__ float sp[64][32];           // [k-chunk][graph]
    float acc[GG];
#pragma unroll
    for (int g = 0; g < GG; g++) acc[g] = 0.f;
    for (int k0 = 0; k0 < 1024; k0 += 64) {
        for (int t = tid; t < 64 * 32; t += 128) {
            int kk = t >> 5, g = t & 31;
            sp[kk][g] = g_pooled[g * 1024 + k0 + kk];
        }
        __syncthreads();
#pragma unroll 8
        for (int kk = 0; kk < 64; kk++) {
            float wv = W[(size_t)(k0 + kk) * 1024 + j];
#pragma unroll
            for (int g = 0; g < GG; g++) acc[g] += sp[kk][g] * wv;
        }
        __syncthreads();
    }
    float bv = bias[j];
#pragma unroll
    for (int g = 0; g < GG; g++) out[(size_t)g * 1024 + j] = acc[g] + bv;
}

// ---------------- host orchestration ---------------------------------------
extern "C" void kernel_launch(void* const* d_in, const int* in_sizes, int n_in,
                              void* d_out, int out_size)
{
    const float* x        = (const float*)d_in[0];
    const int*   ei       = (const int*)  d_in[1];
    const int*   batch    = (const int*)  d_in[2];
    const float* gcn1_w   = (const float*)d_in[3];
    const float* gcn1_b   = (const float*)d_in[4];
    const float* sage_wl  = (const float*)d_in[5];
    const float* sage_wr  = (const float*)d_in[6];
    const float* sage_b   = (const float*)d_in[7];
    const float* gat_w    = (const float*)d_in[8];
    const float* gat_asrc = (const float*)d_in[9];
    const float* gat_adst = (const float*)d_in[10];
    const float* gat_b    = (const float*)d_in[11];
    const float* gcn4_w   = (const float*)d_in[12];
    const float* gcn4_b   = (const float*)d_in[13];
    const float* bn1_g = (const float*)d_in[14]; const float* bn1_b = (const float*)d_in[15];
    const float* bn2_g = (const float*)d_in[16]; const float* bn2_b = (const float*)d_in[17];
    const float* bn3_g = (const float*)d_in[18]; const float* bn3_b = (const float*)d_in[19];
    const float* bn4_g = (const float*)d_in[20]; const float* bn4_b = (const float*)d_in[21];
    const float* fc_w  = (const float*)d_in[22]; const float* fc_b  = (const float*)d_in[23];
    float* out = (float*)d_out;

    const int* src = ei;
    const int* dst = ei + EE;

    float *A, *B, *C, *D;
    cudaGetSymbolAddress((void**)&A, g_bufA);
    cudaGetSymbolAddress((void**)&B, g_bufB);
    cudaGetSymbolAddress((void**)&C, g_bufC);
    cudaGetSymbolAddress((void**)&D, g_bufD);

    // graph build
    k_zero_setup<<<NN / 256, 256>>>();
    k_deg<<<EE / 256, 256>>>(dst);
    k_scan<<<1, 512>>>();
    k_csr_fill<<<EE / 256, 256>>>(src, dst);
    k_dis<<<NN / 256, 256>>>();

    // ---- layer 1: GCN(5->64) + BN + ReLU ----
    k_gemm<<<dim3(1, NN / 128), 256>>>(x, gcn1_w, nullptr, B, NN, 5, 64, 0);
    k_gcn_agg<<<NN, 64>>>(B, gcn1_b, C, 64);
    k_zero_bn<<<1, 512>>>();
    k_bn_stats<<<NN / 64, 64>>>(C, 64);
    k_bn_apply<<<NN * 64 / 256, 256>>>(C, bn1_g, bn1_b, D, 64);

    // ---- layer 2: SAGE(64->128) + BN + ReLU ----
    k_sage_agg<<<NN, 64>>>(D, B);
    k_gemm<<<dim3(1, NN / 128), 256>>>(B, sage_wl, sage_b, C, NN, 64, 128, 0);
    k_gemm<<<dim3(1, NN / 128), 256>>>(D, sage_wr, nullptr, C, NN, 64, 128, 1);
    k_zero_bn<<<1, 512>>>();
    k_bn_stats<<<NN / 64, 128>>>(C, 128);
    k_bn_apply<<<NN * 128 / 256, 256>>>(C, bn2_g, bn2_b, D, 128);

    // ---- layer 3: GAT(128->4x256, head-mean) + BN + ReLU ----
    k_gemm<<<dim3(8, NN / 128), 256>>>(D, gat_w, nullptr, A, NN, 128, 1024, 0);
    k_gat_scores<<<NN, 128>>>(A, gat_asrc, gat_adst);
    k_gat_node<<<NN, 256>>>(A, gat_b, C);
    k_zero_bn<<<1, 512>>>();
    k_bn_stats<<<NN / 64, 256>>>(C, 256);
    k_bn_apply<<<NN * 256 / 256, 256>>>(C, bn3_g, bn3_b, D, 256);

    // ---- layer 4: GCN(256->512) + BN + ReLU ----
    k_gemm<<<dim3(4, NN / 128), 256>>>(D, gcn4_w, nullptr, B, NN, 256, 512, 0);
    k_gcn_agg<<<NN, 256>>>(B, gcn4_b, C, 512);
    k_zero_bn<<<1, 512>>>();
    k_bn_stats<<<NN / 64, 512>>>(C, 512);
    k_bn_apply<<<NN * 512 / 256, 256>>>(C, bn4_g, bn4_b, D, 512);

    // ---- pooling + FC ----
    k_gstart<<<1, 64>>>(batch);
    k_pool<<<dim3(GG, 2), 256>>>();
    k_fc<<<8, 128>>>(fc_w, fc_b, out);
}

// round 2
// speedup vs baseline: 1.2571x; 1.2571x over previous
#include <cuda_runtime.h>
#include <math.h>

#define NN 16384
#define EE 131072
#define GG 32
#define BN_EPS 1e-5f

// ---------------- scratch (device globals: no allocation allowed) ----------
__device__ float g_bufA[NN * 1024];   // GAT hidden hg [N,1024]  (64 MB)
__device__ float g_bufB[NN * 512];    // xw / agg buffers        (32 MB)
__device__ float g_bufC[NN * 512];    // pre-BN buffers          (32 MB)
__device__ float g_bufD[NN * 512];    // post-BN (layer output)  (32 MB)
__device__ float g_es[NN * 4];
__device__ float g_ed[NN * 4];
__device__ int   g_deg[NN];
__device__ int   g_rowptr[NN + 1];
__device__ int   g_cursor[NN];
__device__ int   g_csr[EE];
__device__ float g_dis[NN];
__device__ float g_bnsum[512];
__device__ float g_bnsq[512];
__device__ float g_pooled[GG * 1024];
__device__ int   g_gstart[GG + 1];

// ---------------- graph building -------------------------------------------
__global__ void k_zero_setup() {
    int i = blockIdx.x * blockDim.x + threadIdx.x;
    if (i < NN) { g_deg[i] = 0; g_cursor[i] = 0; }
}

__global__ void k_deg(const int* __restrict__ dst) {
    int e = blockIdx.x * blockDim.x + threadIdx.x;
    if (e < EE) atomicAdd(&g_deg[dst[e]], 1);
}

// exclusive scan of g_deg (16384 = 512 threads * 32) -> g_rowptr
__global__ void k_scan() {
    __shared__ int sh[512];
    int tid = threadIdx.x;
    int base = tid * 32;
    int s = 0;
    for (int i = 0; i < 32; i++) s += g_deg[base + i];
    sh[tid] = s;
    __syncthreads();
    for (int off = 1; off < 512; off <<= 1) {
        int v = (tid >= off) ? sh[tid - off] : 0;
        __syncthreads();
        sh[tid] += v;
        __syncthreads();
    }
    int run = sh[tid] - s;  // exclusive prefix for this chunk
    for (int i = 0; i < 32; i++) {
        g_rowptr[base + i] = run;
        run += g_deg[base + i];
    }
    if (tid == 511) g_rowptr[NN] = sh[511];
}

__global__ void k_csr_fill(const int* __restrict__ src, const int* __restrict__ dst) {
    int e = blockIdx.x * blockDim.x + threadIdx.x;
    if (e < EE) {
        int d = dst[e];
        int pos = g_rowptr[d] + atomicAdd(&g_cursor[d], 1);
        g_csr[pos] = src[e];
    }
}

__global__ void k_dis() {
    int i = blockIdx.x * blockDim.x + threadIdx.x;
    if (i < NN) g_dis[i] = rsqrtf((float)g_deg[i] + 1.0f);  // +1 self loop
}

// ---------------- small generic GEMM (used only for K=5 layer) -------------
__global__ __launch_bounds__(256) void k_gemm_small(
    const float* __restrict__ A, const float* __restrict__ W,
    const float* __restrict__ bias, float* __restrict__ C,
    int M, int K, int Nn, int acc_flag)
{
    __shared__ float As[8][128];
    __shared__ float Bs[8][128];
    int tid = threadIdx.x;
    int tx = tid & 15, ty = tid >> 4;
    int row0 = blockIdx.y * 128, col0 = blockIdx.x * 128;
    float accum[8][8];
#pragma unroll
    for (int i = 0; i < 8; i++)
#pragma unroll
        for (int j = 0; j < 8; j++) accum[i][j] = 0.f;

    int arow = tid >> 1, acol0 = (tid & 1) * 4;
    int brow = tid >> 5, bcol0 = (tid & 31) * 4;

    for (int k0 = 0; k0 < K; k0 += 8) {
#pragma unroll
        for (int i = 0; i < 4; i++) {
            int kk = k0 + acol0 + i;
            As[acol0 + i][arow] = (kk < K) ? A[(size_t)(row0 + arow) * K + kk] : 0.f;
        }
#pragma unroll
        for (int i = 0; i < 4; i++) {
            int col = col0 + bcol0 + i;
            int kk = k0 + brow;
            Bs[brow][bcol0 + i] = (kk < K && col < Nn) ? W[(size_t)kk * Nn + col] : 0.f;
        }
        __syncthreads();
#pragma unroll
        for (int kk = 0; kk < 8; kk++) {
            float ra[8], rb[8];
#pragma unroll
            for (int i = 0; i < 8; i++) ra[i] = As[kk][ty * 8 + i];
#pragma unroll
            for (int j = 0; j < 8; j++) rb[j] = Bs[kk][tx * 8 + j];
#pragma unroll
            for (int i = 0; i < 8; i++)
#pragma unroll
                for (int j = 0; j < 8; j++) accum[i][j] += ra[i] * rb[j];
        }
        __syncthreads();
    }
#pragma unroll
    for (int i = 0; i < 8; i++) {
        int r = row0 + ty * 8 + i;
#pragma unroll
        for (int j = 0; j < 8; j++) {
            int cc = col0 + tx * 8 + j;
            if (cc < Nn) {
                float v = accum[i][j];
                if (bias) v += bias[cc];
                if (acc_flag) C[(size_t)r * Nn + cc] += v;
                else         C[(size_t)r * Nn + cc] = v;
            }
        }
    }
}

// ---------------- fast GEMM: 128x128x16 tiles, float4, prefetch ------------
// requires: M%128==0, K%16==0, N%128==0
__global__ __launch_bounds__(256, 2) void k_gemm_fast(
    const float* __restrict__ A, const float* __restrict__ W,
    const float* __restrict__ bias, float* __restrict__ C,
    int M, int K, int Nn, int acc_flag)
{
    __shared__ float As[16][128];   // [k][row] (transposed)
    __shared__ float Bs[16][128];   // [k][col]
    int tid = threadIdx.x;
    int tx = tid & 15, ty = tid >> 4;
    int row0 = blockIdx.y * 128, col0 = blockIdx.x * 128;

    const float* Abase = A + (size_t)row0 * K;
    const float* Wbase = W + col0;

    // A slots: s = 2*tid + i ; covers 128 rows x 4 float4 along k
    int a_row[2], a_kq[2];
#pragma unroll
    for (int i = 0; i < 2; i++) {
        int s = 2 * tid + i;
        a_row[i] = s >> 2;
        a_kq[i]  = (s & 3) * 4;
    }
    // B slots: s = tid + 256*i ; covers 16 k-rows x 32 float4 along n
    int b_kk = tid >> 5;            // 0..7 (i adds 8)
    int b_c4 = (tid & 31) * 4;

    float4 curA[2], curB[2], nxtA[2], nxtB[2];
#pragma unroll
    for (int i = 0; i < 2; i++) {
        curA[i] = *(const float4*)(Abase + (size_t)a_row[i] * K + a_kq[i]);
        curB[i] = *(const float4*)(Wbase + (size_t)(b_kk + 8 * i) * Nn + b_c4);
    }

    float acc[8][8];
#pragma unroll
    for (int i = 0; i < 8; i++)
#pragma unroll
        for (int j = 0; j < 8; j++) acc[i][j] = 0.f;

    for (int k0 = 0; k0 < K; k0 += 16) {
#pragma unroll
        for (int i = 0; i < 2; i++) {
            As[a_kq[i] + 0][a_row[i]] = curA[i].x;
            As[a_kq[i] + 1][a_row[i]] = curA[i].y;
            As[a_kq[i] + 2][a_row[i]] = curA[i].z;
            As[a_kq[i] + 3][a_row[i]] = curA[i].w;
            *(float4*)&Bs[b_kk + 8 * i][b_c4] = curB[i];
        }
        __syncthreads();
        if (k0 + 16 < K) {
#pragma unroll
            for (int i = 0; i < 2; i++) {
                nxtA[i] = *(const float4*)(Abase + (size_t)a_row[i] * K + (k0 + 16) + a_kq[i]);
                nxtB[i] = *(const float4*)(Wbase + (size_t)(k0 + 16 + b_kk + 8 * i) * Nn + b_c4);
            }
        }
#pragma unroll
        for (int kk = 0; kk < 16; kk++) {
            float4 ra0 = *(const float4*)&As[kk][ty * 8];
            float4 ra1 = *(const float4*)&As[kk][ty * 8 + 4];
            float4 rb0 = *(const float4*)&Bs[kk][tx * 8];
            float4 rb1 = *(const float4*)&Bs[kk][tx * 8 + 4];
            float ra[8] = {ra0.x, ra0.y, ra0.z, ra0.w, ra1.x, ra1.y, ra1.z, ra1.w};
            float rb[8] = {rb0.x, rb0.y, rb0.z, rb0.w, rb1.x, rb1.y, rb1.z, rb1.w};
#pragma unroll
            for (int i = 0; i < 8; i++)
#pragma unroll
                for (int j = 0; j < 8; j++) acc[i][j] += ra[i] * rb[j];
        }
        __syncthreads();
#pragma unroll
        for (int i = 0; i < 2; i++) { curA[i] = nxtA[i]; curB[i] = nxtB[i]; }
    }

#pragma unroll
    for (int i = 0; i < 8; i++) {
        size_t r = (size_t)(row0 + ty * 8 + i);
        float* cp = C + r * Nn + col0 + tx * 8;
#pragma unroll
        for (int j = 0; j < 8; j++) {
            float v = acc[i][j];
            if (bias) v += bias[col0 + tx * 8 + j];
            if (acc_flag) cp[j] += v;
            else          cp[j] = v;
        }
    }
}

// ---------------- GCN aggregation ------------------------------------------
__global__ void k_gcn_agg(const float* __restrict__ xw, const float* __restrict__ bias,
                          float* __restrict__ out, int C)
{
    int d = blockIdx.x;
    int tid = threadIdx.x;
    int B = blockDim.x;
    int st = g_rowptr[d], deg = g_rowptr[d + 1] - st;
    __shared__ int   ssrc[256];
    __shared__ float swgt[256];
    float disd = g_dis[d];
    int c0 = tid, c1 = tid + B;
    bool has1 = (c1 < C);
    float a0 = 0.f, a1 = 0.f;
    for (int base = 0; base < deg; base += B) {
        int n = min(B, deg - base);
        if (tid < n) {
            int s = g_csr[st + base + tid];
            ssrc[tid] = s;
            swgt[tid] = g_dis[s];
        }
        __syncthreads();
        for (int i = 0; i < n; i++) {
            size_t b = (size_t)ssrc[i] * C;
            float w = swgt[i];
            a0 += xw[b + c0] * w;
            if (has1) a1 += xw[b + c1] * w;
        }
        __syncthreads();
    }
    size_t bd = (size_t)d * C;
    a0 += xw[bd + c0] * disd;
    out[bd + c0] = a0 * disd + bias[c0];
    if (has1) {
        a1 += xw[bd + c1] * disd;
        out[bd + c1] = a1 * disd + bias[c1];
    }
}

// ---------------- SAGE mean aggregation (64 channels) ----------------------
__global__ void k_sage_agg(const float* __restrict__ h, float* __restrict__ out) {
    int d = blockIdx.x;
    int tid = threadIdx.x;  // blockDim = 64
    int st = g_rowptr[d], deg = g_rowptr[d + 1] - st;
    __shared__ int ssrc[64];
    float a = 0.f;
    for (int base = 0; base < deg; base += 64) {
        int n = min(64, deg - base);
        if (tid < n) ssrc[tid] = g_csr[st + base + tid];
        __syncthreads();
        for (int i = 0; i < n; i++) a += h[(size_t)ssrc[i] * 64 + tid];
        __syncthreads();
    }
    out[(size_t)d * 64 + tid] = a / (float)max(deg, 1);
}

// ---------------- BatchNorm ------------------------------------------------
__global__ void k_zero_bn() {
    int i = threadIdx.x;
    g_bnsum[i] = 0.f;
    g_bnsq[i] = 0.f;
}

__global__ void k_bn_stats(const float* __restrict__ X, int C) {
    int c = threadIdx.x;  // blockDim = C
    int r0 = blockIdx.x * 64;
    float s = 0.f, q = 0.f;
    for (int r = 0; r < 64; r++) {
        float v = X[(size_t)(r0 + r) * C + c];
        s += v;
        q += v * v;
    }
    atomicAdd(&g_bnsum[c], s);
    atomicAdd(&g_bnsq[c], q);
}

__global__ void k_bn_apply(const float* __restrict__ in, const float* __restrict__ gam,
                           const float* __restrict__ bet, float* __restrict__ out, int C)
{
    int idx = blockIdx.x * blockDim.x + threadIdx.x;
    int c = idx % C;
    float inv_n = 1.0f / (float)NN;
    float mean = g_bnsum[c] * inv_n;
    float var = g_bnsq[c] * inv_n - mean * mean;
    float y = (in[idx] - mean) * rsqrtf(var + BN_EPS) * gam[c] + bet[c];
    out[idx] = fmaxf(y, 0.f);
}

// ---------------- GAT ------------------------------------------------------
__global__ void k_gat_scores(const float* __restrict__ hg,
                             const float* __restrict__ asrc, const float* __restrict__ adst)
{
    int n = blockIdx.x;
    int tid = threadIdx.x;  // 128 threads
    int h = tid >> 5, lane = tid & 31;
    float ps = 0.f, pd = 0.f;
    size_t b = (size_t)n * 1024 + h * 256;
    for (int c = lane; c < 256; c += 32) {
        float v = hg[b + c];
        ps += v * asrc[h * 256 + c];
        pd += v * adst[h * 256 + c];
    }
#pragma unroll
    for (int o = 16; o > 0; o >>= 1) {
        ps += __shfl_xor_sync(0xffffffffu, ps, o);
        pd += __shfl_xor_sync(0xffffffffu, pd, o);
    }
    if (lane == 0) {
        g_es[n * 4 + h] = ps;
        g_ed[n * 4 + h] = pd;
    }
}

__device__ __forceinline__ float leaky02(float x) { return x > 0.f ? x : 0.2f * x; }

__global__ void k_gat_node(const float* __restrict__ hg, const float* __restrict__ bias,
                           float* __restrict__ out)
{
    int d = blockIdx.x;
    int tid = threadIdx.x;  // 256 threads = 256 output channels
    int st = g_rowptr[d], deg = g_rowptr[d + 1] - st;
    __shared__ float s_m[4], s_z[4], s_ed[4], s_esf[4];
    __shared__ int   s_src[128];
    __shared__ float s_alpha[128][4];
    if (tid < 4) { s_ed[tid] = g_ed[d * 4 + tid]; s_esf[tid] = g_es[d * 4 + tid]; }
    __syncthreads();
    int warp = tid >> 5, lane = tid & 31;
    if (warp < 4) {
        int h = warp;
        float edv = s_ed[h];
        float eself = leaky02(s_esf[h] + edv);
        float m = eself;
        for (int i = lane; i < deg; i += 32)
            m = fmaxf(m, leaky02(g_es[g_csr[st + i] * 4 + h] + edv));
#pragma unroll
        for (int o = 16; o > 0; o >>= 1) m = fmaxf(m, __shfl_xor_sync(0xffffffffu, m, o));
        float z = (lane == 0) ? __expf(eself - m) : 0.f;
        for (int i = lane; i < deg; i += 32)
            z += __expf(leaky02(g_es[g_csr[st + i] * 4 + h] + edv) - m);
#pragma unroll
        for (int o = 16; o > 0; o >>= 1) z += __shfl_xor_sync(0xffffffffu, z, o);
        if (lane == 0) { s_m[h] = m; s_z[h] = z; }
    }
    __syncthreads();
    float acc = 0.f;
    int tot = deg + 1;  // + self loop at index deg
    for (int base = 0; base < tot; base += 128) {
        int n = min(128, tot - base);
        if (tid < n) {
            int idx = base + tid;
            int s = (idx < deg) ? g_csr[st + idx] : d;
            s_src[tid] = s;
#pragma unroll
            for (int h = 0; h < 4; h++) {
                float e = leaky02(g_es[s * 4 + h] + s_ed[h]);
                s_alpha[tid][h] = __expf(e - s_m[h]) / s_z[h];
            }
        }
        __syncthreads();
        for (int i = 0; i < n; i++) {
            size_t b = (size_t)s_src[i] * 1024 + tid;
            acc += s_alpha[i][0] * hg[b]
                 + s_alpha[i][1] * hg[b + 256]
                 + s_alpha[i][2] * hg[b + 512]
                 + s_alpha[i][3] * hg[b + 768];
        }
        __syncthreads();
    }
    out[(size_t)d * 256 + tid] = 0.25f * acc + bias[tid];
}

// ---------------- pooling + FC ---------------------------------------------
__global__ void k_gstart(const int* __restrict__ batch) {
    int g = threadIdx.x;
    if (g <= GG) {
        int lo = 0, hi = NN;
        while (lo < hi) {
            int mid = (lo + hi) >> 1;
            if (batch[mid] < g) lo = mid + 1;
            else hi = mid;
        }
        g_gstart[g] = lo;
    }
}

__global__ void k_pool() {
    int g = blockIdx.x;
    int c = blockIdx.y * 256 + threadIdx.x;  // 512 channels over 2 y-blocks
    int st = g_gstart[g], en = g_gstart[g + 1];
    int cnt = en - st;
    float s = 0.f, m = -3.4e38f;
    int i = st;
    for (; i + 4 <= en; i += 4) {
        float v0 = g_bufD[(size_t)(i + 0) * 512 + c];
        float v1 = g_bufD[(size_t)(i + 1) * 512 + c];
        float v2 = g_bufD[(size_t)(i + 2) * 512 + c];
        float v3 = g_bufD[(size_t)(i + 3) * 512 + c];
        s += (v0 + v1) + (v2 + v3);
        m = fmaxf(m, fmaxf(fmaxf(v0, v1), fmaxf(v2, v3)));
    }
    for (; i < en; i++) {
        float v = g_bufD[(size_t)i * 512 + c];
        s += v;
        m = fmaxf(m, v);
    }
    g_pooled[g * 1024 + c] = s / (float)max(cnt, 1);
    g_pooled[g * 1024 + 512 + c] = (cnt > 0) ? m : 0.f;
}

// FC: grid (8 j-chunks, 8 g-chunks of 4 graphs), 128 threads
__global__ __launch_bounds__(128) void k_fc(const float* __restrict__ W,
                                            const float* __restrict__ bias,
                                            float* __restrict__ out)
{
    __shared__ float sp[4][1024];
    int tid = threadIdx.x;
    int j = blockIdx.x * 128 + tid;
    int g0 = blockIdx.y * 4;
    for (int t = tid; t < 4 * 1024; t += 128)
        sp[t >> 10][t & 1023] = g_pooled[(g0 + (t >> 10)) * 1024 + (t & 1023)];
    __syncthreads();
    float acc[4] = {0.f, 0.f, 0.f, 0.f};
#pragma unroll 4
    for (int kk = 0; kk < 1024; kk++) {
        float wv = W[(size_t)kk * 1024 + j];
#pragma unroll
        for (int g = 0; g < 4; g++) acc[g] += sp[g][kk] * wv;
    }
    float bv = bias[j];
#pragma unroll
    for (int g = 0; g < 4; g++) out[(size_t)(g0 + g) * 1024 + j] = acc[g] + bv;
}

// ---------------- host orchestration ---------------------------------------
extern "C" void kernel_launch(void* const* d_in, const int* in_sizes, int n_in,
                              void* d_out, int out_size)
{
    const float* x        = (const float*)d_in[0];
    const int*   ei       = (const int*)  d_in[1];
    const int*   batch    = (const int*)  d_in[2];
    const float* gcn1_w   = (const float*)d_in[3];
    const float* gcn1_b   = (const float*)d_in[4];
    const float* sage_wl  = (const float*)d_in[5];
    const float* sage_wr  = (const float*)d_in[6];
    const float* sage_b   = (const float*)d_in[7];
    const float* gat_w    = (const float*)d_in[8];
    const float* gat_asrc = (const float*)d_in[9];
    const float* gat_adst = (const float*)d_in[10];
    const float* gat_b    = (const float*)d_in[11];
    const float* gcn4_w   = (const float*)d_in[12];
    const float* gcn4_b   = (const float*)d_in[13];
    const float* bn1_g = (const float*)d_in[14]; const float* bn1_b = (const float*)d_in[15];
    const float* bn2_g = (const float*)d_in[16]; const float* bn2_b = (const float*)d_in[17];
    const float* bn3_g = (const float*)d_in[18]; const float* bn3_b = (const float*)d_in[19];
    const float* bn4_g = (const float*)d_in[20]; const float* bn4_b = (const float*)d_in[21];
    const float* fc_w  = (const float*)d_in[22]; const float* fc_b  = (const float*)d_in[23];
    float* out = (float*)d_out;

    const int* src = ei;
    const int* dst = ei + EE;

    float *A, *B, *C, *D;
    cudaGetSymbolAddress((void**)&A, g_bufA);
    cudaGetSymbolAddress((void**)&B, g_bufB);
    cudaGetSymbolAddress((void**)&C, g_bufC);
    cudaGetSymbolAddress((void**)&D, g_bufD);

    // graph build
    k_zero_setup<<<NN / 256, 256>>>();
    k_deg<<<EE / 256, 256>>>(dst);
    k_scan<<<1, 512>>>();
    k_csr_fill<<<EE / 256, 256>>>(src, dst);
    k_dis<<<NN / 256, 256>>>();

    // ---- layer 1: GCN(5->64) + BN + ReLU ----
    k_gemm_small<<<dim3(1, NN / 128), 256>>>(x, gcn1_w, nullptr, B, NN, 5, 64, 0);
    k_gcn_agg<<<NN, 64>>>(B, gcn1_b, C, 64);
    k_zero_bn<<<1, 512>>>();
    k_bn_stats<<<NN / 64, 64>>>(C, 64);
    k_bn_apply<<<NN * 64 / 256, 256>>>(C, bn1_g, bn1_b, D, 64);

    // ---- layer 2: SAGE(64->128) + BN + ReLU ----
    k_sage_agg<<<NN, 64>>>(D, B);
    k_gemm_fast<<<dim3(1, NN / 128), 256>>>(B, sage_wl, sage_b, C, NN, 64, 128, 0);
    k_gemm_fast<<<dim3(1, NN / 128), 256>>>(D, sage_wr, nullptr, C, NN, 64, 128, 1);
    k_zero_bn<<<1, 512>>>();
    k_bn_stats<<<NN / 64, 128>>>(C, 128);
    k_bn_apply<<<NN * 128 / 256, 256>>>(C, bn2_g, bn2_b, D, 128);

    // ---- layer 3: GAT(128->4x256, head-mean) + BN + ReLU ----
    k_gemm_fast<<<dim3(8, NN / 128), 256>>>(D, gat_w, nullptr, A, NN, 128, 1024, 0);
    k_gat_scores<<<NN, 128>>>(A, gat_asrc, gat_adst);
    k_gat_node<<<NN, 256>>>(A, gat_b, C);
    k_zero_bn<<<1, 512>>>();
    k_bn_stats<<<NN / 64, 256>>>(C, 256);
    k_bn_apply<<<NN * 256 / 256, 256>>>(C, bn3_g, bn3_b, D, 256);

    // ---- layer 4: GCN(256->512) + BN + ReLU ----
    k_gemm_fast<<<dim3(4, NN / 128), 256>>>(D, gcn4_w, nullptr, B, NN, 256, 512, 0);
    k_gcn_agg<<<NN, 256>>>(B, gcn4_b, C, 512);
    k_zero_bn<<<1, 512>>>();
    k_bn_stats<<<NN / 64, 512>>>(C, 512);
    k_bn_apply<<<NN * 512 / 256, 256>>>(C, bn4_g, bn4_b, D, 512);

    // ---- pooling + FC ----
    k_gstart<<<1, 64>>>(batch);
    k_pool<<<dim3(GG, 2), 256>>>();
    k_fc<<<dim3(8, 8), 128>>>(fc_w, fc_b, out);
}

// round 3
// speedup vs baseline: 1.3331x; 1.0604x over previous
#include <cuda_runtime.h>
#include <mma.h>
#include <math.h>

using namespace nvcuda;

#define NN 16384
#define EE 131072
#define GG 32
#define BN_EPS 1e-5f

// ---------------- scratch (device globals: no allocation allowed) ----------
__device__ float g_bufA[NN * 1024];   // GAT hidden hg [N,1024]  (64 MB)
__device__ float g_bufB[NN * 512];    // xw / packed sage buffers (32 MB)
__device__ float g_bufC[NN * 512];    // pre-BN buffers           (32 MB)
__device__ float g_bufD[NN * 512];    // post-BN (layer output)   (32 MB)
__device__ float g_es[NN * 4];
__device__ float g_ed[NN * 4];
__device__ int   g_deg[NN];
__device__ int   g_rowptr[NN + 1];
__device__ int   g_cursor[NN];
__device__ int   g_csr[EE];
__device__ float g_dis[NN];
__device__ float g_bnsum[512];
__device__ float g_bnsq[512];
__device__ float g_pooled[GG * 1024];
__device__ int   g_gstart[GG + 1];

// ---------------- graph building -------------------------------------------
__global__ void k_zero_setup() {
    int i = blockIdx.x * blockDim.x + threadIdx.x;
    if (i < NN) { g_deg[i] = 0; g_cursor[i] = 0; }
}

__global__ void k_deg(const int* __restrict__ dst) {
    int e = blockIdx.x * blockDim.x + threadIdx.x;
    if (e < EE) atomicAdd(&g_deg[dst[e]], 1);
}

__global__ void k_scan() {
    __shared__ int sh[512];
    int tid = threadIdx.x;
    int base = tid * 32;
    int s = 0;
    for (int i = 0; i < 32; i++) s += g_deg[base + i];
    sh[tid] = s;
    __syncthreads();
    for (int off = 1; off < 512; off <<= 1) {
        int v = (tid >= off) ? sh[tid - off] : 0;
        __syncthreads();
        sh[tid] += v;
        __syncthreads();
    }
    int run = sh[tid] - s;
    for (int i = 0; i < 32; i++) {
        g_rowptr[base + i] = run;
        run += g_deg[base + i];
    }
    if (tid == 511) g_rowptr[NN] = sh[511];
}

__global__ void k_csr_fill(const int* __restrict__ src, const int* __restrict__ dst) {
    int e = blockIdx.x * blockDim.x + threadIdx.x;
    if (e < EE) {
        int d = dst[e];
        int pos = g_rowptr[d] + atomicAdd(&g_cursor[d], 1);
        g_csr[pos] = src[e];
    }
}

__global__ void k_dis() {
    int i = blockIdx.x * blockDim.x + threadIdx.x;
    if (i < NN) g_dis[i] = rsqrtf((float)g_deg[i] + 1.0f);
}

// ---------------- small generic GEMM (used only for K=5 layer) -------------
__global__ __launch_bounds__(256) void k_gemm_small(
    const float* __restrict__ A, const float* __restrict__ W,
    float* __restrict__ C, int M, int K, int Nn)
{
    __shared__ float As[8][128];
    __shared__ float Bs[8][128];
    int tid = threadIdx.x;
    int tx = tid & 15, ty = tid >> 4;
    int row0 = blockIdx.y * 128, col0 = blockIdx.x * 128;
    float accum[8][8];
#pragma unroll
    for (int i = 0; i < 8; i++)
#pragma unroll
        for (int j = 0; j < 8; j++) accum[i][j] = 0.f;

    int arow = tid >> 1, acol0 = (tid & 1) * 4;
    int brow = tid >> 5, bcol0 = (tid & 31) * 4;

    for (int k0 = 0; k0 < K; k0 += 8) {
#pragma unroll
        for (int i = 0; i < 4; i++) {
            int kk = k0 + acol0 + i;
            As[acol0 + i][arow] = (kk < K) ? A[(size_t)(row0 + arow) * K + kk] : 0.f;
        }
#pragma unroll
        for (int i = 0; i < 4; i++) {
            int col = col0 + bcol0 + i;
            int kk = k0 + brow;
            Bs[brow][bcol0 + i] = (kk < K && col < Nn) ? W[(size_t)kk * Nn + col] : 0.f;
        }
        __syncthreads();
#pragma unroll
        for (int kk = 0; kk < 8; kk++) {
            float ra[8], rb[8];
#pragma unroll
            for (int i = 0; i < 8; i++) ra[i] = As[kk][ty * 8 + i];
#pragma unroll
            for (int j = 0; j < 8; j++) rb[j] = Bs[kk][tx * 8 + j];
#pragma unroll
            for (int i = 0; i < 8; i++)
#pragma unroll
                for (int j = 0; j < 8; j++) accum[i][j] += ra[i] * rb[j];
        }
        __syncthreads();
    }
#pragma unroll
    for (int i = 0; i < 8; i++) {
        int r = row0 + ty * 8 + i;
#pragma unroll
        for (int j = 0; j < 8; j++) {
            int cc = col0 + tx * 8 + j;
            if (cc < Nn) C[(size_t)r * Nn + cc] = accum[i][j];
        }
    }
}

// ---------------- TF32 tensor-core GEMM ------------------------------------
// C[M,N] = A[M,K] @ Wpack (+bias), Wpack rows k<ksplit from W1, else W2.
// requires M%128==0, N%128==0, K%16==0.
// Block 128x128x16, 256 threads = 8 warps (2x4), warp tile 64x32.
__global__ __launch_bounds__(256, 2) void k_gemm_tf32(
    const float* __restrict__ A,
    const float* __restrict__ W1, const float* __restrict__ W2, int ksplit,
    const float* __restrict__ bias, float* __restrict__ C,
    int M, int K, int Nn)
{
    __shared__ float As[128][20];    // 128 rows x 16 k (pad 20)
    __shared__ float Bs[16][132];    // 16 k x 128 cols (pad 132)
    __shared__ float stage[8][16][20];

    int tid = threadIdx.x;
    int warp = tid >> 5;
    int wm = warp >> 2;              // 0..1
    int wn = warp & 3;               // 0..3
    int row0 = blockIdx.y * 128, col0 = blockIdx.x * 128;

    // A slots: 2 float4 per thread
    int a_r[2], a_c[2];
#pragma unroll
    for (int i = 0; i < 2; i++) {
        int s = tid * 2 + i;
        a_r[i] = s >> 2;
        a_c[i] = (s & 3) * 4;
    }
    // B slots: 2 float4 per thread
    int b_r[2], b_c[2];
#pragma unroll
    for (int i = 0; i < 2; i++) {
        int s = tid + 256 * i;
        b_r[i] = s >> 5;
        b_c[i] = (s & 31) * 4;
    }

    const float* Abase = A + (size_t)row0 * K;

    float4 cA[2], cB[2];
#pragma unroll
    for (int i = 0; i < 2; i++) {
        cA[i] = *(const float4*)(Abase + (size_t)a_r[i] * K + a_c[i]);
        int k = b_r[i];
        const float* wp = (k < ksplit) ? (W1 + (size_t)k * Nn)
                                       : (W2 + (size_t)(k - ksplit) * Nn);
        cB[i] = *(const float4*)(wp + col0 + b_c[i]);
    }

    wmma::fragment<wmma::accumulator, 16, 16, 8, float> acc[4][2];
#pragma unroll
    for (int i = 0; i < 4; i++)
#pragma unroll
        for (int j = 0; j < 2; j++) wmma::fill_fragment(acc[i][j], 0.f);

    for (int k0 = 0; k0 < K; k0 += 16) {
#pragma unroll
        for (int i = 0; i < 2; i++) {
            *(float4*)&As[a_r[i]][a_c[i]] = cA[i];
            *(float4*)&Bs[b_r[i]][b_c[i]] = cB[i];
        }
        __syncthreads();
        if (k0 + 16 < K) {
#pragma unroll
            for (int i = 0; i < 2; i++) {
                cA[i] = *(const float4*)(Abase + (size_t)a_r[i] * K + (k0 + 16) + a_c[i]);
                int k = k0 + 16 + b_r[i];
                const float* wp = (k < ksplit) ? (W1 + (size_t)k * Nn)
                                               : (W2 + (size_t)(k - ksplit) * Nn);
                cB[i] = *(const float4*)(wp + col0 + b_c[i]);
            }
        }
#pragma unroll
        for (int kk = 0; kk < 16; kk += 8) {
            wmma::fragment<wmma::matrix_a, 16, 16, 8, wmma::precision::tf32, wmma::row_major> af[4];
            wmma::fragment<wmma::matrix_b, 16, 16, 8, wmma::precision::tf32, wmma::row_major> bf[2];
#pragma unroll
            for (int i = 0; i < 4; i++) {
                wmma::load_matrix_sync(af[i], &As[wm * 64 + i * 16][kk], 20);
#pragma unroll
                for (int t = 0; t < af[i].num_elements; t++)
                    af[i].x[t] = wmma::__float_to_tf32(af[i].x[t]);
            }
#pragma unroll
            for (int j = 0; j < 2; j++) {
                wmma::load_matrix_sync(bf[j], &Bs[kk][wn * 32 + j * 16], 132);
#pragma unroll
                for (int t = 0; t < bf[j].num_elements; t++)
                    bf[j].x[t] = wmma::__float_to_tf32(bf[j].x[t]);
            }
#pragma unroll
            for (int i = 0; i < 4; i++)
#pragma unroll
                for (int j = 0; j < 2; j++)
                    wmma::mma_sync(acc[i][j], af[i], bf[j], acc[i][j]);
        }
        __syncthreads();
    }

    // epilogue via per-warp staging (adds optional bias)
    int lane = tid & 31;
    int er = lane >> 1;              // 0..15
    int ec = (lane & 1) * 8;         // 0 or 8
#pragma unroll
    for (int i = 0; i < 4; i++) {
#pragma unroll
        for (int j = 0; j < 2; j++) {
            wmma::store_matrix_sync(&stage[warp][0][0], acc[i][j], 20, wmma::mem_row_major);
            __syncwarp();
            int gr = row0 + wm * 64 + i * 16 + er;
            int gc = col0 + wn * 32 + j * 16 + ec;
            float* cp = C + (size_t)gr * Nn + gc;
#pragma unroll
            for (int q = 0; q < 8; q++) {
                float v = stage[warp][er][ec + q];
                if (bias) v += bias[gc + q];
                cp[q] = v;
            }
            __syncwarp();
        }
    }
}

// ---------------- GCN aggregation ------------------------------------------
__global__ void k_gcn_agg(const float* __restrict__ xw, const float* __restrict__ bias,
                          float* __restrict__ out, int C)
{
    int d = blockIdx.x;
    int tid = threadIdx.x;
    int B = blockDim.x;
    int st = g_rowptr[d], deg = g_rowptr[d + 1] - st;
    __shared__ int   ssrc[256];
    __shared__ float swgt[256];
    float disd = g_dis[d];
    int c0 = tid, c1 = tid + B;
    bool has1 = (c1 < C);
    float a0 = 0.f, a1 = 0.f;
    for (int base = 0; base < deg; base += B) {
        int n = min(B, deg - base);
        if (tid < n) {
            int s = g_csr[st + base + tid];
            ssrc[tid] = s;
            swgt[tid] = g_dis[s];
        }
        __syncthreads();
        for (int i = 0; i < n; i++) {
            size_t b = (size_t)ssrc[i] * C;
            float w = swgt[i];
            a0 += xw[b + c0] * w;
            if (has1) a1 += xw[b + c1] * w;
        }
        __syncthreads();
    }
    size_t bd = (size_t)d * C;
    a0 += xw[bd + c0] * disd;
    out[bd + c0] = a0 * disd + bias[c0];
    if (has1) {
        a1 += xw[bd + c1] * disd;
        out[bd + c1] = a1 * disd + bias[c1];
    }
}

// ---------------- SAGE mean aggregation into packed buffer -----------------
// P[N,128]: cols 64..127 hold h (written by bn_apply of layer1);
// this kernel writes mean-agg into cols 0..63.
__global__ void k_sage_agg(float* __restrict__ P) {
    int d = blockIdx.x;
    int tid = threadIdx.x;  // blockDim = 64
    int st = g_rowptr[d], deg = g_rowptr[d + 1] - st;
    __shared__ int ssrc[64];
    float a = 0.f;
    for (int base = 0; base < deg; base += 64) {
        int n = min(64, deg - base);
        if (tid < n) ssrc[tid] = g_csr[st + base + tid];
        __syncthreads();
        for (int i = 0; i < n; i++) a += P[(size_t)ssrc[i] * 128 + 64 + tid];
        __syncthreads();
    }
    P[(size_t)d * 128 + tid] = a / (float)max(deg, 1);
}

// ---------------- BatchNorm ------------------------------------------------
__global__ void k_zero_bn() {
    int i = threadIdx.x;
    g_bnsum[i] = 0.f;
    g_bnsq[i] = 0.f;
}

__global__ void k_bn_stats(const float* __restrict__ X, int C) {
    int c = threadIdx.x;
    int r0 = blockIdx.x * 64;
    float s = 0.f, q = 0.f;
    for (int r = 0; r < 64; r++) {
        float v = X[(size_t)(r0 + r) * C + c];
        s += v;
        q += v * v;
    }
    atomicAdd(&g_bnsum[c], s);
    atomicAdd(&g_bnsq[c], q);
}

// writes out[row*ostride + ooff + c]
__global__ void k_bn_apply(const float* __restrict__ in, const float* __restrict__ gam,
                           const float* __restrict__ bet, float* __restrict__ out,
                           int C, int ostride, int ooff)
{
    int idx = blockIdx.x * blockDim.x + threadIdx.x;
    int c = idx % C;
    int row = idx / C;
    float inv_n = 1.0f / (float)NN;
    float mean = g_bnsum[c] * inv_n;
    float var = g_bnsq[c] * inv_n - mean * mean;
    float y = (in[idx] - mean) * rsqrtf(var + BN_EPS) * gam[c] + bet[c];
    out[(size_t)row * ostride + ooff + c] = fmaxf(y, 0.f);
}

// ---------------- GAT ------------------------------------------------------
__global__ void k_gat_scores(const float* __restrict__ hg,
                             const float* __restrict__ asrc, const float* __restrict__ adst)
{
    int n = blockIdx.x;
    int tid = threadIdx.x;  // 128
    int h = tid >> 5, lane = tid & 31;
    float ps = 0.f, pd = 0.f;
    size_t b = (size_t)n * 1024 + h * 256;
    for (int c = lane; c < 256; c += 32) {
        float v = hg[b + c];
        ps += v * asrc[h * 256 + c];
        pd += v * adst[h * 256 + c];
    }
#pragma unroll
    for (int o = 16; o > 0; o >>= 1) {
        ps += __shfl_xor_sync(0xffffffffu, ps, o);
        pd += __shfl_xor_sync(0xffffffffu, pd, o);
    }
    if (lane == 0) {
        g_es[n * 4 + h] = ps;
        g_ed[n * 4 + h] = pd;
    }
}

__device__ __forceinline__ float leaky02(float x) { return x > 0.f ? x : 0.2f * x; }

__global__ void k_gat_node(const float* __restrict__ hg, const float* __restrict__ bias,
                           float* __restrict__ out)
{
    int d = blockIdx.x;
    int tid = threadIdx.x;  // 256
    int st = g_rowptr[d], deg = g_rowptr[d + 1] - st;
    __shared__ float s_m[4], s_z[4], s_ed[4], s_esf[4];
    __shared__ int   s_src[128];
    __shared__ float s_alpha[128][4];
    if (tid < 4) { s_ed[tid] = g_ed[d * 4 + tid]; s_esf[tid] = g_es[d * 4 + tid]; }
    __syncthreads();
    int warp = tid >> 5, lane = tid & 31;
    if (warp < 4) {
        int h = warp;
        float edv = s_ed[h];
        float eself = leaky02(s_esf[h] + edv);
        float m = eself;
        for (int i = lane; i < deg; i += 32)
            m = fmaxf(m, leaky02(g_es[g_csr[st + i] * 4 + h] + edv));
#pragma unroll
        for (int o = 16; o > 0; o >>= 1) m = fmaxf(m, __shfl_xor_sync(0xffffffffu, m, o));
        float z = (lane == 0) ? __expf(eself - m) : 0.f;
        for (int i = lane; i < deg; i += 32)
            z += __expf(leaky02(g_es[g_csr[st + i] * 4 + h] + edv) - m);
#pragma unroll
        for (int o = 16; o > 0; o >>= 1) z += __shfl_xor_sync(0xffffffffu, z, o);
        if (lane == 0) { s_m[h] = m; s_z[h] = z; }
    }
    __syncthreads();
    float acc = 0.f;
    int tot = deg + 1;
    for (int base = 0; base < tot; base += 128) {
        int n = min(128, tot - base);
        if (tid < n) {
            int idx = base + tid;
            int s = (idx < deg) ? g_csr[st + idx] : d;
            s_src[tid] = s;
#pragma unroll
            for (int h = 0; h < 4; h++) {
                float e = leaky02(g_es[s * 4 + h] + s_ed[h]);
                s_alpha[tid][h] = __expf(e - s_m[h]) / s_z[h];
            }
        }
        __syncthreads();
        for (int i = 0; i < n; i++) {
            size_t b = (size_t)s_src[i] * 1024 + tid;
            acc += s_alpha[i][0] * hg[b]
                 + s_alpha[i][1] * hg[b + 256]
                 + s_alpha[i][2] * hg[b + 512]
                 + s_alpha[i][3] * hg[b + 768];
        }
        __syncthreads();
    }
    out[(size_t)d * 256 + tid] = 0.25f * acc + bias[tid];
}

// ---------------- pooling + FC ---------------------------------------------
__global__ void k_gstart(const int* __restrict__ batch) {
    int g = threadIdx.x;
    if (g <= GG) {
        int lo = 0, hi = NN;
        while (lo < hi) {
            int mid = (lo + hi) >> 1;
            if (batch[mid] < g) lo = mid + 1;
            else hi = mid;
        }
        g_gstart[g] = lo;
    }
}

__global__ void k_pool() {
    int g = blockIdx.x;
    int c = blockIdx.y * 256 + threadIdx.x;
    int st = g_gstart[g], en = g_gstart[g + 1];
    int cnt = en - st;
    float s = 0.f, m = -3.4e38f;
    int i = st;
    for (; i + 4 <= en; i += 4) {
        float v0 = g_bufD[(size_t)(i + 0) * 512 + c];
        float v1 = g_bufD[(size_t)(i + 1) * 512 + c];
        float v2 = g_bufD[(size_t)(i + 2) * 512 + c];
        float v3 = g_bufD[(size_t)(i + 3) * 512 + c];
        s += (v0 + v1) + (v2 + v3);
        m = fmaxf(m, fmaxf(fmaxf(v0, v1), fmaxf(v2, v3)));
    }
    for (; i < en; i++) {
        float v = g_bufD[(size_t)i * 512 + c];
        s += v;
        m = fmaxf(m, v);
    }
    g_pooled[g * 1024 + c] = s / (float)max(cnt, 1);
    g_pooled[g * 1024 + 512 + c] = (cnt > 0) ? m : 0.f;
}

__global__ __launch_bounds__(128) void k_fc(const float* __restrict__ W,
                                            const float* __restrict__ bias,
                                            float* __restrict__ out)
{
    __shared__ float sp[4][1024];
    int tid = threadIdx.x;
    int j = blockIdx.x * 128 + tid;
    int g0 = blockIdx.y * 4;
    for (int t = tid; t < 4 * 1024; t += 128)
        sp[t >> 10][t & 1023] = g_pooled[(g0 + (t >> 10)) * 1024 + (t & 1023)];
    __syncthreads();
    float acc[4] = {0.f, 0.f, 0.f, 0.f};
#pragma unroll 4
    for (int kk = 0; kk < 1024; kk++) {
        float wv = W[(size_t)kk * 1024 + j];
#pragma unroll
        for (int g = 0; g < 4; g++) acc[g] += sp[g][kk] * wv;
    }
    float bv = bias[j];
#pragma unroll
    for (int g = 0; g < 4; g++) out[(size_t)(g0 + g) * 1024 + j] = acc[g] + bv;
}

// ---------------- host orchestration ---------------------------------------
extern "C" void kernel_launch(void* const* d_in, const int* in_sizes, int n_in,
                              void* d_out, int out_size)
{
    const float* x        = (const float*)d_in[0];
    const int*   ei       = (const int*)  d_in[1];
    const int*   batch    = (const int*)  d_in[2];
    const float* gcn1_w   = (const float*)d_in[3];
    const float* gcn1_b   = (const float*)d_in[4];
    const float* sage_wl  = (const float*)d_in[5];
    const float* sage_wr  = (const float*)d_in[6];
    const float* sage_b   = (const float*)d_in[7];
    const float* gat_w    = (const float*)d_in[8];
    const float* gat_asrc = (const float*)d_in[9];
    const float* gat_adst = (const float*)d_in[10];
    const float* gat_b    = (const float*)d_in[11];
    const float* gcn4_w   = (const float*)d_in[12];
    const float* gcn4_b   = (const float*)d_in[13];
    const float* bn1_g = (const float*)d_in[14]; const float* bn1_b = (const float*)d_in[15];
    const float* bn2_g = (const float*)d_in[16]; const float* bn2_b = (const float*)d_in[17];
    const float* bn3_g = (const float*)d_in[18]; const float* bn3_b = (const float*)d_in[19];
    const float* bn4_g = (const float*)d_in[20]; const float* bn4_b = (const float*)d_in[21];
    const float* fc_w  = (const float*)d_in[22]; const float* fc_b  = (const float*)d_in[23];
    float* out = (float*)d_out;

    const int* src = ei;
    const int* dst = ei + EE;

    float *A, *B, *C, *D;
    cudaGetSymbolAddress((void**)&A, g_bufA);
    cudaGetSymbolAddress((void**)&B, g_bufB);
    cudaGetSymbolAddress((void**)&C, g_bufC);
    cudaGetSymbolAddress((void**)&D, g_bufD);

    // graph build
    k_zero_setup<<<NN / 256, 256>>>();
    k_deg<<<EE / 256, 256>>>(dst);
    k_scan<<<1, 512>>>();
    k_csr_fill<<<EE / 256, 256>>>(src, dst);
    k_dis<<<NN / 256, 256>>>();

    // ---- layer 1: GCN(5->64) + BN + ReLU ----
    k_gemm_small<<<dim3(1, NN / 128), 256>>>(x, gcn1_w, C, NN, 5, 64);
    k_gcn_agg<<<NN, 64>>>(C, gcn1_b, D, 64);      // D holds pre-BN [N,64]
    k_zero_bn<<<1, 512>>>();
    k_bn_stats<<<NN / 64, 64>>>(D, 64);
    // write h into packed buffer B[N,128] cols 64..127
    k_bn_apply<<<NN * 64 / 256, 256>>>(D, bn1_g, bn1_b, B, 64, 128, 64);

    // ---- layer 2: SAGE(64->128) + BN + ReLU (fused single GEMM) ----
    k_sage_agg<<<NN, 64>>>(B);                    // fills cols 0..63
    k_gemm_tf32<<<dim3(1, NN / 128), 256>>>(B, sage_wl, sage_wr, 64, sage_b, C, NN, 128, 128);
    k_zero_bn<<<1, 512>>>();
    k_bn_stats<<<NN / 64, 128>>>(C, 128);
    k_bn_apply<<<NN * 128 / 256, 256>>>(C, bn2_g, bn2_b, D, 128, 128, 0);

    // ---- layer 3: GAT(128->4x256, head-mean) + BN + ReLU ----
    k_gemm_tf32<<<dim3(8, NN / 128), 256>>>(D, gat_w, nullptr, 128, nullptr, A, NN, 128, 1024);
    k_gat_scores<<<NN, 128>>>(A, gat_asrc, gat_adst);
    k_gat_node<<<NN, 256>>>(A, gat_b, C);
    k_zero_bn<<<1, 512>>>();
    k_bn_stats<<<NN / 64, 256>>>(C, 256);
    k_bn_apply<<<NN * 256 / 256, 256>>>(C, bn3_g, bn3_b, D, 256, 256, 0);

    // ---- layer 4: GCN(256->512) + BN + ReLU ----
    k_gemm_tf32<<<dim3(4, NN / 128), 256>>>(D, gcn4_w, nullptr, 256, nullptr, B, NN, 256, 512);
    k_gcn_agg<<<NN, 256>>>(B, gcn4_b, C, 512);
    k_zero_bn<<<1, 512>>>();
    k_bn_stats<<<NN / 64, 512>>>(C, 512);
    k_bn_apply<<<NN * 512 / 256, 256>>>(C, bn4_g, bn4_b, D, 512, 512, 0);

    // ---- pooling + FC ----
    k_gstart<<<1, 64>>>(batch);
    k_pool<<<dim3(GG, 2), 256>>>();
    k_fc<<<dim3(8, 8), 128>>>(fc_w, fc_b, out);
}

// round 4
// speedup vs baseline: 1.5645x; 1.1736x over previous
#include <cuda_runtime.h>
#include <mma.h>
#include <math.h>

using namespace nvcuda;

#define NN 16384
#define EE 131072
#define GG 32
#define BN_EPS 1e-5f

// ---------------- scratch (device globals: no allocation allowed) ----------
__device__ float g_bufA[NN * 1024];   // GAT hidden hg [N,1024]  (64 MB)
__device__ float g_bufB[NN * 512];    // xa / packed sage / agg  (32 MB)
__device__ float g_bufC[NN * 512];    // pre-BN buffers          (32 MB)
__device__ float g_bufD[NN * 512];    // post-BN (layer output)  (32 MB)
__device__ float g_es[NN * 4];
__device__ float g_ed[NN * 4];
__device__ int   g_deg[NN];
__device__ int   g_rowptr[NN + 1];
__device__ int   g_cursor[NN];
__device__ int   g_csr[EE];
__device__ float g_dis[NN];
__device__ float g_bnsum[2048];       // 4 layers: offsets 0,512,1024,1536
__device__ float g_bnsq[2048];
__device__ float g_pooled[GG * 1024];
__device__ int   g_gstart[GG + 1];

// ---------------- graph building -------------------------------------------
__global__ void k_zero_setup() {
    int i = blockIdx.x * blockDim.x + threadIdx.x;
    if (i < NN) { g_deg[i] = 0; g_cursor[i] = 0; }
    if (i < 2048) { g_bnsum[i] = 0.f; g_bnsq[i] = 0.f; }
}

__global__ void k_deg(const int* __restrict__ dst) {
    int e = blockIdx.x * blockDim.x + threadIdx.x;
    if (e < EE) atomicAdd(&g_deg[dst[e]], 1);
}

// exclusive scan of g_deg -> g_rowptr ; also writes g_dis
__global__ void k_scan() {
    __shared__ int sh[512];
    int tid = threadIdx.x;
    int base = tid * 32;
    int s = 0;
    for (int i = 0; i < 32; i++) s += g_deg[base + i];
    sh[tid] = s;
    __syncthreads();
    for (int off = 1; off < 512; off <<= 1) {
        int v = (tid >= off) ? sh[tid - off] : 0;
        __syncthreads();
        sh[tid] += v;
        __syncthreads();
    }
    int run = sh[tid] - s;
    for (int i = 0; i < 32; i++) {
        int dg = g_deg[base + i];
        g_rowptr[base + i] = run;
        g_dis[base + i] = rsqrtf((float)dg + 1.0f);
        run += dg;
    }
    if (tid == 511) g_rowptr[NN] = sh[511];
}

__global__ void k_csr_fill(const int* __restrict__ src, const int* __restrict__ dst) {
    int e = blockIdx.x * blockDim.x + threadIdx.x;
    if (e < EE) {
        int d = dst[e];
        int pos = g_rowptr[d] + atomicAdd(&g_cursor[d], 1);
        g_csr[pos] = src[e];
    }
}

// ---------------- layer-1: aggregate raw x (5 channels), warp per node -----
__global__ void k_aggx5(const float* __restrict__ x, float* __restrict__ xa) {
    int gw = (blockIdx.x * blockDim.x + threadIdx.x) >> 5;
    int lane = threadIdx.x & 31;
    if (gw >= NN) return;
    int d = gw;
    int st = g_rowptr[d], deg = g_rowptr[d + 1] - st;
    float disd = g_dis[d];
    float a = 0.f;
    for (int i = 0; i < deg; i++) {
        int s = g_csr[st + i];
        float w = g_dis[s];
        if (lane < 5) a += x[s * 5 + lane] * w;
    }
    if (lane < 5) {
        a += x[d * 5 + lane] * disd;
        xa[d * 5 + lane] = a * disd;
    }
}

// ---------------- small generic GEMM (K=5 layer) ----------------------------
__global__ __launch_bounds__(256) void k_gemm_small(
    const float* __restrict__ A, const float* __restrict__ W,
    float* __restrict__ C, int M, int K, int Nn)
{
    __shared__ float As[8][128];
    __shared__ float Bs[8][128];
    int tid = threadIdx.x;
    int tx = tid & 15, ty = tid >> 4;
    int row0 = blockIdx.y * 128, col0 = blockIdx.x * 128;
    float accum[8][8];
#pragma unroll
    for (int i = 0; i < 8; i++)
#pragma unroll
        for (int j = 0; j < 8; j++) accum[i][j] = 0.f;

    int arow = tid >> 1, acol0 = (tid & 1) * 4;
    int brow = tid >> 5, bcol0 = (tid & 31) * 4;

    for (int k0 = 0; k0 < K; k0 += 8) {
#pragma unroll
        for (int i = 0; i < 4; i++) {
            int kk = k0 + acol0 + i;
            As[acol0 + i][arow] = (kk < K) ? A[(size_t)(row0 + arow) * K + kk] : 0.f;
        }
#pragma unroll
        for (int i = 0; i < 4; i++) {
            int col = col0 + bcol0 + i;
            int kk = k0 + brow;
            Bs[brow][bcol0 + i] = (kk < K && col < Nn) ? W[(size_t)kk * Nn + col] : 0.f;
        }
        __syncthreads();
#pragma unroll
        for (int kk = 0; kk < 8; kk++) {
            float ra[8], rb[8];
#pragma unroll
            for (int i = 0; i < 8; i++) ra[i] = As[kk][ty * 8 + i];
#pragma unroll
            for (int j = 0; j < 8; j++) rb[j] = Bs[kk][tx * 8 + j];
#pragma unroll
            for (int i = 0; i < 8; i++)
#pragma unroll
                for (int j = 0; j < 8; j++) accum[i][j] += ra[i] * rb[j];
        }
        __syncthreads();
    }
#pragma unroll
    for (int i = 0; i < 8; i++) {
        int r = row0 + ty * 8 + i;
#pragma unroll
        for (int j = 0; j < 8; j++) {
            int cc = col0 + tx * 8 + j;
            if (cc < Nn) C[(size_t)r * Nn + cc] = accum[i][j];
        }
    }
}

// ---------------- TF32 tensor-core GEMM (no bias, direct store) ------------
// C[M,N] = A[M,K] @ Wpack ; rows k<ksplit from W1, else W2.
__global__ __launch_bounds__(256, 2) void k_gemm_tf32(
    const float* __restrict__ A,
    const float* __restrict__ W1, const float* __restrict__ W2, int ksplit,
    float* __restrict__ C, int M, int K, int Nn)
{
    __shared__ float As[128][20];
    __shared__ float Bs[16][132];

    int tid = threadIdx.x;
    int warp = tid >> 5;
    int wm = warp >> 2;
    int wn = warp & 3;
    int row0 = blockIdx.y * 128, col0 = blockIdx.x * 128;

    int a_r[2], a_c[2];
#pragma unroll
    for (int i = 0; i < 2; i++) {
        int s = tid * 2 + i;
        a_r[i] = s >> 2;
        a_c[i] = (s & 3) * 4;
    }
    int b_r[2], b_c[2];
#pragma unroll
    for (int i = 0; i < 2; i++) {
        int s = tid + 256 * i;
        b_r[i] = s >> 5;
        b_c[i] = (s & 31) * 4;
    }

    const float* Abase = A + (size_t)row0 * K;

    float4 cA[2], cB[2];
#pragma unroll
    for (int i = 0; i < 2; i++) {
        cA[i] = *(const float4*)(Abase + (size_t)a_r[i] * K + a_c[i]);
        int k = b_r[i];
        const float* wp = (k < ksplit) ? (W1 + (size_t)k * Nn)
                                       : (W2 + (size_t)(k - ksplit) * Nn);
        cB[i] = *(const float4*)(wp + col0 + b_c[i]);
    }

    wmma::fragment<wmma::accumulator, 16, 16, 8, float> acc[4][2];
#pragma unroll
    for (int i = 0; i < 4; i++)
#pragma unroll
        for (int j = 0; j < 2; j++) wmma::fill_fragment(acc[i][j], 0.f);

    for (int k0 = 0; k0 < K; k0 += 16) {
#pragma unroll
        for (int i = 0; i < 2; i++) {
            *(float4*)&As[a_r[i]][a_c[i]] = cA[i];
            *(float4*)&Bs[b_r[i]][b_c[i]] = cB[i];
        }
        __syncthreads();
        if (k0 + 16 < K) {
#pragma unroll
            for (int i = 0; i < 2; i++) {
                cA[i] = *(const float4*)(Abase + (size_t)a_r[i] * K + (k0 + 16) + a_c[i]);
                int k = k0 + 16 + b_r[i];
                const float* wp = (k < ksplit) ? (W1 + (size_t)k * Nn)
                                               : (W2 + (size_t)(k - ksplit) * Nn);
                cB[i] = *(const float4*)(wp + col0 + b_c[i]);
            }
        }
#pragma unroll
        for (int kk = 0; kk < 16; kk += 8) {
            wmma::fragment<wmma::matrix_a, 16, 16, 8, wmma::precision::tf32, wmma::row_major> af[4];
            wmma::fragment<wmma::matrix_b, 16, 16, 8, wmma::precision::tf32, wmma::row_major> bf[2];
#pragma unroll
            for (int i = 0; i < 4; i++) {
                wmma::load_matrix_sync(af[i], &As[wm * 64 + i * 16][kk], 20);
#pragma unroll
                for (int t = 0; t < af[i].num_elements; t++)
                    af[i].x[t] = wmma::__float_to_tf32(af[i].x[t]);
            }
#pragma unroll
            for (int j = 0; j < 2; j++) {
                wmma::load_matrix_sync(bf[j], &Bs[kk][wn * 32 + j * 16], 132);
#pragma unroll
                for (int t = 0; t < bf[j].num_elements; t++)
                    bf[j].x[t] = wmma::__float_to_tf32(bf[j].x[t]);
            }
#pragma unroll
            for (int i = 0; i < 4; i++)
#pragma unroll
                for (int j = 0; j < 2; j++)
                    wmma::mma_sync(acc[i][j], af[i], bf[j], acc[i][j]);
        }
        __syncthreads();
    }

#pragma unroll
    for (int i = 0; i < 4; i++)
#pragma unroll
        for (int j = 0; j < 2; j++) {
            int gr = row0 + wm * 64 + i * 16;
            int gc = col0 + wn * 32 + j * 16;
            wmma::store_matrix_sync(C + (size_t)gr * Nn + gc, acc[i][j], Nn,
                                    wmma::mem_row_major);
        }
}

// ---------------- GCN aggregation, float4, C multiple of 4 ------------------
// out[d] = dis_d*(sum dis_s*in[s] + dis_d*in[d]) ; blockDim = C/4
__global__ void k_gcn_agg4(const float* __restrict__ in, float* __restrict__ out, int C4)
{
    int d = blockIdx.x;
    int tid = threadIdx.x;
    int st = g_rowptr[d], deg = g_rowptr[d + 1] - st;
    __shared__ int   ssrc[64];
    __shared__ float swgt[64];
    float disd = g_dis[d];
    const float4* in4 = (const float4*)in;
    float4 a = make_float4(0.f, 0.f, 0.f, 0.f);
    for (int base = 0; base < deg; base += 64) {
        int n = min(64, deg - base);
        if (tid < n) {
            int s = g_csr[st + base + tid];
            ssrc[tid] = s;
            swgt[tid] = g_dis[s];
        }
        __syncthreads();
        for (int i = 0; i < n; i++) {
            float4 v = in4[(size_t)ssrc[i] * C4 + tid];
            float w = swgt[i];
            a.x += v.x * w; a.y += v.y * w; a.z += v.z * w; a.w += v.w * w;
        }
        __syncthreads();
    }
    float4 v = in4[(size_t)d * C4 + tid];
    a.x += v.x * disd; a.y += v.y * disd; a.z += v.z * disd; a.w += v.w * disd;
    a.x *= disd; a.y *= disd; a.z *= disd; a.w *= disd;
    ((float4*)out)[(size_t)d * C4 + tid] = a;
}

// ---------------- SAGE mean aggregation into packed buffer -----------------
// P[N,128]: cols 64..127 hold h; writes mean-agg into cols 0..63.
__global__ void k_sage_agg(float* __restrict__ P) {
    int d = blockIdx.x;
    int tid = threadIdx.x;  // 64
    int st = g_rowptr[d], deg = g_rowptr[d + 1] - st;
    __shared__ int ssrc[64];
    float a = 0.f;
    for (int base = 0; base < deg; base += 64) {
        int n = min(64, deg - base);
        if (tid < n) ssrc[tid] = g_csr[st + base + tid];
        __syncthreads();
        for (int i = 0; i < n; i++) a += P[(size_t)ssrc[i] * 128 + 64 + tid];
        __syncthreads();
    }
    P[(size_t)d * 128 + tid] = a / (float)max(deg, 1);
}

// ---------------- BatchNorm ------------------------------------------------
__global__ void k_bn_stats(const float* __restrict__ X, int C, int statoff) {
    int c = threadIdx.x;  // blockDim = C
    int r0 = blockIdx.x * 256;  // grid = 64
    float s = 0.f, q = 0.f;
    for (int r = 0; r < 256; r++) {
        float v = X[(size_t)(r0 + r) * C + c];
        s += v;
        q += v * v;
    }
    atomicAdd(&g_bnsum[statoff + c], s);
    atomicAdd(&g_bnsq[statoff + c], q);
}

// float4 apply+relu; out4[row*ostride4 + ooff4 + c4]
__global__ void k_bn_apply4(const float* __restrict__ in, const float* __restrict__ gam,
                            const float* __restrict__ bet, float* __restrict__ out,
                            int C4, int statoff, int ostride4, int ooff4)
{
    int idx = blockIdx.x * blockDim.x + threadIdx.x;
    int c4 = idx % C4;
    int row = idx / C4;
    float4 v = ((const float4*)in)[idx];
    float inv_n = 1.0f / (float)NN;
    float r[4] = {v.x, v.y, v.z, v.w};
#pragma unroll
    for (int j = 0; j < 4; j++) {
        int c = c4 * 4 + j;
        float mean = g_bnsum[statoff + c] * inv_n;
        float var = g_bnsq[statoff + c] * inv_n - mean * mean;
        float y = (r[j] - mean) * rsqrtf(var + BN_EPS) * gam[c] + bet[c];
        r[j] = fmaxf(y, 0.f);
    }
    ((float4*)out)[(size_t)row * ostride4 + ooff4 + c4] =
        make_float4(r[0], r[1], r[2], r[3]);
}

// ---------------- GAT ------------------------------------------------------
__global__ void k_gat_scores(const float* __restrict__ hg,
                             const float* __restrict__ asrc, const float* __restrict__ adst)
{
    int n = blockIdx.x;
    int tid = threadIdx.x;  // 128
    int h = tid >> 5, lane = tid & 31;
    float ps = 0.f, pd = 0.f;
    size_t b = (size_t)n * 1024 + h * 256;
    for (int c = lane; c < 256; c += 32) {
        float v = hg[b + c];
        ps += v * asrc[h * 256 + c];
        pd += v * adst[h * 256 + c];
    }
#pragma unroll
    for (int o = 16; o > 0; o >>= 1) {
        ps += __shfl_xor_sync(0xffffffffu, ps, o);
        pd += __shfl_xor_sync(0xffffffffu, pd, o);
    }
    if (lane == 0) {
        g_es[n * 4 + h] = ps;
        g_ed[n * 4 + h] = pd;
    }
}

__device__ __forceinline__ float leaky02(float x) { return x > 0.f ? x : 0.2f * x; }

// float4 version: thread t handles head h=t>>6, float4 chunk q=t&63.
__global__ void k_gat_node4(const float* __restrict__ hg, float* __restrict__ out)
{
    int d = blockIdx.x;
    int tid = threadIdx.x;  // 256
    int st = g_rowptr[d], deg = g_rowptr[d + 1] - st;
    __shared__ float s_m[4], s_z[4], s_ed[4];
    __shared__ int   s_src[128];
    __shared__ float s_alpha[128][4];
    __shared__ float4 sred[256];
    if (tid < 4) s_ed[tid] = g_ed[d * 4 + tid];
    __syncthreads();
    int warp = tid >> 5, lane = tid & 31;
    if (warp < 4) {
        int h = warp;
        float edv = s_ed[h];
        float eself = leaky02(g_es[d * 4 + h] + edv);
        float m = eself;
        for (int i = lane; i < deg; i += 32)
            m = fmaxf(m, leaky02(g_es[g_csr[st + i] * 4 + h] + edv));
#pragma unroll
        for (int o = 16; o > 0; o >>= 1) m = fmaxf(m, __shfl_xor_sync(0xffffffffu, m, o));
        float z = (lane == 0) ? __expf(eself - m) : 0.f;
        for (int i = lane; i < deg; i += 32)
            z += __expf(leaky02(g_es[g_csr[st + i] * 4 + h] + edv) - m);
#pragma unroll
        for (int o = 16; o > 0; o >>= 1) z += __shfl_xor_sync(0xffffffffu, z, o);
        if (lane == 0) { s_m[h] = m; s_z[h] = z; }
    }
    __syncthreads();

    int h = tid >> 6, q = tid & 63;
    float4 acc = make_float4(0.f, 0.f, 0.f, 0.f);
    int tot = deg + 1;  // + self loop
    for (int base = 0; base < tot; base += 128) {
        int n = min(128, tot - base);
        if (tid < n) {
            int idx = base + tid;
            int s = (idx < deg) ? g_csr[st + idx] : d;
            s_src[tid] = s;
#pragma unroll
            for (int hh = 0; hh < 4; hh++) {
                float e = leaky02(g_es[s * 4 + hh] + s_ed[hh]);
                s_alpha[tid][hh] = __expf(e - s_m[hh]) / s_z[hh];
            }
        }
        __syncthreads();
        for (int i = 0; i < n; i++) {
            const float4* p = (const float4*)(hg + (size_t)s_src[i] * 1024);
            float4 v = p[h * 64 + q];
            float al = s_alpha[i][h];
            acc.x += v.x * al; acc.y += v.y * al; acc.z += v.z * al; acc.w += v.w * al;
        }
        __syncthreads();
    }
    sred[tid] = acc;
    __syncthreads();
    if (tid < 64) {
        float4 a = sred[tid], b = sred[64 + tid], c = sred[128 + tid], e = sred[192 + tid];
        float4 r;
        r.x = 0.25f * (a.x + b.x + c.x + e.x);
        r.y = 0.25f * (a.y + b.y + c.y + e.y);
        r.z = 0.25f * (a.z + b.z + c.z + e.z);
        r.w = 0.25f * (a.w + b.w + c.w + e.w);
        ((float4*)out)[(size_t)d * 64 + tid] = r;
    }
}

// ---------------- pooling + FC ---------------------------------------------
__global__ void k_gstart(const int* __restrict__ batch) {
    int g = threadIdx.x;
    if (g <= GG) {
        int lo = 0, hi = NN;
        while (lo < hi) {
            int mid = (lo + hi) >> 1;
            if (batch[mid] < g) lo = mid + 1;
            else hi = mid;
        }
        g_gstart[g] = lo;
    }
}

// 128 threads (float4 over 512 ch), grid GG
__global__ void k_pool4() {
    int g = blockIdx.x;
    int c4 = threadIdx.x;
    int st = g_gstart[g], en = g_gstart[g + 1];
    int cnt = en - st;
    const float4* D4 = (const float4*)g_bufD;
    float4 s = make_float4(0.f, 0.f, 0.f, 0.f);
    float4 m = make_float4(-3.4e38f, -3.4e38f, -3.4e38f, -3.4e38f);
    for (int i = st; i < en; i++) {
        float4 v = D4[(size_t)i * 128 + c4];
        s.x += v.x; s.y += v.y; s.z += v.z; s.w += v.w;
        m.x = fmaxf(m.x, v.x); m.y = fmaxf(m.y, v.y);
        m.z = fmaxf(m.z, v.z); m.w = fmaxf(m.w, v.w);
    }
    float inv = 1.f / (float)max(cnt, 1);
    float4* P4 = (float4*)g_pooled;
    P4[g * 256 + c4] = make_float4(s.x * inv, s.y * inv, s.z * inv, s.w * inv);
    if (cnt <= 0) m = make_float4(0.f, 0.f, 0.f, 0.f);
    P4[g * 256 + 128 + c4] = m;
}

__global__ __launch_bounds__(128) void k_fc(const float* __restrict__ W,
                                            const float* __restrict__ bias,
                                            float* __restrict__ out)
{
    __shared__ float sp[4][1024];
    int tid = threadIdx.x;
    int j = blockIdx.x * 128 + tid;
    int g0 = blockIdx.y * 4;
    for (int t = tid; t < 4 * 1024; t += 128)
        sp[t >> 10][t & 1023] = g_pooled[(g0 + (t >> 10)) * 1024 + (t & 1023)];
    __syncthreads();
    float acc[4] = {0.f, 0.f, 0.f, 0.f};
#pragma unroll 4
    for (int kk = 0; kk < 1024; kk++) {
        float wv = W[(size_t)kk * 1024 + j];
#pragma unroll
        for (int g = 0; g < 4; g++) acc[g] += sp[g][kk] * wv;
    }
    float bv = bias[j];
#pragma unroll
    for (int g = 0; g < 4; g++) out[(size_t)(g0 + g) * 1024 + j] = acc[g] + bv;
}

// ---------------- host orchestration ---------------------------------------
extern "C" void kernel_launch(void* const* d_in, const int* in_sizes, int n_in,
                              void* d_out, int out_size)
{
    const float* x        = (const float*)d_in[0];
    const int*   ei       = (const int*)  d_in[1];
    const int*   batch    = (const int*)  d_in[2];
    const float* gcn1_w   = (const float*)d_in[3];
    const float* sage_wl  = (const float*)d_in[5];
    const float* sage_wr  = (const float*)d_in[6];
    const float* gat_w    = (const float*)d_in[8];
    const float* gat_asrc = (const float*)d_in[9];
    const float* gat_adst = (const float*)d_in[10];
    const float* gcn4_w   = (const float*)d_in[12];
    const float* bn1_g = (const float*)d_in[14]; const float* bn1_b = (const float*)d_in[15];
    const float* bn2_g = (const float*)d_in[16]; const float* bn2_b = (const float*)d_in[17];
    const float* bn3_g = (const float*)d_in[18]; const float* bn3_b = (const float*)d_in[19];
    const float* bn4_g = (const float*)d_in[20]; const float* bn4_b = (const float*)d_in[21];
    const float* fc_w  = (const float*)d_in[22]; const float* fc_b  = (const float*)d_in[23];
    float* out = (float*)d_out;

    const int* src = ei;
    const int* dst = ei + EE;

    float *A, *B, *C, *D;
    cudaGetSymbolAddress((void**)&A, g_bufA);
    cudaGetSymbolAddress((void**)&B, g_bufB);
    cudaGetSymbolAddress((void**)&C, g_bufC);
    cudaGetSymbolAddress((void**)&D, g_bufD);

    // graph build (+ BN stat zeroing)
    k_zero_setup<<<NN / 256, 256>>>();
    k_deg<<<EE / 256, 256>>>(dst);
    k_scan<<<1, 512>>>();
    k_csr_fill<<<EE / 256, 256>>>(src, dst);

    // ---- layer 1: GCN(5->64): aggregate-first, then GEMM ----
    k_aggx5<<<NN * 32 / 256, 256>>>(x, B);                 // B = xa [N,5]
    k_gemm_small<<<dim3(1, NN / 128), 256>>>(B, gcn1_w, C, NN, 5, 64);
    k_bn_stats<<<64, 64>>>(C, 64, 0);
    k_bn_apply4<<<NN * 16 / 256, 256>>>(C, bn1_g, bn1_b, B, 16, 0, 32, 16);  // B packed [N,128] cols 64..127

    // ---- layer 2: SAGE(64->128), fused single GEMM ----
    k_sage_agg<<<NN, 64>>>(B);                             // fills cols 0..63
    k_gemm_tf32<<<dim3(1, NN / 128), 256>>>(B, sage_wl, sage_wr, 64, C, NN, 128, 128);
    k_bn_stats<<<64, 128>>>(C, 128, 512);
    k_bn_apply4<<<NN * 32 / 256, 256>>>(C, bn2_g, bn2_b, D, 32, 512, 32, 0);

    // ---- layer 3: GAT(128->4x256, head-mean) ----
    k_gemm_tf32<<<dim3(8, NN / 128), 256>>>(D, gat_w, gat_w, 128, A, NN, 128, 1024);
    k_gat_scores<<<NN, 128>>>(A, gat_asrc, gat_adst);
    k_gat_node4<<<NN, 256>>>(A, C);
    k_bn_stats<<<64, 256>>>(C, 256, 1024);
    k_bn_apply4<<<NN * 64 / 256, 256>>>(C, bn3_g, bn3_b, D, 64, 1024, 64, 0);

    // ---- layer 4: GCN(256->512): aggregate-first, then GEMM ----
    k_gcn_agg4<<<NN, 64>>>(D, B, 64);                      // B = agg [N,256]
    k_gemm_tf32<<<dim3(4, NN / 128), 256>>>(B, gcn4_w, gcn4_w, 256, C, NN, 256, 512);
    k_bn_stats<<<64, 512>>>(C, 512, 1536);
    k_bn_apply4<<<NN * 128 / 256, 256>>>(C, bn4_g, bn4_b, D, 128, 1536, 128, 0);

    // ---- pooling + FC ----
    k_gstart<<<1, 64>>>(batch);
    k_pool4<<<GG, 128>>>();
    k_fc<<<dim3(8, 8), 128>>>(fc_w, fc_b, out);
}

// round 5
// speedup vs baseline: 1.6139x; 1.0316x over previous
#include <cuda_runtime.h>
#include <mma.h>
#include <math.h>

using namespace nvcuda;

#define NN 16384
#define EE 131072
#define GG 32
#define BN_EPS 1e-5f

// ---------------- scratch (device globals: no allocation allowed) ----------
__device__ float g_bufA[NN * 1024];   // GAT hidden hg [N,1024]  (64 MB)
__device__ float g_bufB[NN * 512];    // xa / packed sage / agg  (32 MB)
__device__ float g_bufC[NN * 512];    // pre-BN buffers          (32 MB)
__device__ float g_bufD[NN * 512];    // post-BN layer2 output   (32 MB)
__device__ float g_es[NN * 4];
__device__ float g_ed[NN * 4];
__device__ int   g_deg[NN];
__device__ int   g_rowptr[NN + 1];
__device__ int   g_cursor[NN];
__device__ int   g_csr[EE];
__device__ float g_dis[NN];
__device__ float g_bnsum[2048];       // layers at offsets 0,512,1024,1536
__device__ float g_bnsq[2048];
__device__ float g_wa[1024];          // [sel(2)][head(4)][k(128)]
__device__ float g_pooled[GG * 1024];
__device__ int   g_gstart[GG + 1];

// ---------------- graph building -------------------------------------------
__global__ void k_zero_setup() {
    int i = blockIdx.x * blockDim.x + threadIdx.x;
    if (i < NN) { g_deg[i] = 0; g_cursor[i] = 0; }
    if (i < 2048) { g_bnsum[i] = 0.f; g_bnsq[i] = 0.f; }
}

__global__ void k_deg(const int* __restrict__ dst) {
    int e = blockIdx.x * blockDim.x + threadIdx.x;
    if (e < EE) atomicAdd(&g_deg[dst[e]], 1);
}

__global__ void k_scan() {
    __shared__ int sh[512];
    int tid = threadIdx.x;
    int base = tid * 32;
    int s = 0;
    for (int i = 0; i < 32; i++) s += g_deg[base + i];
    sh[tid] = s;
    __syncthreads();
    for (int off = 1; off < 512; off <<= 1) {
        int v = (tid >= off) ? sh[tid - off] : 0;
        __syncthreads();
        sh[tid] += v;
        __syncthreads();
    }
    int run = sh[tid] - s;
    for (int i = 0; i < 32; i++) {
        int dg = g_deg[base + i];
        g_rowptr[base + i] = run;
        g_dis[base + i] = rsqrtf((float)dg + 1.0f);
        run += dg;
    }
    if (tid == 511) g_rowptr[NN] = sh[511];
}

__global__ void k_csr_fill(const int* __restrict__ src, const int* __restrict__ dst) {
    int e = blockIdx.x * blockDim.x + threadIdx.x;
    if (e < EE) {
        int d = dst[e];
        int pos = g_rowptr[d] + atomicAdd(&g_cursor[d], 1);
        g_csr[pos] = src[e];
    }
}

// ---------------- layer-1: aggregate raw x (5 channels), warp per node -----
__global__ void k_aggx5(const float* __restrict__ x, float* __restrict__ xa) {
    int gw = (blockIdx.x * blockDim.x + threadIdx.x) >> 5;
    int lane = threadIdx.x & 31;
    if (gw >= NN) return;
    int d = gw;
    int st = g_rowptr[d], deg = g_rowptr[d + 1] - st;
    float disd = g_dis[d];
    float a = 0.f;
    for (int i = 0; i < deg; i++) {
        int s = g_csr[st + i];
        float w = g_dis[s];
        if (lane < 5) a += x[s * 5 + lane] * w;
    }
    if (lane < 5) {
        a += x[d * 5 + lane] * disd;
        xa[d * 5 + lane] = a * disd;
    }
}

// ---------------- small generic GEMM (K=5 layer) ----------------------------
__global__ __launch_bounds__(256) void k_gemm_small(
    const float* __restrict__ A, const float* __restrict__ W,
    float* __restrict__ C, int M, int K, int Nn)
{
    __shared__ float As[8][128];
    __shared__ float Bs[8][128];
    int tid = threadIdx.x;
    int tx = tid & 15, ty = tid >> 4;
    int row0 = blockIdx.y * 128, col0 = blockIdx.x * 128;
    float accum[8][8];
#pragma unroll
    for (int i = 0; i < 8; i++)
#pragma unroll
        for (int j = 0; j < 8; j++) accum[i][j] = 0.f;

    int arow = tid >> 1, acol0 = (tid & 1) * 4;
    int brow = tid >> 5, bcol0 = (tid & 31) * 4;

    for (int k0 = 0; k0 < K; k0 += 8) {
#pragma unroll
        for (int i = 0; i < 4; i++) {
            int kk = k0 + acol0 + i;
            As[acol0 + i][arow] = (kk < K) ? A[(size_t)(row0 + arow) * K + kk] : 0.f;
        }
#pragma unroll
        for (int i = 0; i < 4; i++) {
            int col = col0 + bcol0 + i;
            int kk = k0 + brow;
            Bs[brow][bcol0 + i] = (kk < K && col < Nn) ? W[(size_t)kk * Nn + col] : 0.f;
        }
        __syncthreads();
#pragma unroll
        for (int kk = 0; kk < 8; kk++) {
            float ra[8], rb[8];
#pragma unroll
            for (int i = 0; i < 8; i++) ra[i] = As[kk][ty * 8 + i];
#pragma unroll
            for (int j = 0; j < 8; j++) rb[j] = Bs[kk][tx * 8 + j];
#pragma unroll
            for (int i = 0; i < 8; i++)
#pragma unroll
                for (int j = 0; j < 8; j++) accum[i][j] += ra[i] * rb[j];
        }
        __syncthreads();
    }
#pragma unroll
    for (int i = 0; i < 8; i++) {
        int r = row0 + ty * 8 + i;
#pragma unroll
        for (int j = 0; j < 8; j++) {
            int cc = col0 + tx * 8 + j;
            if (cc < Nn) C[(size_t)r * Nn + cc] = accum[i][j];
        }
    }
}

// ---------------- TF32 tensor-core GEMM (no bias, direct store) ------------
__global__ __launch_bounds__(256, 2) void k_gemm_tf32(
    const float* __restrict__ A,
    const float* __restrict__ W1, const float* __restrict__ W2, int ksplit,
    float* __restrict__ C, int M, int K, int Nn)
{
    __shared__ float As[128][20];
    __shared__ float Bs[16][132];

    int tid = threadIdx.x;
    int warp = tid >> 5;
    int wm = warp >> 2;
    int wn = warp & 3;
    int row0 = blockIdx.y * 128, col0 = blockIdx.x * 128;

    int a_r[2], a_c[2];
#pragma unroll
    for (int i = 0; i < 2; i++) {
        int s = tid * 2 + i;
        a_r[i] = s >> 2;
        a_c[i] = (s & 3) * 4;
    }
    int b_r[2], b_c[2];
#pragma unroll
    for (int i = 0; i < 2; i++) {
        int s = tid + 256 * i;
        b_r[i] = s >> 5;
        b_c[i] = (s & 31) * 4;
    }

    const float* Abase = A + (size_t)row0 * K;

    float4 cA[2], cB[2];
#pragma unroll
    for (int i = 0; i < 2; i++) {
        cA[i] = *(const float4*)(Abase + (size_t)a_r[i] * K + a_c[i]);
        int k = b_r[i];
        const float* wp = (k < ksplit) ? (W1 + (size_t)k * Nn)
                                       : (W2 + (size_t)(k - ksplit) * Nn);
        cB[i] = *(const float4*)(wp + col0 + b_c[i]);
    }

    wmma::fragment<wmma::accumulator, 16, 16, 8, float> acc[4][2];
#pragma unroll
    for (int i = 0; i < 4; i++)
#pragma unroll
        for (int j = 0; j < 2; j++) wmma::fill_fragment(acc[i][j], 0.f);

    for (int k0 = 0; k0 < K; k0 += 16) {
#pragma unroll
        for (int i = 0; i < 2; i++) {
            *(float4*)&As[a_r[i]][a_c[i]] = cA[i];
            *(float4*)&Bs[b_r[i]][b_c[i]] = cB[i];
        }
        __syncthreads();
        if (k0 + 16 < K) {
#pragma unroll
            for (int i = 0; i < 2; i++) {
                cA[i] = *(const float4*)(Abase + (size_t)a_r[i] * K + (k0 + 16) + a_c[i]);
                int k = k0 + 16 + b_r[i];
                const float* wp = (k < ksplit) ? (W1 + (size_t)k * Nn)
                                               : (W2 + (size_t)(k - ksplit) * Nn);
                cB[i] = *(const float4*)(wp + col0 + b_c[i]);
            }
        }
#pragma unroll
        for (int kk = 0; kk < 16; kk += 8) {
            wmma::fragment<wmma::matrix_a, 16, 16, 8, wmma::precision::tf32, wmma::row_major> af[4];
            wmma::fragment<wmma::matrix_b, 16, 16, 8, wmma::precision::tf32, wmma::row_major> bf[2];
#pragma unroll
            for (int i = 0; i < 4; i++) {
                wmma::load_matrix_sync(af[i], &As[wm * 64 + i * 16][kk], 20);
#pragma unroll
                for (int t = 0; t < af[i].num_elements; t++)
                    af[i].x[t] = wmma::__float_to_tf32(af[i].x[t]);
            }
#pragma unroll
            for (int j = 0; j < 2; j++) {
                wmma::load_matrix_sync(bf[j], &Bs[kk][wn * 32 + j * 16], 132);
#pragma unroll
                for (int t = 0; t < bf[j].num_elements; t++)
                    bf[j].x[t] = wmma::__float_to_tf32(bf[j].x[t]);
            }
#pragma unroll
            for (int i = 0; i < 4; i++)
#pragma unroll
                for (int j = 0; j < 2; j++)
                    wmma::mma_sync(acc[i][j], af[i], bf[j], acc[i][j]);
        }
        __syncthreads();
    }

#pragma unroll
    for (int i = 0; i < 4; i++)
#pragma unroll
        for (int j = 0; j < 2; j++) {
            int gr = row0 + wm * 64 + i * 16;
            int gc = col0 + wn * 32 + j * 16;
            wmma::store_matrix_sync(C + (size_t)gr * Nn + gc, acc[i][j], Nn,
                                    wmma::mem_row_major);
        }
}

// ---------------- layer-4 GCN gather with fused BN3+ReLU --------------------
// reads pre-BN C3 [N,256], applies bn3 transform per element, gathers.
__global__ void k_gcn_agg4_bn(const float* __restrict__ C3,
                              const float* __restrict__ gam, const float* __restrict__ bet,
                              float* __restrict__ out)
{
    int d = blockIdx.x;
    int tid = threadIdx.x;  // 64, C4 = 64
    int st = g_rowptr[d], deg = g_rowptr[d + 1] - st;
    __shared__ int   ssrc[64];
    __shared__ float swgt[64];
    float disd = g_dis[d];
    // BN3 coefs for my 4 channels (statoff 1024)
    float sc[4], sh[4];
    float inv_n = 1.0f / (float)NN;
#pragma unroll
    for (int j = 0; j < 4; j++) {
        int c = tid * 4 + j;
        float mean = g_bnsum[1024 + c] * inv_n;
        float var = g_bnsq[1024 + c] * inv_n - mean * mean;
        float s = rsqrtf(var + BN_EPS) * gam[c];
        sc[j] = s;
        sh[j] = bet[c] - mean * s;
    }
    const float4* in4 = (const float4*)C3;
    float4 a = make_float4(0.f, 0.f, 0.f, 0.f);
    for (int base = 0; base < deg; base += 64) {
        int n = min(64, deg - base);
        if (tid < n) {
            int s = g_csr[st + base + tid];
            ssrc[tid] = s;
            swgt[tid] = g_dis[s];
        }
        __syncthreads();
        for (int i = 0; i < n; i++) {
            float4 v = in4[(size_t)ssrc[i] * 64 + tid];
            float w = swgt[i];
            a.x += fmaxf(fmaf(v.x, sc[0], sh[0]), 0.f) * w;
            a.y += fmaxf(fmaf(v.y, sc[1], sh[1]), 0.f) * w;
            a.z += fmaxf(fmaf(v.z, sc[2], sh[2]), 0.f) * w;
            a.w += fmaxf(fmaf(v.w, sc[3], sh[3]), 0.f) * w;
        }
        __syncthreads();
    }
    float4 v = in4[(size_t)d * 64 + tid];
    a.x += fmaxf(fmaf(v.x, sc[0], sh[0]), 0.f) * disd;
    a.y += fmaxf(fmaf(v.y, sc[1], sh[1]), 0.f) * disd;
    a.z += fmaxf(fmaf(v.z, sc[2], sh[2]), 0.f) * disd;
    a.w += fmaxf(fmaf(v.w, sc[3], sh[3]), 0.f) * disd;
    a.x *= disd; a.y *= disd; a.z *= disd; a.w *= disd;
    ((float4*)out)[(size_t)d * 64 + tid] = a;
}

// ---------------- SAGE mean aggregation, warp/node, dual-source halves -----
// P[N,128] packed: cols 64..127 (float4 16..31) hold h; writes mean into 0..63.
__global__ void k_sage_agg(float* __restrict__ P) {
    int w = threadIdx.x >> 5;
    int d = blockIdx.x * 8 + w;
    int lane = threadIdx.x & 31;
    int st = g_rowptr[d], deg = g_rowptr[d + 1] - st;
    int half = lane >> 4;
    int c4 = (lane & 15) + 16;
    const float4* P4 = (const float4*)P;
    float4 a = make_float4(0.f, 0.f, 0.f, 0.f);
    for (int i = 0; i < deg; i += 2) {
        int idx = i + half;
        if (idx < deg) {
            int s = g_csr[st + idx];
            float4 v = P4[(size_t)s * 32 + c4];
            a.x += v.x; a.y += v.y; a.z += v.z; a.w += v.w;
        }
    }
    a.x += __shfl_xor_sync(0xffffffffu, a.x, 16);
    a.y += __shfl_xor_sync(0xffffffffu, a.y, 16);
    a.z += __shfl_xor_sync(0xffffffffu, a.z, 16);
    a.w += __shfl_xor_sync(0xffffffffu, a.w, 16);
    if (lane < 16) {
        float inv = 1.f / (float)max(deg, 1);
        ((float4*)P)[(size_t)d * 32 + lane] =
            make_float4(a.x * inv, a.y * inv, a.z * inv, a.w * inv);
    }
}

// ---------------- BatchNorm stats ------------------------------------------
__global__ void k_bn_stats(const float* __restrict__ X, int C, int statoff) {
    int c = threadIdx.x;
    int r0 = blockIdx.x * 256;
    float s = 0.f, q = 0.f;
    for (int r = 0; r < 256; r++) {
        float v = X[(size_t)(r0 + r) * C + c];
        s += v;
        q += v * v;
    }
    atomicAdd(&g_bnsum[statoff + c], s);
    atomicAdd(&g_bnsq[statoff + c], q);
}

__global__ void k_bn_apply4(const float* __restrict__ in, const float* __restrict__ gam,
                            const float* __restrict__ bet, float* __restrict__ out,
                            int C4, int statoff, int ostride4, int ooff4)
{
    int idx = blockIdx.x * blockDim.x + threadIdx.x;
    int c4 = idx % C4;
    int row = idx / C4;
    float4 v = ((const float4*)in)[idx];
    float inv_n = 1.0f / (float)NN;
    float r[4] = {v.x, v.y, v.z, v.w};
#pragma unroll
    for (int j = 0; j < 4; j++) {
        int c = c4 * 4 + j;
        float mean = g_bnsum[statoff + c] * inv_n;
        float var = g_bnsq[statoff + c] * inv_n - mean * mean;
        float y = (r[j] - mean) * rsqrtf(var + BN_EPS) * gam[c] + bet[c];
        r[j] = fmaxf(y, 0.f);
    }
    ((float4*)out)[(size_t)row * ostride4 + ooff4 + c4] =
        make_float4(r[0], r[1], r[2], r[3]);
}

// ---------------- GAT: projected attention vectors --------------------------
// g_wa[sel*512 + h*128 + k] = sum_c gat_w[k*1024 + h*256 + c] * a[h*256 + c]
__global__ void k_wa(const float* __restrict__ gat_w,
                     const float* __restrict__ asrc, const float* __restrict__ adst)
{
    int b = blockIdx.x;       // 0..7 : sel = b>>2, h = b&3
    int k = threadIdx.x;      // 0..127
    int sel = b >> 2, h = b & 3;
    const float* a = (sel == 0) ? asrc : adst;
    float s = 0.f;
    for (int c = 0; c < 256; c++)
        s += gat_w[(size_t)k * 1024 + h * 256 + c] * a[h * 256 + c];
    g_wa[sel * 512 + h * 128 + k] = s;
}

// es/ed[n,h] = sum_k D[n,k] * wa[sel][h][k] ; warp per node
__global__ void k_esed(const float* __restrict__ D) {
    __shared__ float swa[1024];
    int tid = threadIdx.x;  // 256
    for (int t = tid; t < 1024; t += 256) swa[t] = g_wa[t];
    __syncthreads();
    int w = tid >> 5, lane = tid & 31;
    int n = blockIdx.x * 8 + w;
    float4 v = ((const float4*)D)[(size_t)n * 32 + lane];
    float p[8];
#pragma unroll
    for (int s = 0; s < 2; s++)
#pragma unroll
        for (int h = 0; h < 4; h++) {
            float4 wv = ((const float4*)swa)[(s * 512 + h * 128) / 4 + lane];
            p[s * 4 + h] = v.x * wv.x + v.y * wv.y + v.z * wv.z + v.w * wv.w;
        }
#pragma unroll
    for (int o = 16; o > 0; o >>= 1)
#pragma unroll
        for (int j = 0; j < 8; j++)
            p[j] += __shfl_xor_sync(0xffffffffu, p[j], o);
    if (lane < 4) g_es[n * 4 + lane] = p[lane];
    else if (lane < 8) g_ed[n * 4 + (lane - 4)] = p[lane];
}

__device__ __forceinline__ float leaky02(float x) { return x > 0.f ? x : 0.2f * x; }

// per-node softmax attention + float4 weighted gather
__global__ void k_gat_node4(const float* __restrict__ hg, float* __restrict__ out)
{
    int d = blockIdx.x;
    int tid = threadIdx.x;  // 256
    int st = g_rowptr[d], deg = g_rowptr[d + 1] - st;
    __shared__ float s_m[4], s_z[4], s_ed[4];
    __shared__ int   s_src[128];
    __shared__ float s_alpha[128][4];
    __shared__ float4 sred[256];
    if (tid < 4) s_ed[tid] = g_ed[d * 4 + tid];
    __syncthreads();
    int warp = tid >> 5, lane = tid & 31;
    if (warp < 4) {
        int h = warp;
        float edv = s_ed[h];
        float eself = leaky02(g_es[d * 4 + h] + edv);
        float m = eself;
        for (int i = lane; i < deg; i += 32)
            m = fmaxf(m, leaky02(g_es[g_csr[st + i] * 4 + h] + edv));
#pragma unroll
        for (int o = 16; o > 0; o >>= 1) m = fmaxf(m, __shfl_xor_sync(0xffffffffu, m, o));
        float z = (lane == 0) ? __expf(eself - m) : 0.f;
        for (int i = lane; i < deg; i += 32)
            z += __expf(leaky02(g_es[g_csr[st + i] * 4 + h] + edv) - m);
#pragma unroll
        for (int o = 16; o > 0; o >>= 1) z += __shfl_xor_sync(0xffffffffu, z, o);
        if (lane == 0) { s_m[h] = m; s_z[h] = z; }
    }
    __syncthreads();

    int h = tid >> 6, q = tid & 63;
    float4 acc = make_float4(0.f, 0.f, 0.f, 0.f);
    int tot = deg + 1;
    for (int base = 0; base < tot; base += 128) {
        int n = min(128, tot - base);
        if (tid < n) {
            int idx = base + tid;
            int s = (idx < deg) ? g_csr[st + idx] : d;
            s_src[tid] = s;
#pragma unroll
            for (int hh = 0; hh < 4; hh++) {
                float e = leaky02(g_es[s * 4 + hh] + s_ed[hh]);
                s_alpha[tid][hh] = __expf(e - s_m[hh]) / s_z[hh];
            }
        }
        __syncthreads();
        for (int i = 0; i < n; i++) {
            const float4* p = (const float4*)(hg + (size_t)s_src[i] * 1024);
            float4 v = p[h * 64 + q];
            float al = s_alpha[i][h];
            acc.x += v.x * al; acc.y += v.y * al; acc.z += v.z * al; acc.w += v.w * al;
        }
        __syncthreads();
    }
    sred[tid] = acc;
    __syncthreads();
    if (tid < 64) {
        float4 a = sred[tid], b = sred[64 + tid], c = sred[128 + tid], e = sred[192 + tid];
        float4 r;
        r.x = 0.25f * (a.x + b.x + c.x + e.x);
        r.y = 0.25f * (a.y + b.y + c.y + e.y);
        r.z = 0.25f * (a.z + b.z + c.z + e.z);
        r.w = 0.25f * (a.w + b.w + c.w + e.w);
        ((float4*)out)[(size_t)d * 64 + tid] = r;
    }
}

// ---------------- pooling (fused BN4+ReLU) + FC -----------------------------
__global__ void k_gstart(const int* __restrict__ batch) {
    int g = threadIdx.x;
    if (g <= GG) {
        int lo = 0, hi = NN;
        while (lo < hi) {
            int mid = (lo + hi) >> 1;
            if (batch[mid] < g) lo = mid + 1;
            else hi = mid;
        }
        g_gstart[g] = lo;
    }
}

// reads pre-BN C4 [N,512], applies bn4+relu inline, pools mean/max
__global__ void k_pool_bn(const float* __restrict__ C4buf,
                          const float* __restrict__ gam, const float* __restrict__ bet)
{
    int g = blockIdx.x;
    int c4 = threadIdx.x;  // 128
    int st = g_gstart[g], en = g_gstart[g + 1];
    int cnt = en - st;
    float sc[4], sh[4];
    float inv_n = 1.0f / (float)NN;
#pragma unroll
    for (int j = 0; j < 4; j++) {
        int c = c4 * 4 + j;
        float mean = g_bnsum[1536 + c] * inv_n;
        float var = g_bnsq[1536 + c] * inv_n - mean * mean;
        float s = rsqrtf(var + BN_EPS) * gam[c];
        sc[j] = s;
        sh[j] = bet[c] - mean * s;
    }
    const float4* D4 = (const float4*)C4buf;
    float4 s = make_float4(0.f, 0.f, 0.f, 0.f);
    float4 m = make_float4(-3.4e38f, -3.4e38f, -3.4e38f, -3.4e38f);
    for (int i = st; i < en; i++) {
        float4 v = D4[(size_t)i * 128 + c4];
        v.x = fmaxf(fmaf(v.x, sc[0], sh[0]), 0.f);
        v.y = fmaxf(fmaf(v.y, sc[1], sh[1]), 0.f);
        v.z = fmaxf(fmaf(v.z, sc[2], sh[2]), 0.f);
        v.w = fmaxf(fmaf(v.w, sc[3], sh[3]), 0.f);
        s.x += v.x; s.y += v.y; s.z += v.z; s.w += v.w;
        m.x = fmaxf(m.x, v.x); m.y = fmaxf(m.y, v.y);
        m.z = fmaxf(m.z, v.z); m.w = fmaxf(m.w, v.w);
    }
    float inv = 1.f / (float)max(cnt, 1);
    float4* P4 = (float4*)g_pooled;
    P4[g * 256 + c4] = make_float4(s.x * inv, s.y * inv, s.z * inv, s.w * inv);
    if (cnt <= 0) m = make_float4(0.f, 0.f, 0.f, 0.f);
    P4[g * 256 + 128 + c4] = m;
}

__global__ __launch_bounds__(128) void k_fc(const float* __restrict__ W,
                                            const float* __restrict__ bias,
                                            float* __restrict__ out)
{
    __shared__ float sp[4][1024];
    int tid = threadIdx.x;
    int j = blockIdx.x * 128 + tid;
    int g0 = blockIdx.y * 4;
    for (int t = tid; t < 4 * 1024; t += 128)
        sp[t >> 10][t & 1023] = g_pooled[(g0 + (t >> 10)) * 1024 + (t & 1023)];
    __syncthreads();
    float acc[4] = {0.f, 0.f, 0.f, 0.f};
#pragma unroll 4
    for (int kk = 0; kk < 1024; kk++) {
        float wv = W[(size_t)kk * 1024 + j];
#pragma unroll
        for (int g = 0; g < 4; g++) acc[g] += sp[g][kk] * wv;
    }
    float bv = bias[j];
#pragma unroll
    for (int g = 0; g < 4; g++) out[(size_t)(g0 + g) * 1024 + j] = acc[g] + bv;
}

// ---------------- host orchestration ---------------------------------------
extern "C" void kernel_launch(void* const* d_in, const int* in_sizes, int n_in,
                              void* d_out, int out_size)
{
    const float* x        = (const float*)d_in[0];
    const int*   ei       = (const int*)  d_in[1];
    const int*   batch    = (const int*)  d_in[2];
    const float* gcn1_w   = (const float*)d_in[3];
    const float* sage_wl  = (const float*)d_in[5];
    const float* sage_wr  = (const float*)d_in[6];
    const float* gat_w    = (const float*)d_in[8];
    const float* gat_asrc = (const float*)d_in[9];
    const float* gat_adst = (const float*)d_in[10];
    const float* gcn4_w   = (const float*)d_in[12];
    const float* bn1_g = (const float*)d_in[14]; const float* bn1_b = (const float*)d_in[15];
    const float* bn2_g = (const float*)d_in[16]; const float* bn2_b = (const float*)d_in[17];
    const float* bn3_g = (const float*)d_in[18]; const float* bn3_b = (const float*)d_in[19];
    const float* bn4_g = (const float*)d_in[20]; const float* bn4_b = (const float*)d_in[21];
    const float* fc_w  = (const float*)d_in[22]; const float* fc_b  = (const float*)d_in[23];
    float* out = (float*)d_out;

    const int* src = ei;
    const int* dst = ei + EE;

    float *A, *B, *C, *D;
    cudaGetSymbolAddress((void**)&A, g_bufA);
    cudaGetSymbolAddress((void**)&B, g_bufB);
    cudaGetSymbolAddress((void**)&C, g_bufC);
    cudaGetSymbolAddress((void**)&D, g_bufD);

    // graph build (+ BN stat zeroing)
    k_zero_setup<<<NN / 256, 256>>>();
    k_deg<<<EE / 256, 256>>>(dst);
    k_scan<<<1, 512>>>();
    k_csr_fill<<<EE / 256, 256>>>(src, dst);

    // ---- layer 1: GCN(5->64): aggregate-first, then GEMM ----
    k_aggx5<<<NN * 32 / 256, 256>>>(x, B);                 // B = xa [N,5]
    k_gemm_small<<<dim3(1, NN / 128), 256>>>(B, gcn1_w, C, NN, 5, 64);
    k_bn_stats<<<64, 64>>>(C, 64, 0);
    k_bn_apply4<<<NN * 16 / 256, 256>>>(C, bn1_g, bn1_b, B, 16, 0, 32, 16);

    // ---- layer 2: SAGE(64->128), fused single GEMM ----
    k_sage_agg<<<NN / 8, 256>>>(B);                        // fills cols 0..63
    k_gemm_tf32<<<dim3(1, NN / 128), 256>>>(B, sage_wl, sage_wr, 64, C, NN, 128, 128);
    k_bn_stats<<<64, 128>>>(C, 128, 512);
    k_bn_apply4<<<NN * 32 / 256, 256>>>(C, bn2_g, bn2_b, D, 32, 512, 32, 0);

    // ---- layer 3: GAT(128->4x256, head-mean) ----
    k_wa<<<8, 128>>>(gat_w, gat_asrc, gat_adst);
    k_gemm_tf32<<<dim3(8, NN / 128), 256>>>(D, gat_w, gat_w, 128, A, NN, 128, 1024);
    k_esed<<<NN / 8, 256>>>(D);
    k_gat_node4<<<NN, 256>>>(A, C);
    k_bn_stats<<<64, 256>>>(C, 256, 1024);

    // ---- layer 4: GCN(256->512): BN3 fused into gather, then GEMM ----
    k_gcn_agg4_bn<<<NN, 64>>>(C, bn3_g, bn3_b, B);         // B = agg [N,256]
    k_gemm_tf32<<<dim3(4, NN / 128), 256>>>(B, gcn4_w, gcn4_w, 256, C, NN, 256, 512);
    k_bn_stats<<<64, 512>>>(C, 512, 1536);

    // ---- pooling (BN4 fused) + FC ----
    k_gstart<<<1, 64>>>(batch);
    k_pool_bn<<<GG, 128>>>(C, bn4_g, bn4_b);
    k_fc<<<dim3(8, 8), 128>>>(fc_w, fc_b, out);
}

// round 6
// speedup vs baseline: 1.6546x; 1.0252x over previous
#include <cuda_runtime.h>
#include <mma.h>
#include <math.h>

using namespace nvcuda;

#define NN 16384
#define EE 131072
#define GG 32
#define BN_EPS 1e-5f

// ---------------- scratch (device globals: no allocation allowed) ----------
__device__ float g_bufA[NN * 512];    // GAT per-head agg [N,512] (32 MB)
__device__ float g_bufB[NN * 512];    // xa / packed sage / agg   (32 MB)
__device__ float g_bufC[NN * 512];    // pre-BN buffers           (32 MB)
__device__ float g_bufD[NN * 512];    // post-BN layer2 output    (32 MB)
__device__ float g_es[NN * 4];
__device__ float g_ed[NN * 4];
__device__ int   g_deg[NN];
__device__ int   g_rowptr[NN + 1];
__device__ int   g_cursor[NN];
__device__ int   g_csr[EE];
__device__ float g_dis[NN];
__device__ float g_bnsum[2048];       // layers at offsets 0,512,1024,1536
__device__ float g_bnsq[2048];
__device__ float g_wa[1024];          // [sel(2)][head(4)][k(128)]
__device__ float g_pooled[GG * 1024];
__device__ int   g_gstart[GG + 1];

// ---------------- graph building -------------------------------------------
__global__ void k_zero_setup() {
    int i = blockIdx.x * blockDim.x + threadIdx.x;
    if (i < NN) { g_deg[i] = 0; g_cursor[i] = 0; }
    if (i < 2048) { g_bnsum[i] = 0.f; g_bnsq[i] = 0.f; }
}

__global__ void k_deg(const int* __restrict__ dst) {
    int e = blockIdx.x * blockDim.x + threadIdx.x;
    if (e < EE) atomicAdd(&g_deg[dst[e]], 1);
}

__global__ void k_scan() {
    __shared__ int sh[512];
    int tid = threadIdx.x;
    int base = tid * 32;
    int s = 0;
    for (int i = 0; i < 32; i++) s += g_deg[base + i];
    sh[tid] = s;
    __syncthreads();
    for (int off = 1; off < 512; off <<= 1) {
        int v = (tid >= off) ? sh[tid - off] : 0;
        __syncthreads();
        sh[tid] += v;
        __syncthreads();
    }
    int run = sh[tid] - s;
    for (int i = 0; i < 32; i++) {
        int dg = g_deg[base + i];
        g_rowptr[base + i] = run;
        g_dis[base + i] = rsqrtf((float)dg + 1.0f);
        run += dg;
    }
    if (tid == 511) g_rowptr[NN] = sh[511];
}

__global__ void k_csr_fill(const int* __restrict__ src, const int* __restrict__ dst) {
    int e = blockIdx.x * blockDim.x + threadIdx.x;
    if (e < EE) {
        int d = dst[e];
        int pos = g_rowptr[d] + atomicAdd(&g_cursor[d], 1);
        g_csr[pos] = src[e];
    }
}

// ---------------- layer-1: aggregate raw x (5 channels), warp per node -----
__global__ void k_aggx5(const float* __restrict__ x, float* __restrict__ xa) {
    int gw = (blockIdx.x * blockDim.x + threadIdx.x) >> 5;
    int lane = threadIdx.x & 31;
    if (gw >= NN) return;
    int d = gw;
    int st = g_rowptr[d], deg = g_rowptr[d + 1] - st;
    float disd = g_dis[d];
    float a = 0.f;
    for (int i = 0; i < deg; i++) {
        int s = g_csr[st + i];
        float w = g_dis[s];
        if (lane < 5) a += x[s * 5 + lane] * w;
    }
    if (lane < 5) {
        a += x[d * 5 + lane] * disd;
        xa[d * 5 + lane] = a * disd;
    }
}

// ---------------- small generic GEMM (K=5 layer) ----------------------------
__global__ __launch_bounds__(256) void k_gemm_small(
    const float* __restrict__ A, const float* __restrict__ W,
    float* __restrict__ C, int M, int K, int Nn)
{
    __shared__ float As[8][128];
    __shared__ float Bs[8][128];
    int tid = threadIdx.x;
    int tx = tid & 15, ty = tid >> 4;
    int row0 = blockIdx.y * 128, col0 = blockIdx.x * 128;
    float accum[8][8];
#pragma unroll
    for (int i = 0; i < 8; i++)
#pragma unroll
        for (int j = 0; j < 8; j++) accum[i][j] = 0.f;

    int arow = tid >> 1, acol0 = (tid & 1) * 4;
    int brow = tid >> 5, bcol0 = (tid & 31) * 4;

    for (int k0 = 0; k0 < K; k0 += 8) {
#pragma unroll
        for (int i = 0; i < 4; i++) {
            int kk = k0 + acol0 + i;
            As[acol0 + i][arow] = (kk < K) ? A[(size_t)(row0 + arow) * K + kk] : 0.f;
        }
#pragma unroll
        for (int i = 0; i < 4; i++) {
            int col = col0 + bcol0 + i;
            int kk = k0 + brow;
            Bs[brow][bcol0 + i] = (kk < K && col < Nn) ? W[(size_t)kk * Nn + col] : 0.f;
        }
        __syncthreads();
#pragma unroll
        for (int kk = 0; kk < 8; kk++) {
            float ra[8], rb[8];
#pragma unroll
            for (int i = 0; i < 8; i++) ra[i] = As[kk][ty * 8 + i];
#pragma unroll
            for (int j = 0; j < 8; j++) rb[j] = Bs[kk][tx * 8 + j];
#pragma unroll
            for (int i = 0; i < 8; i++)
#pragma unroll
                for (int j = 0; j < 8; j++) accum[i][j] += ra[i] * rb[j];
        }
        __syncthreads();
    }
#pragma unroll
    for (int i = 0; i < 8; i++) {
        int r = row0 + ty * 8 + i;
#pragma unroll
        for (int j = 0; j < 8; j++) {
            int cc = col0 + tx * 8 + j;
            if (cc < Nn) C[(size_t)r * Nn + cc] = accum[i][j];
        }
    }
}

// ---------------- TF32 tensor-core GEMM (no bias, direct store) ------------
// gatmode==0: B row k -> (k<ksplit ? W1[k] : W2[k-ksplit])
// gatmode==1: B row k -> gat stacked: W1 + (k&127)*1024 + (k>>7)*256
__global__ __launch_bounds__(256, 2) void k_gemm_tf32(
    const float* __restrict__ A,
    const float* __restrict__ W1, const float* __restrict__ W2, int ksplit,
    float* __restrict__ C, int M, int K, int Nn, int gatmode)
{
    __shared__ float As[128][20];
    __shared__ float Bs[16][132];

    int tid = threadIdx.x;
    int warp = tid >> 5;
    int wm = warp >> 2;
    int wn = warp & 3;
    int row0 = blockIdx.y * 128, col0 = blockIdx.x * 128;

    int a_r[2], a_c[2];
#pragma unroll
    for (int i = 0; i < 2; i++) {
        int s = tid * 2 + i;
        a_r[i] = s >> 2;
        a_c[i] = (s & 3) * 4;
    }
    int b_r[2], b_c[2];
#pragma unroll
    for (int i = 0; i < 2; i++) {
        int s = tid + 256 * i;
        b_r[i] = s >> 5;
        b_c[i] = (s & 31) * 4;
    }

    const float* Abase = A + (size_t)row0 * K;

    float4 cA[2], cB[2];
#pragma unroll
    for (int i = 0; i < 2; i++) {
        cA[i] = *(const float4*)(Abase + (size_t)a_r[i] * K + a_c[i]);
        int k = b_r[i];
        const float* wp;
        if (gatmode) wp = W1 + (size_t)(k & 127) * 1024 + (k >> 7) * 256;
        else wp = (k < ksplit) ? (W1 + (size_t)k * Nn)
                               : (W2 + (size_t)(k - ksplit) * Nn);
        cB[i] = *(const float4*)(wp + col0 + b_c[i]);
    }

    wmma::fragment<wmma::accumulator, 16, 16, 8, float> acc[4][2];
#pragma unroll
    for (int i = 0; i < 4; i++)
#pragma unroll
        for (int j = 0; j < 2; j++) wmma::fill_fragment(acc[i][j], 0.f);

    for (int k0 = 0; k0 < K; k0 += 16) {
#pragma unroll
        for (int i = 0; i < 2; i++) {
            *(float4*)&As[a_r[i]][a_c[i]] = cA[i];
            *(float4*)&Bs[b_r[i]][b_c[i]] = cB[i];
        }
        __syncthreads();
        if (k0 + 16 < K) {
#pragma unroll
            for (int i = 0; i < 2; i++) {
                cA[i] = *(const float4*)(Abase + (size_t)a_r[i] * K + (k0 + 16) + a_c[i]);
                int k = k0 + 16 + b_r[i];
                const float* wp;
                if (gatmode) wp = W1 + (size_t)(k & 127) * 1024 + (k >> 7) * 256;
                else wp = (k < ksplit) ? (W1 + (size_t)k * Nn)
                                       : (W2 + (size_t)(k - ksplit) * Nn);
                cB[i] = *(const float4*)(wp + col0 + b_c[i]);
            }
        }
#pragma unroll
        for (int kk = 0; kk < 16; kk += 8) {
            wmma::fragment<wmma::matrix_a, 16, 16, 8, wmma::precision::tf32, wmma::row_major> af[4];
            wmma::fragment<wmma::matrix_b, 16, 16, 8, wmma::precision::tf32, wmma::row_major> bf[2];
#pragma unroll
            for (int i = 0; i < 4; i++) {
                wmma::load_matrix_sync(af[i], &As[wm * 64 + i * 16][kk], 20);
#pragma unroll
                for (int t = 0; t < af[i].num_elements; t++)
                    af[i].x[t] = wmma::__float_to_tf32(af[i].x[t]);
            }
#pragma unroll
            for (int j = 0; j < 2; j++) {
                wmma::load_matrix_sync(bf[j], &Bs[kk][wn * 32 + j * 16], 132);
#pragma unroll
                for (int t = 0; t < bf[j].num_elements; t++)
                    bf[j].x[t] = wmma::__float_to_tf32(bf[j].x[t]);
            }
#pragma unroll
            for (int i = 0; i < 4; i++)
#pragma unroll
                for (int j = 0; j < 2; j++)
                    wmma::mma_sync(acc[i][j], af[i], bf[j], acc[i][j]);
        }
        __syncthreads();
    }

#pragma unroll
    for (int i = 0; i < 4; i++)
#pragma unroll
        for (int j = 0; j < 2; j++) {
            int gr = row0 + wm * 64 + i * 16;
            int gc = col0 + wn * 32 + j * 16;
            wmma::store_matrix_sync(C + (size_t)gr * Nn + gc, acc[i][j], Nn,
                                    wmma::mem_row_major);
        }
}

// ---------------- layer-4 GCN gather with fused BN3+ReLU --------------------
__global__ void k_gcn_agg4_bn(const float* __restrict__ C3,
                              const float* __restrict__ gam, const float* __restrict__ bet,
                              float* __restrict__ out)
{
    int d = blockIdx.x;
    int tid = threadIdx.x;  // 64, C4 = 64
    int st = g_rowptr[d], deg = g_rowptr[d + 1] - st;
    __shared__ int   ssrc[64];
    __shared__ float swgt[64];
    float disd = g_dis[d];
    float sc[4], sh[4];
    float inv_n = 1.0f / (float)NN;
#pragma unroll
    for (int j = 0; j < 4; j++) {
        int c = tid * 4 + j;
        float mean = g_bnsum[1024 + c] * inv_n;
        float var = g_bnsq[1024 + c] * inv_n - mean * mean;
        float s = rsqrtf(var + BN_EPS) * gam[c];
        sc[j] = s;
        sh[j] = bet[c] - mean * s;
    }
    const float4* in4 = (const float4*)C3;
    float4 a = make_float4(0.f, 0.f, 0.f, 0.f);
    for (int base = 0; base < deg; base += 64) {
        int n = min(64, deg - base);
        if (tid < n) {
            int s = g_csr[st + base + tid];
            ssrc[tid] = s;
            swgt[tid] = g_dis[s];
        }
        __syncthreads();
        for (int i = 0; i < n; i++) {
            float4 v = in4[(size_t)ssrc[i] * 64 + tid];
            float w = swgt[i];
            a.x += fmaxf(fmaf(v.x, sc[0], sh[0]), 0.f) * w;
            a.y += fmaxf(fmaf(v.y, sc[1], sh[1]), 0.f) * w;
            a.z += fmaxf(fmaf(v.z, sc[2], sh[2]), 0.f) * w;
            a.w += fmaxf(fmaf(v.w, sc[3], sh[3]), 0.f) * w;
        }
        __syncthreads();
    }
    float4 v = in4[(size_t)d * 64 + tid];
    a.x += fmaxf(fmaf(v.x, sc[0], sh[0]), 0.f) * disd;
    a.y += fmaxf(fmaf(v.y, sc[1], sh[1]), 0.f) * disd;
    a.z += fmaxf(fmaf(v.z, sc[2], sh[2]), 0.f) * disd;
    a.w += fmaxf(fmaf(v.w, sc[3], sh[3]), 0.f) * disd;
    a.x *= disd; a.y *= disd; a.z *= disd; a.w *= disd;
    ((float4*)out)[(size_t)d * 64 + tid] = a;
}

// ---------------- SAGE mean aggregation, warp/node --------------------------
__global__ void k_sage_agg(float* __restrict__ P) {
    int w = threadIdx.x >> 5;
    int d = blockIdx.x * 8 + w;
    int lane = threadIdx.x & 31;
    int st = g_rowptr[d], deg = g_rowptr[d + 1] - st;
    int half = lane >> 4;
    int c4 = (lane & 15) + 16;
    const float4* P4 = (const float4*)P;
    float4 a = make_float4(0.f, 0.f, 0.f, 0.f);
    for (int i = 0; i < deg; i += 2) {
        int idx = i + half;
        if (idx < deg) {
            int s = g_csr[st + idx];
            float4 v = P4[(size_t)s * 32 + c4];
            a.x += v.x; a.y += v.y; a.z += v.z; a.w += v.w;
        }
    }
    a.x += __shfl_xor_sync(0xffffffffu, a.x, 16);
    a.y += __shfl_xor_sync(0xffffffffu, a.y, 16);
    a.z += __shfl_xor_sync(0xffffffffu, a.z, 16);
    a.w += __shfl_xor_sync(0xffffffffu, a.w, 16);
    if (lane < 16) {
        float inv = 1.f / (float)max(deg, 1);
        ((float4*)P)[(size_t)d * 32 + lane] =
            make_float4(a.x * inv, a.y * inv, a.z * inv, a.w * inv);
    }
}

// ---------------- BatchNorm stats ------------------------------------------
__global__ void k_bn_stats(const float* __restrict__ X, int C, int statoff) {
    int c = threadIdx.x;
    int r0 = blockIdx.x * 256;
    float s = 0.f, q = 0.f;
    for (int r = 0; r < 256; r++) {
        float v = X[(size_t)(r0 + r) * C + c];
        s += v;
        q += v * v;
    }
    atomicAdd(&g_bnsum[statoff + c], s);
    atomicAdd(&g_bnsq[statoff + c], q);
}

__global__ void k_bn_apply4(const float* __restrict__ in, const float* __restrict__ gam,
                            const float* __restrict__ bet, float* __restrict__ out,
                            int C4, int statoff, int ostride4, int ooff4)
{
    int idx = blockIdx.x * blockDim.x + threadIdx.x;
    int c4 = idx % C4;
    int row = idx / C4;
    float4 v = ((const float4*)in)[idx];
    float inv_n = 1.0f / (float)NN;
    float r[4] = {v.x, v.y, v.z, v.w};
#pragma unroll
    for (int j = 0; j < 4; j++) {
        int c = c4 * 4 + j;
        float mean = g_bnsum[statoff + c] * inv_n;
        float var = g_bnsq[statoff + c] * inv_n - mean * mean;
        float y = (r[j] - mean) * rsqrtf(var + BN_EPS) * gam[c] + bet[c];
        r[j] = fmaxf(y, 0.f);
    }
    ((float4*)out)[(size_t)row * ostride4 + ooff4 + c4] =
        make_float4(r[0], r[1], r[2], r[3]);
}

// ---------------- GAT: projected attention vectors --------------------------
__global__ void k_wa(const float* __restrict__ gat_w,
                     const float* __restrict__ asrc, const float* __restrict__ adst)
{
    int b = blockIdx.x;       // 0..7 : sel = b>>2, h = b&3
    int k = threadIdx.x;      // 0..127
    int sel = b >> 2, h = b & 3;
    const float* a = (sel == 0) ? asrc : adst;
    float s = 0.f;
    for (int c = 0; c < 256; c++)
        s += gat_w[(size_t)k * 1024 + h * 256 + c] * a[h * 256 + c];
    g_wa[sel * 512 + h * 128 + k] = s;
}

// es/ed[n,h] = sum_k D[n,k] * wa[sel][h][k] ; warp per node
__global__ void k_esed(const float* __restrict__ D) {
    __shared__ float swa[1024];
    int tid = threadIdx.x;  // 256
    for (int t = tid; t < 1024; t += 256) swa[t] = g_wa[t];
    __syncthreads();
    int w = tid >> 5, lane = tid & 31;
    int n = blockIdx.x * 8 + w;
    float4 v = ((const float4*)D)[(size_t)n * 32 + lane];
    float p[8];
#pragma unroll
    for (int s = 0; s < 2; s++)
#pragma unroll
        for (int h = 0; h < 4; h++) {
            float4 wv = ((const float4*)swa)[(s * 512 + h * 128) / 4 + lane];
            p[s * 4 + h] = v.x * wv.x + v.y * wv.y + v.z * wv.z + v.w * wv.w;
        }
#pragma unroll
    for (int o = 16; o > 0; o >>= 1)
#pragma unroll
        for (int j = 0; j < 8; j++)
            p[j] += __shfl_xor_sync(0xffffffffu, p[j], o);
    if (lane < 4) g_es[n * 4 + lane] = p[lane];
    else if (lane < 8) g_ed[n * 4 + (lane - 4)] = p[lane];
}

__device__ __forceinline__ float leaky02(float x) { return x > 0.f ? x : 0.2f * x; }

// per-node softmax + per-head aggregation of D (128 ch) -> agg[N,512]
// agg[d, h*128 + k] = sum_s alpha_{s,h} * D[s,k]  (incl. self loop)
__global__ void k_gat_agg(const float* __restrict__ D, float* __restrict__ agg)
{
    int d = blockIdx.x;
    int tid = threadIdx.x;  // 128: h = tid>>5, q = tid&31 (float4 chunk of 128ch)
    int st = g_rowptr[d], deg = g_rowptr[d + 1] - st;
    __shared__ float s_m[4], s_z[4], s_ed[4];
    __shared__ int   s_src[128];
    __shared__ float s_alpha[128][4];
    if (tid < 4) s_ed[tid] = g_ed[d * 4 + tid];
    __syncthreads();
    int warp = tid >> 5, lane = tid & 31;
    {
        int h = warp;
        float edv = s_ed[h];
        float eself = leaky02(g_es[d * 4 + h] + edv);
        float m = eself;
        for (int i = lane; i < deg; i += 32)
            m = fmaxf(m, leaky02(g_es[g_csr[st + i] * 4 + h] + edv));
#pragma unroll
        for (int o = 16; o > 0; o >>= 1) m = fmaxf(m, __shfl_xor_sync(0xffffffffu, m, o));
        float z = (lane == 0) ? __expf(eself - m) : 0.f;
        for (int i = lane; i < deg; i += 32)
            z += __expf(leaky02(g_es[g_csr[st + i] * 4 + h] + edv) - m);
#pragma unroll
        for (int o = 16; o > 0; o >>= 1) z += __shfl_xor_sync(0xffffffffu, z, o);
        if (lane == 0) { s_m[h] = m; s_z[h] = z; }
    }
    __syncthreads();

    int h = tid >> 5, q = tid & 31;
    float4 acc = make_float4(0.f, 0.f, 0.f, 0.f);
    int tot = deg + 1;
    for (int base = 0; base < tot; base += 128) {
        int n = min(128, tot - base);
        if (tid < n) {
            int idx = base + tid;
            int s = (idx < deg) ? g_csr[st + idx] : d;
            s_src[tid] = s;
#pragma unroll
            for (int hh = 0; hh < 4; hh++) {
                float e = leaky02(g_es[s * 4 + hh] + s_ed[hh]);
                s_alpha[tid][hh] = __expf(e - s_m[hh]) / s_z[hh];
            }
        }
        __syncthreads();
        for (int i = 0; i < n; i++) {
            float4 v = ((const float4*)(D + (size_t)s_src[i] * 128))[q];
            float al = s_alpha[i][h];
            acc.x += v.x * al; acc.y += v.y * al; acc.z += v.z * al; acc.w += v.w * al;
        }
        __syncthreads();
    }
    ((float4*)agg)[(size_t)d * 128 + h * 32 + q] = acc;
}

// ---------------- pooling (fused BN4+ReLU) + FC -----------------------------
__global__ void k_gstart(const int* __restrict__ batch) {
    int g = threadIdx.x;
    if (g <= GG) {
        int lo = 0, hi = NN;
        while (lo < hi) {
            int mid = (lo + hi) >> 1;
            if (batch[mid] < g) lo = mid + 1;
            else hi = mid;
        }
        g_gstart[g] = lo;
    }
}

__global__ void k_pool_bn(const float* __restrict__ C4buf,
                          const float* __restrict__ gam, const float* __restrict__ bet)
{
    int g = blockIdx.x;
    int c4 = threadIdx.x;  // 128
    int st = g_gstart[g], en = g_gstart[g + 1];
    int cnt = en - st;
    float sc[4], sh[4];
    float inv_n = 1.0f / (float)NN;
#pragma unroll
    for (int j = 0; j < 4; j++) {
        int c = c4 * 4 + j;
        float mean = g_bnsum[1536 + c] * inv_n;
        float var = g_bnsq[1536 + c] * inv_n - mean * mean;
        float s = rsqrtf(var + BN_EPS) * gam[c];
        sc[j] = s;
        sh[j] = bet[c] - mean * s;
    }
    const float4* D4 = (const float4*)C4buf;
    float4 s = make_float4(0.f, 0.f, 0.f, 0.f);
    float4 m = make_float4(-3.4e38f, -3.4e38f, -3.4e38f, -3.4e38f);
    for (int i = st; i < en; i++) {
        float4 v = D4[(size_t)i * 128 + c4];
        v.x = fmaxf(fmaf(v.x, sc[0], sh[0]), 0.f);
        v.y = fmaxf(fmaf(v.y, sc[1], sh[1]), 0.f);
        v.z = fmaxf(fmaf(v.z, sc[2], sh[2]), 0.f);
        v.w = fmaxf(fmaf(v.w, sc[3], sh[3]), 0.f);
        s.x += v.x; s.y += v.y; s.z += v.z; s.w += v.w;
        m.x = fmaxf(m.x, v.x); m.y = fmaxf(m.y, v.y);
        m.z = fmaxf(m.z, v.z); m.w = fmaxf(m.w, v.w);
    }
    float inv = 1.f / (float)max(cnt, 1);
    float4* P4 = (float4*)g_pooled;
    P4[g * 256 + c4] = make_float4(s.x * inv, s.y * inv, s.z * inv, s.w * inv);
    if (cnt <= 0) m = make_float4(0.f, 0.f, 0.f, 0.f);
    P4[g * 256 + 128 + c4] = m;
}

__global__ __launch_bounds__(128) void k_fc(const float* __restrict__ W,
                                            const float* __restrict__ bias,
                                            float* __restrict__ out)
{
    __shared__ float sp[4][1024];
    int tid = threadIdx.x;
    int j = blockIdx.x * 128 + tid;
    int g0 = blockIdx.y * 4;
    for (int t = tid; t < 4 * 1024; t += 128)
        sp[t >> 10][t & 1023] = g_pooled[(g0 + (t >> 10)) * 1024 + (t & 1023)];
    __syncthreads();
    float acc[4] = {0.f, 0.f, 0.f, 0.f};
#pragma unroll 4
    for (int kk = 0; kk < 1024; kk++) {
        float wv = W[(size_t)kk * 1024 + j];
#pragma unroll
        for (int g = 0; g < 4; g++) acc[g] += sp[g][kk] * wv;
    }
    float bv = bias[j];
#pragma unroll
    for (int g = 0; g < 4; g++) out[(size_t)(g0 + g) * 1024 + j] = acc[g] + bv;
}

// ---------------- host orchestration ---------------------------------------
extern "C" void kernel_launch(void* const* d_in, const int* in_sizes, int n_in,
                              void* d_out, int out_size)
{
    const float* x        = (const float*)d_in[0];
    const int*   ei       = (const int*)  d_in[1];
    const int*   batch    = (const int*)  d_in[2];
    const float* gcn1_w   = (const float*)d_in[3];
    const float* sage_wl  = (const float*)d_in[5];
    const float* sage_wr  = (const float*)d_in[6];
    const float* gat_w    = (const float*)d_in[8];
    const float* gat_asrc = (const float*)d_in[9];
    const float* gat_adst = (const float*)d_in[10];
    const float* gcn4_w   = (const float*)d_in[12];
    const float* bn1_g = (const float*)d_in[14]; const float* bn1_b = (const float*)d_in[15];
    const float* bn2_g = (const float*)d_in[16]; const float* bn2_b = (const float*)d_in[17];
    const float* bn3_g = (const float*)d_in[18]; const float* bn3_b = (const float*)d_in[19];
    const float* bn4_g = (const float*)d_in[20]; const float* bn4_b = (const float*)d_in[21];
    const float* fc_w  = (const float*)d_in[22]; const float* fc_b  = (const float*)d_in[23];
    float* out = (float*)d_out;

    const int* src = ei;
    const int* dst = ei + EE;

    float *A, *B, *C, *D;
    cudaGetSymbolAddress((void**)&A, g_bufA);
    cudaGetSymbolAddress((void**)&B, g_bufB);
    cudaGetSymbolAddress((void**)&C, g_bufC);
    cudaGetSymbolAddress((void**)&D, g_bufD);

    // graph build (+ BN stat zeroing)
    k_zero_setup<<<NN / 256, 256>>>();
    k_deg<<<EE / 256, 256>>>(dst);
    k_scan<<<1, 512>>>();
    k_csr_fill<<<EE / 256, 256>>>(src, dst);

    // ---- layer 1: GCN(5->64): aggregate-first, then GEMM ----
    k_aggx5<<<NN * 32 / 256, 256>>>(x, B);
    k_gemm_small<<<dim3(1, NN / 128), 256>>>(B, gcn1_w, C, NN, 5, 64);
    k_bn_stats<<<64, 64>>>(C, 64, 0);
    k_bn_apply4<<<NN * 16 / 256, 256>>>(C, bn1_g, bn1_b, B, 16, 0, 32, 16);

    // ---- layer 2: SAGE(64->128), fused single GEMM ----
    k_sage_agg<<<NN / 8, 256>>>(B);
    k_gemm_tf32<<<dim3(1, NN / 128), 256>>>(B, sage_wl, sage_wr, 64, C, NN, 128, 128, 0);
    k_bn_stats<<<64, 128>>>(C, 128, 512);
    k_bn_apply4<<<NN * 32 / 256, 256>>>(C, bn2_g, bn2_b, D, 32, 512, 32, 0);

    // ---- layer 3: GAT(128->4x256, head-mean) via aggregate-then-transform ----
    k_wa<<<8, 128>>>(gat_w, gat_asrc, gat_adst);
    k_esed<<<NN / 8, 256>>>(D);
    k_gat_agg<<<NN, 128>>>(D, A);                           // A = agg [N,512]
    k_gemm_tf32<<<dim3(2, NN / 128), 256>>>(A, gat_w, nullptr, 0, C, NN, 512, 256, 1);
    k_bn_stats<<<64, 256>>>(C, 256, 1024);

    // ---- layer 4: GCN(256->512): BN3 fused into gather, then GEMM ----
    k_gcn_agg4_bn<<<NN, 64>>>(C, bn3_g, bn3_b, B);          // B = agg [N,256]
    k_gemm_tf32<<<dim3(4, NN / 128), 256>>>(B, gcn4_w, gcn4_w, 256, C, NN, 256, 512, 0);
    k_bn_stats<<<64, 512>>>(C, 512, 1536);

    // ---- pooling (BN4 fused) + FC ----
    k_gstart<<<1, 64>>>(batch);
    k_pool_bn<<<GG, 128>>>(C, bn4_g, bn4_b);
    k_fc<<<dim3(8, 8), 128>>>(fc_w, fc_b, out);
}

// round 7
// speedup vs baseline: 1.7416x; 1.0526x over previous
#include <cuda_runtime.h>
#include <mma.h>
#include <math.h>

using namespace nvcuda;

#define NN 16384
#define EE 131072
#define GG 32
#define BN_EPS 1e-5f

// ---------------- scratch (device globals: no allocation allowed) ----------
__device__ float g_bufA[NN * 512];    // GAT per-head agg [N,512] (32 MB)
__device__ float g_bufB[NN * 512];    // xa / packed sage / agg   (32 MB)
__device__ float g_bufC[NN * 512];    // pre-BN buffers           (32 MB)
__device__ float g_bufD[NN * 512];    // post-BN layer2 output    (32 MB)
__device__ float g_es[NN * 4];
__device__ float g_ed[NN * 4];
__device__ int   g_deg[NN];
__device__ int   g_rowptr[NN + 1];
__device__ int   g_cursor[NN];
__device__ int   g_csr[EE];
__device__ float g_dis[NN];
__device__ float g_bnsum[2048];       // layers at offsets 0,512,1024,1536
__device__ float g_bnsq[2048];
__device__ float g_wa[1024];          // [sel(2)][head(4)][k(128)]
__device__ float g_pooled[GG * 1024];
__device__ int   g_gstart[GG + 1];

// ---------------- graph building -------------------------------------------
__global__ void k_zero_setup() {
    int i = blockIdx.x * blockDim.x + threadIdx.x;
    if (i < NN) { g_deg[i] = 0; g_cursor[i] = 0; }
    if (i < 2048) { g_bnsum[i] = 0.f; g_bnsq[i] = 0.f; }
}

__global__ void k_deg(const int* __restrict__ dst) {
    int e = blockIdx.x * blockDim.x + threadIdx.x;
    if (e < EE) atomicAdd(&g_deg[dst[e]], 1);
}

__global__ void k_scan() {
    __shared__ int sh[512];
    int tid = threadIdx.x;
    int base = tid * 32;
    int s = 0;
    for (int i = 0; i < 32; i++) s += g_deg[base + i];
    sh[tid] = s;
    __syncthreads();
    for (int off = 1; off < 512; off <<= 1) {
        int v = (tid >= off) ? sh[tid - off] : 0;
        __syncthreads();
        sh[tid] += v;
        __syncthreads();
    }
    int run = sh[tid] - s;
    for (int i = 0; i < 32; i++) {
        int dg = g_deg[base + i];
        g_rowptr[base + i] = run;
        g_dis[base + i] = rsqrtf((float)dg + 1.0f);
        run += dg;
    }
    if (tid == 511) g_rowptr[NN] = sh[511];
}

__global__ void k_csr_fill(const int* __restrict__ src, const int* __restrict__ dst) {
    int e = blockIdx.x * blockDim.x + threadIdx.x;
    if (e < EE) {
        int d = dst[e];
        int pos = g_rowptr[d] + atomicAdd(&g_cursor[d], 1);
        g_csr[pos] = src[e];
    }
}

// ---------------- layer-1: aggregate raw x (5 channels), warp per node -----
__global__ void k_aggx5(const float* __restrict__ x, float* __restrict__ xa) {
    int gw = (blockIdx.x * blockDim.x + threadIdx.x) >> 5;
    int lane = threadIdx.x & 31;
    if (gw >= NN) return;
    int d = gw;
    int st = g_rowptr[d], deg = g_rowptr[d + 1] - st;
    float disd = g_dis[d];
    float a = 0.f;
    for (int i = 0; i < deg; i++) {
        int s = g_csr[st + i];
        float w = g_dis[s];
        if (lane < 5) a += x[s * 5 + lane] * w;
    }
    if (lane < 5) {
        a += x[d * 5 + lane] * disd;
        xa[d * 5 + lane] = a * disd;
    }
}

// ---------------- small generic GEMM (K=5 layer) ----------------------------
__global__ __launch_bounds__(256) void k_gemm_small(
    const float* __restrict__ A, const float* __restrict__ W,
    float* __restrict__ C, int M, int K, int Nn)
{
    __shared__ float As[8][128];
    __shared__ float Bs[8][128];
    int tid = threadIdx.x;
    int tx = tid & 15, ty = tid >> 4;
    int row0 = blockIdx.y * 128, col0 = blockIdx.x * 128;
    float accum[8][8];
#pragma unroll
    for (int i = 0; i < 8; i++)
#pragma unroll
        for (int j = 0; j < 8; j++) accum[i][j] = 0.f;

    int arow = tid >> 1, acol0 = (tid & 1) * 4;
    int brow = tid >> 5, bcol0 = (tid & 31) * 4;

    for (int k0 = 0; k0 < K; k0 += 8) {
#pragma unroll
        for (int i = 0; i < 4; i++) {
            int kk = k0 + acol0 + i;
            As[acol0 + i][arow] = (kk < K) ? A[(size_t)(row0 + arow) * K + kk] : 0.f;
        }
#pragma unroll
        for (int i = 0; i < 4; i++) {
            int col = col0 + bcol0 + i;
            int kk = k0 + brow;
            Bs[brow][bcol0 + i] = (kk < K && col < Nn) ? W[(size_t)kk * Nn + col] : 0.f;
        }
        __syncthreads();
#pragma unroll
        for (int kk = 0; kk < 8; kk++) {
            float ra[8], rb[8];
#pragma unroll
            for (int i = 0; i < 8; i++) ra[i] = As[kk][ty * 8 + i];
#pragma unroll
            for (int j = 0; j < 8; j++) rb[j] = Bs[kk][tx * 8 + j];
#pragma unroll
            for (int i = 0; i < 8; i++)
#pragma unroll
                for (int j = 0; j < 8; j++) accum[i][j] += ra[i] * rb[j];
        }
        __syncthreads();
    }
#pragma unroll
    for (int i = 0; i < 8; i++) {
        int r = row0 + ty * 8 + i;
#pragma unroll
        for (int j = 0; j < 8; j++) {
            int cc = col0 + tx * 8 + j;
            if (cc < Nn) C[(size_t)r * Nn + cc] = accum[i][j];
        }
    }
}

// ---------------- TF32 tensor-core GEMM ------------------------------------
// tf32-truncation happens at smem store; fragments load pre-truncated bits.
__device__ __forceinline__ float4 to_tf32_4(float4 v) {
    v.x = wmma::__float_to_tf32(v.x);
    v.y = wmma::__float_to_tf32(v.y);
    v.z = wmma::__float_to_tf32(v.z);
    v.w = wmma::__float_to_tf32(v.w);
    return v;
}

__global__ __launch_bounds__(256, 2) void k_gemm_tf32(
    const float* __restrict__ A,
    const float* __restrict__ W1, const float* __restrict__ W2, int ksplit,
    float* __restrict__ C, int M, int K, int Nn, int gatmode)
{
    __shared__ float As[128][20];
    __shared__ float Bs[16][132];

    int tid = threadIdx.x;
    int warp = tid >> 5;
    int wm = warp >> 2;
    int wn = warp & 3;
    int row0 = blockIdx.y * 128, col0 = blockIdx.x * 128;

    int a_r[2], a_c[2];
#pragma unroll
    for (int i = 0; i < 2; i++) {
        int s = tid * 2 + i;
        a_r[i] = s >> 2;
        a_c[i] = (s & 3) * 4;
    }
    int b_r[2], b_c[2];
#pragma unroll
    for (int i = 0; i < 2; i++) {
        int s = tid + 256 * i;
        b_r[i] = s >> 5;
        b_c[i] = (s & 31) * 4;
    }

    const float* Abase = A + (size_t)row0 * K;

    float4 cA[2], cB[2];
#pragma unroll
    for (int i = 0; i < 2; i++) {
        cA[i] = *(const float4*)(Abase + (size_t)a_r[i] * K + a_c[i]);
        int k = b_r[i];
        const float* wp;
        if (gatmode) wp = W1 + (size_t)(k & 127) * 1024 + (k >> 7) * 256;
        else wp = (k < ksplit) ? (W1 + (size_t)k * Nn)
                               : (W2 + (size_t)(k - ksplit) * Nn);
        cB[i] = *(const float4*)(wp + col0 + b_c[i]);
    }

    wmma::fragment<wmma::accumulator, 16, 16, 8, float> acc[4][2];
#pragma unroll
    for (int i = 0; i < 4; i++)
#pragma unroll
        for (int j = 0; j < 2; j++) wmma::fill_fragment(acc[i][j], 0.f);

    for (int k0 = 0; k0 < K; k0 += 16) {
#pragma unroll
        for (int i = 0; i < 2; i++) {
            *(float4*)&As[a_r[i]][a_c[i]] = to_tf32_4(cA[i]);
            *(float4*)&Bs[b_r[i]][b_c[i]] = to_tf32_4(cB[i]);
        }
        __syncthreads();
        if (k0 + 16 < K) {
#pragma unroll
            for (int i = 0; i < 2; i++) {
                cA[i] = *(const float4*)(Abase + (size_t)a_r[i] * K + (k0 + 16) + a_c[i]);
                int k = k0 + 16 + b_r[i];
                const float* wp;
                if (gatmode) wp = W1 + (size_t)(k & 127) * 1024 + (k >> 7) * 256;
                else wp = (k < ksplit) ? (W1 + (size_t)k * Nn)
                                       : (W2 + (size_t)(k - ksplit) * Nn);
                cB[i] = *(const float4*)(wp + col0 + b_c[i]);
            }
        }
#pragma unroll
        for (int kk = 0; kk < 16; kk += 8) {
            wmma::fragment<wmma::matrix_a, 16, 16, 8, wmma::precision::tf32, wmma::row_major> af[4];
            wmma::fragment<wmma::matrix_b, 16, 16, 8, wmma::precision::tf32, wmma::row_major> bf[2];
#pragma unroll
            for (int i = 0; i < 4; i++)
                wmma::load_matrix_sync(af[i], &As[wm * 64 + i * 16][kk], 20);
#pragma unroll
            for (int j = 0; j < 2; j++)
                wmma::load_matrix_sync(bf[j], &Bs[kk][wn * 32 + j * 16], 132);
#pragma unroll
            for (int i = 0; i < 4; i++)
#pragma unroll
                for (int j = 0; j < 2; j++)
                    wmma::mma_sync(acc[i][j], af[i], bf[j], acc[i][j]);
        }
        __syncthreads();
    }

#pragma unroll
    for (int i = 0; i < 4; i++)
#pragma unroll
        for (int j = 0; j < 2; j++) {
            int gr = row0 + wm * 64 + i * 16;
            int gc = col0 + wn * 32 + j * 16;
            wmma::store_matrix_sync(C + (size_t)gr * Nn + gc, acc[i][j], Nn,
                                    wmma::mem_row_major);
        }
}

// ---------------- layer-4 GCN gather with fused BN3+ReLU -------------------
// warp-autonomous: 4 nodes per 256-thread block, 64 threads (2 warps) / node,
// no shared staging, no __syncthreads.
__global__ __launch_bounds__(256) void k_gcn_agg4_bn(
    const float* __restrict__ C3,
    const float* __restrict__ gam, const float* __restrict__ bet,
    float* __restrict__ out)
{
    int tid = threadIdx.x;
    int d = blockIdx.x * 4 + (tid >> 6);
    int t = tid & 63;                     // float4 channel index (256 ch)
    int st = g_rowptr[d], deg = g_rowptr[d + 1] - st;
    float disd = g_dis[d];
    float sc[4], sh[4];
    float inv_n = 1.0f / (float)NN;
#pragma unroll
    for (int j = 0; j < 4; j++) {
        int c = t * 4 + j;
        float mean = g_bnsum[1024 + c] * inv_n;
        float var = g_bnsq[1024 + c] * inv_n - mean * mean;
        float s = rsqrtf(var + BN_EPS) * gam[c];
        sc[j] = s;
        sh[j] = bet[c] - mean * s;
    }
    const float4* in4 = (const float4*)C3;
    float4 a = make_float4(0.f, 0.f, 0.f, 0.f);
    int i = 0;
    for (; i + 2 <= deg; i += 2) {
        int s0 = g_csr[st + i], s1 = g_csr[st + i + 1];
        float w0 = g_dis[s0], w1 = g_dis[s1];
        float4 v0 = in4[(size_t)s0 * 64 + t];
        float4 v1 = in4[(size_t)s1 * 64 + t];
        a.x += fmaxf(fmaf(v0.x, sc[0], sh[0]), 0.f) * w0 + fmaxf(fmaf(v1.x, sc[0], sh[0]), 0.f) * w1;
        a.y += fmaxf(fmaf(v0.y, sc[1], sh[1]), 0.f) * w0 + fmaxf(fmaf(v1.y, sc[1], sh[1]), 0.f) * w1;
        a.z += fmaxf(fmaf(v0.z, sc[2], sh[2]), 0.f) * w0 + fmaxf(fmaf(v1.z, sc[2], sh[2]), 0.f) * w1;
        a.w += fmaxf(fmaf(v0.w, sc[3], sh[3]), 0.f) * w0 + fmaxf(fmaf(v1.w, sc[3], sh[3]), 0.f) * w1;
    }
    if (i < deg) {
        int s0 = g_csr[st + i];
        float w0 = g_dis[s0];
        float4 v0 = in4[(size_t)s0 * 64 + t];
        a.x += fmaxf(fmaf(v0.x, sc[0], sh[0]), 0.f) * w0;
        a.y += fmaxf(fmaf(v0.y, sc[1], sh[1]), 0.f) * w0;
        a.z += fmaxf(fmaf(v0.z, sc[2], sh[2]), 0.f) * w0;
        a.w += fmaxf(fmaf(v0.w, sc[3], sh[3]), 0.f) * w0;
    }
    float4 v = in4[(size_t)d * 64 + t];
    a.x += fmaxf(fmaf(v.x, sc[0], sh[0]), 0.f) * disd;
    a.y += fmaxf(fmaf(v.y, sc[1], sh[1]), 0.f) * disd;
    a.z += fmaxf(fmaf(v.z, sc[2], sh[2]), 0.f) * disd;
    a.w += fmaxf(fmaf(v.w, sc[3], sh[3]), 0.f) * disd;
    a.x *= disd; a.y *= disd; a.z *= disd; a.w *= disd;
    ((float4*)out)[(size_t)d * 64 + t] = a;
}

// ---------------- SAGE mean aggregation, warp/node --------------------------
__global__ void k_sage_agg(float* __restrict__ P) {
    int w = threadIdx.x >> 5;
    int d = blockIdx.x * 8 + w;
    int lane = threadIdx.x & 31;
    int st = g_rowptr[d], deg = g_rowptr[d + 1] - st;
    int half = lane >> 4;
    int c4 = (lane & 15) + 16;
    const float4* P4 = (const float4*)P;
    float4 a = make_float4(0.f, 0.f, 0.f, 0.f);
    for (int i = 0; i < deg; i += 2) {
        int idx = i + half;
        if (idx < deg) {
            int s = g_csr[st + idx];
            float4 v = P4[(size_t)s * 32 + c4];
            a.x += v.x; a.y += v.y; a.z += v.z; a.w += v.w;
        }
    }
    a.x += __shfl_xor_sync(0xffffffffu, a.x, 16);
    a.y += __shfl_xor_sync(0xffffffffu, a.y, 16);
    a.z += __shfl_xor_sync(0xffffffffu, a.z, 16);
    a.w += __shfl_xor_sync(0xffffffffu, a.w, 16);
    if (lane < 16) {
        float inv = 1.f / (float)max(deg, 1);
        ((float4*)P)[(size_t)d * 32 + lane] =
            make_float4(a.x * inv, a.y * inv, a.z * inv, a.w * inv);
    }
}

// ---------------- BatchNorm stats ------------------------------------------
__global__ void k_bn_stats(const float* __restrict__ X, int C, int statoff) {
    int c = threadIdx.x;
    int r0 = blockIdx.x * 256;
    float s = 0.f, q = 0.f;
    for (int r = 0; r < 256; r++) {
        float v = X[(size_t)(r0 + r) * C + c];
        s += v;
        q += v * v;
    }
    atomicAdd(&g_bnsum[statoff + c], s);
    atomicAdd(&g_bnsq[statoff + c], q);
}

__global__ void k_bn_apply4(const float* __restrict__ in, const float* __restrict__ gam,
                            const float* __restrict__ bet, float* __restrict__ out,
                            int C4, int statoff, int ostride4, int ooff4)
{
    int idx = blockIdx.x * blockDim.x + threadIdx.x;
    int c4 = idx % C4;
    int row = idx / C4;
    float4 v = ((const float4*)in)[idx];
    float inv_n = 1.0f / (float)NN;
    float r[4] = {v.x, v.y, v.z, v.w};
#pragma unroll
    for (int j = 0; j < 4; j++) {
        int c = c4 * 4 + j;
        float mean = g_bnsum[statoff + c] * inv_n;
        float var = g_bnsq[statoff + c] * inv_n - mean * mean;
        float y = (r[j] - mean) * rsqrtf(var + BN_EPS) * gam[c] + bet[c];
        r[j] = fmaxf(y, 0.f);
    }
    ((float4*)out)[(size_t)row * ostride4 + ooff4 + c4] =
        make_float4(r[0], r[1], r[2], r[3]);
}

// ---------------- GAT: projected attention vectors --------------------------
__global__ void k_wa(const float* __restrict__ gat_w,
                     const float* __restrict__ asrc, const float* __restrict__ adst)
{
    int b = blockIdx.x;       // 0..7 : sel = b>>2, h = b&3
    int k = threadIdx.x;      // 0..127
    int sel = b >> 2, h = b & 3;
    const float* a = (sel == 0) ? asrc : adst;
    float s = 0.f;
    for (int c = 0; c < 256; c++)
        s += gat_w[(size_t)k * 1024 + h * 256 + c] * a[h * 256 + c];
    g_wa[sel * 512 + h * 128 + k] = s;
}

// es/ed[n,h] = sum_k D[n,k] * wa[sel][h][k] ; warp per node
__global__ void k_esed(const float* __restrict__ D) {
    __shared__ float swa[1024];
    int tid = threadIdx.x;  // 256
    for (int t = tid; t < 1024; t += 256) swa[t] = g_wa[t];
    __syncthreads();
    int w = tid >> 5, lane = tid & 31;
    int n = blockIdx.x * 8 + w;
    float4 v = ((const float4*)D)[(size_t)n * 32 + lane];
    float p[8];
#pragma unroll
    for (int s = 0; s < 2; s++)
#pragma unroll
        for (int h = 0; h < 4; h++) {
            float4 wv = ((const float4*)swa)[(s * 512 + h * 128) / 4 + lane];
            p[s * 4 + h] = v.x * wv.x + v.y * wv.y + v.z * wv.z + v.w * wv.w;
        }
#pragma unroll
    for (int o = 16; o > 0; o >>= 1)
#pragma unroll
        for (int j = 0; j < 8; j++)
            p[j] += __shfl_xor_sync(0xffffffffu, p[j], o);
    if (lane < 4) g_es[n * 4 + lane] = p[lane];
    else if (lane < 8) g_ed[n * 4 + (lane - 4)] = p[lane];
}

__device__ __forceinline__ float leaky02(float x) { return x > 0.f ? x : 0.2f * x; }

// warp-autonomous GAT aggregation: warp = (node, head), no block syncs.
// 256 threads = 8 warps = 2 nodes/block.
// agg[d, h*128 + k] = sum_s alpha_{s,h} * D[s,k]  (incl. self loop)
__global__ __launch_bounds__(256) void k_gat_agg(const float* __restrict__ D,
                                                 float* __restrict__ agg)
{
    int warp = threadIdx.x >> 5;
    int lane = threadIdx.x & 31;
    int d = blockIdx.x * 2 + (warp >> 2);
    int h = warp & 3;
    int st = g_rowptr[d], deg = g_rowptr[d + 1] - st;
    float edv = g_ed[d * 4 + h];
    float eself = leaky02(g_es[d * 4 + h] + edv);

    // max
    float m = eself;
    for (int i = lane; i < deg; i += 32)
        m = fmaxf(m, leaky02(g_es[g_csr[st + i] * 4 + h] + edv));
#pragma unroll
    for (int o = 16; o > 0; o >>= 1) m = fmaxf(m, __shfl_xor_sync(0xffffffffu, m, o));
    // sum
    float z = (lane == 0) ? __expf(eself - m) : 0.f;
    for (int i = lane; i < deg; i += 32)
        z += __expf(leaky02(g_es[g_csr[st + i] * 4 + h] + edv) - m);
#pragma unroll
    for (int o = 16; o > 0; o >>= 1) z += __shfl_xor_sync(0xffffffffu, z, o);
    float invz = 1.f / z;

    // aggregation: lane owns float4 chunk `lane` of 128 channels
    const float4* D4 = (const float4*)D;
    float4 acc = make_float4(0.f, 0.f, 0.f, 0.f);
    int i = 0;
    for (; i + 2 <= deg; i += 2) {
        int s0 = g_csr[st + i], s1 = g_csr[st + i + 1];
        float a0 = __expf(leaky02(g_es[s0 * 4 + h] + edv) - m) * invz;
        float a1 = __expf(leaky02(g_es[s1 * 4 + h] + edv) - m) * invz;
        float4 v0 = D4[(size_t)s0 * 32 + lane];
        float4 v1 = D4[(size_t)s1 * 32 + lane];
        acc.x += v0.x * a0 + v1.x * a1;
        acc.y += v0.y * a0 + v1.y * a1;
        acc.z += v0.z * a0 + v1.z * a1;
        acc.w += v0.w * a0 + v1.w * a1;
    }
    if (i < deg) {
        int s0 = g_csr[st + i];
        float a0 = __expf(leaky02(g_es[s0 * 4 + h] + edv) - m) * invz;
        float4 v0 = D4[(size_t)s0 * 32 + lane];
        acc.x += v0.x * a0; acc.y += v0.y * a0; acc.z += v0.z * a0; acc.w += v0.w * a0;
    }
    {   // self loop
        float a0 = __expf(eself - m) * invz;
        float4 v0 = D4[(size_t)d * 32 + lane];
        acc.x += v0.x * a0; acc.y += v0.y * a0; acc.z += v0.z * a0; acc.w += v0.w * a0;
    }
    ((float4*)agg)[(size_t)d * 128 + h * 32 + lane] = acc;
}

// ---------------- pooling (fused BN4+ReLU) + FC -----------------------------
__global__ void k_gstart(const int* __restrict__ batch) {
    int g = threadIdx.x;
    if (g <= GG) {
        int lo = 0, hi = NN;
        while (lo < hi) {
            int mid = (lo + hi) >> 1;
            if (batch[mid] < g) lo = mid + 1;
            else hi = mid;
        }
        g_gstart[g] = lo;
    }
}

__global__ void k_pool_bn(const float* __restrict__ C4buf,
                          const float* __restrict__ gam, const float* __restrict__ bet)
{
    int g = blockIdx.x;
    int c4 = threadIdx.x;  // 128
    int st = g_gstart[g], en = g_gstart[g + 1];
    int cnt = en - st;
    float sc[4], sh[4];
    float inv_n = 1.0f / (float)NN;
#pragma unroll
    for (int j = 0; j < 4; j++) {
        int c = c4 * 4 + j;
        float mean = g_bnsum[1536 + c] * inv_n;
        float var = g_bnsq[1536 + c] * inv_n - mean * mean;
        float s = rsqrtf(var + BN_EPS) * gam[c];
        sc[j] = s;
        sh[j] = bet[c] - mean * s;
    }
    const float4* D4 = (const float4*)C4buf;
    float4 s = make_float4(0.f, 0.f, 0.f, 0.f);
    float4 m = make_float4(-3.4e38f, -3.4e38f, -3.4e38f, -3.4e38f);
    for (int i = st; i < en; i++) {
        float4 v = D4[(size_t)i * 128 + c4];
        v.x = fmaxf(fmaf(v.x, sc[0], sh[0]), 0.f);
        v.y = fmaxf(fmaf(v.y, sc[1], sh[1]), 0.f);
        v.z = fmaxf(fmaf(v.z, sc[2], sh[2]), 0.f);
        v.w = fmaxf(fmaf(v.w, sc[3], sh[3]), 0.f);
        s.x += v.x; s.y += v.y; s.z += v.z; s.w += v.w;
        m.x = fmaxf(m.x, v.x); m.y = fmaxf(m.y, v.y);
        m.z = fmaxf(m.z, v.z); m.w = fmaxf(m.w, v.w);
    }
    float inv = 1.f / (float)max(cnt, 1);
    float4* P4 = (float4*)g_pooled;
    P4[g * 256 + c4] = make_float4(s.x * inv, s.y * inv, s.z * inv, s.w * inv);
    if (cnt <= 0) m = make_float4(0.f, 0.f, 0.f, 0.f);
    P4[g * 256 + 128 + c4] = m;
}

__global__ __launch_bounds__(128) void k_fc(const float* __restrict__ W,
                                            const float* __restrict__ bias,
                                            float* __restrict__ out)
{
    __shared__ float sp[4][1024];
    int tid = threadIdx.x;
    int j = blockIdx.x * 128 + tid;
    int g0 = blockIdx.y * 4;
    for (int t = tid; t < 4 * 1024; t += 128)
        sp[t >> 10][t & 1023] = g_pooled[(g0 + (t >> 10)) * 1024 + (t & 1023)];
    __syncthreads();
    float acc[4] = {0.f, 0.f, 0.f, 0.f};
#pragma unroll 4
    for (int kk = 0; kk < 1024; kk++) {
        float wv = W[(size_t)kk * 1024 + j];
#pragma unroll
        for (int g = 0; g < 4; g++) acc[g] += sp[g][kk] * wv;
    }
    float bv = bias[j];
#pragma unroll
    for (int g = 0; g < 4; g++) out[(size_t)(g0 + g) * 1024 + j] = acc[g] + bv;
}

// ---------------- host orchestration ---------------------------------------
extern "C" void kernel_launch(void* const* d_in, const int* in_sizes, int n_in,
                              void* d_out, int out_size)
{
    const float* x        = (const float*)d_in[0];
    const int*   ei       = (const int*)  d_in[1];
    const int*   batch    = (const int*)  d_in[2];
    const float* gcn1_w   = (const float*)d_in[3];
    const float* sage_wl  = (const float*)d_in[5];
    const float* sage_wr  = (const float*)d_in[6];
    const float* gat_w    = (const float*)d_in[8];
    const float* gat_asrc = (const float*)d_in[9];
    const float* gat_adst = (const float*)d_in[10];
    const float* gcn4_w   = (const float*)d_in[12];
    const float* bn1_g = (const float*)d_in[14]; const float* bn1_b = (const float*)d_in[15];
    const float* bn2_g = (const float*)d_in[16]; const float* bn2_b = (const float*)d_in[17];
    const float* bn3_g = (const float*)d_in[18]; const float* bn3_b = (const float*)d_in[19];
    const float* bn4_g = (const float*)d_in[20]; const float* bn4_b = (const float*)d_in[21];
    const float* fc_w  = (const float*)d_in[22]; const float* fc_b  = (const float*)d_in[23];
    float* out = (float*)d_out;

    const int* src = ei;
    const int* dst = ei + EE;

    float *A, *B, *C, *D;
    cudaGetSymbolAddress((void**)&A, g_bufA);
    cudaGetSymbolAddress((void**)&B, g_bufB);
    cudaGetSymbolAddress((void**)&C, g_bufC);
    cudaGetSymbolAddress((void**)&D, g_bufD);

    // graph build (+ BN stat zeroing)
    k_zero_setup<<<NN / 256, 256>>>();
    k_deg<<<EE / 256, 256>>>(dst);
    k_scan<<<1, 512>>>();
    k_csr_fill<<<EE / 256, 256>>>(src, dst);

    // ---- layer 1: GCN(5->64): aggregate-first, then GEMM ----
    k_aggx5<<<NN * 32 / 256, 256>>>(x, B);
    k_gemm_small<<<dim3(1, NN / 128), 256>>>(B, gcn1_w, C, NN, 5, 64);
    k_bn_stats<<<64, 64>>>(C, 64, 0);
    k_bn_apply4<<<NN * 16 / 256, 256>>>(C, bn1_g, bn1_b, B, 16, 0, 32, 16);

    // ---- layer 2: SAGE(64->128), fused single GEMM ----
    k_sage_agg<<<NN / 8, 256>>>(B);
    k_gemm_tf32<<<dim3(1, NN / 128), 256>>>(B, sage_wl, sage_wr, 64, C, NN, 128, 128, 0);
    k_bn_stats<<<64, 128>>>(C, 128, 512);
    k_bn_apply4<<<NN * 32 / 256, 256>>>(C, bn2_g, bn2_b, D, 32, 512, 32, 0);

    // ---- layer 3: GAT(128->4x256, head-mean) via aggregate-then-transform ----
    k_wa<<<8, 128>>>(gat_w, gat_asrc, gat_adst);
    k_esed<<<NN / 8, 256>>>(D);
    k_gat_agg<<<NN / 2, 256>>>(D, A);                       // A = agg [N,512]
    k_gemm_tf32<<<dim3(2, NN / 128), 256>>>(A, gat_w, nullptr, 0, C, NN, 512, 256, 1);
    k_bn_stats<<<64, 256>>>(C, 256, 1024);

    // ---- layer 4: GCN(256->512): BN3 fused into gather, then GEMM ----
    k_gcn_agg4_bn<<<NN / 4, 256>>>(C, bn3_g, bn3_b, B);     // B = agg [N,256]
    k_gemm_tf32<<<dim3(4, NN / 128), 256>>>(B, gcn4_w, gcn4_w, 256, C, NN, 256, 512, 0);
    k_bn_stats<<<64, 512>>>(C, 512, 1536);

    // ---- pooling (BN4 fused) + FC ----
    k_gstart<<<1, 64>>>(batch);
    k_pool_bn<<<GG, 128>>>(C, bn4_g, bn4_b);
    k_fc<<<dim3(8, 8), 128>>>(fc_w, fc_b, out);
}

// round 9
// speedup vs baseline: 1.8017x; 1.0346x over previous
#include <cuda_runtime.h>
#include <mma.h>
#include <math.h>

using namespace nvcuda;

#define NN 16384
#define EE 131072
#define GG 32
#define BN_EPS 1e-5f

// ---------------- scratch (device globals: no allocation allowed) ----------
__device__ float g_bufA[NN * 512];    // GAT per-head agg [N,512] (32 MB)
__device__ float g_bufB[NN * 512];    // xa / packed sage / agg   (32 MB)
__device__ float g_bufC[NN * 512];    // pre-BN buffers           (32 MB)
__device__ float g_bufD[NN * 512];    // post-BN layer2 output    (32 MB)
__device__ float g_es[NN * 4];
__device__ float g_ed[NN * 4];
__device__ int   g_deg[NN];
__device__ int   g_rowptr[NN + 1];
__device__ int   g_cursor[NN];
__device__ int   g_csr[EE];
__device__ float g_dis[NN];
__device__ float g_bnsum[2048];       // layers at offsets 0,512,1024,1536
__device__ float g_bnsq[2048];
__device__ float g_wa[1024];          // [sel(2)][head(4)][k(128)]
__device__ float g_pooled[GG * 1024];
__device__ int   g_gstart[GG + 1];

// ---------------- fused setup: zero + wa projection + gstart ----------------
// grid 69: blocks 0..63 zero, 64..67 wa (2 sub-blocks of 128 thr), 68 gstart
__global__ void k_setup(const float* __restrict__ gat_w,
                        const float* __restrict__ asrc, const float* __restrict__ adst,
                        const int* __restrict__ batch)
{
    int b = blockIdx.x;
    int tid = threadIdx.x;
    if (b < 64) {
        int i = b * 256 + tid;
        g_deg[i] = 0;
        g_cursor[i] = 0;
        if (i < 2048) { g_bnsum[i] = 0.f; g_bnsq[i] = 0.f; }
    } else if (b < 68) {
        int sub = (b - 64) * 2 + (tid >> 7);   // 0..7
        int k = tid & 127;
        int sel = sub >> 2, h = sub & 3;
        const float* a = (sel == 0) ? asrc : adst;
        float s = 0.f;
        for (int c = 0; c < 256; c++)
            s += gat_w[(size_t)k * 1024 + h * 256 + c] * a[h * 256 + c];
        g_wa[sel * 512 + h * 128 + k] = s;
    } else {
        int g = tid;
        if (g <= GG) {
            int lo = 0, hi = NN;
            while (lo < hi) {
                int mid = (lo + hi) >> 1;
                if (batch[mid] < g) lo = mid + 1;
                else hi = mid;
            }
            g_gstart[g] = lo;
        }
    }
}

__global__ void k_deg(const int* __restrict__ dst) {
    int e = blockIdx.x * blockDim.x + threadIdx.x;
    if (e < EE) atomicAdd(&g_deg[dst[e]], 1);
}

__global__ void k_scan() {
    __shared__ int sh[512];
    int tid = threadIdx.x;
    int base = tid * 32;
    int s = 0;
    for (int i = 0; i < 32; i++) s += g_deg[base + i];
    sh[tid] = s;
    __syncthreads();
    for (int off = 1; off < 512; off <<= 1) {
        int v = (tid >= off) ? sh[tid - off] : 0;
        __syncthreads();
        sh[tid] += v;
        __syncthreads();
    }
    int run = sh[tid] - s;
    for (int i = 0; i < 32; i++) {
        int dg = g_deg[base + i];
        g_rowptr[base + i] = run;
        g_dis[base + i] = rsqrtf((float)dg + 1.0f);
        run += dg;
    }
    if (tid == 511) g_rowptr[NN] = sh[511];
}

__global__ void k_csr_fill(const int* __restrict__ src, const int* __restrict__ dst) {
    int e = blockIdx.x * blockDim.x + threadIdx.x;
    if (e < EE) {
        int d = dst[e];
        int pos = g_rowptr[d] + atomicAdd(&g_cursor[d], 1);
        g_csr[pos] = src[e];
    }
}

// ---------------- layer 1 fully fused: gather(5ch) + 5x64 GEMV + BN stats ---
// warp per node, 8 nodes/block.
__global__ __launch_bounds__(256) void k_l1(const float* __restrict__ x,
                                            const float* __restrict__ W,
                                            float* __restrict__ C)
{
    __shared__ float sW[320];
    __shared__ float ssum[64], ssq[64];
    int tid = threadIdx.x;
    for (int t = tid; t < 320; t += 256) sW[t] = W[t];   // FIX: strided load
    if (tid < 64) { ssum[tid] = 0.f; ssq[tid] = 0.f; }
    __syncthreads();

    int w = tid >> 5, lane = tid & 31;
    int d = blockIdx.x * 8 + w;
    int st = g_rowptr[d], deg = g_rowptr[d + 1] - st;
    float disd = g_dis[d];
    float a = 0.f;
    for (int i = 0; i < deg; i++) {
        int s = g_csr[st + i];
        float wt = g_dis[s];
        if (lane < 5) a += x[s * 5 + lane] * wt;
    }
    if (lane < 5) a = (a + x[d * 5 + lane] * disd) * disd;
    float xa0 = __shfl_sync(0xffffffffu, a, 0);
    float xa1 = __shfl_sync(0xffffffffu, a, 1);
    float xa2 = __shfl_sync(0xffffffffu, a, 2);
    float xa3 = __shfl_sync(0xffffffffu, a, 3);
    float xa4 = __shfl_sync(0xffffffffu, a, 4);

    int c0 = lane, c1 = lane + 32;
    float h0 = xa0 * sW[c0] + xa1 * sW[64 + c0] + xa2 * sW[128 + c0]
             + xa3 * sW[192 + c0] + xa4 * sW[256 + c0];
    float h1 = xa0 * sW[c1] + xa1 * sW[64 + c1] + xa2 * sW[128 + c1]
             + xa3 * sW[192 + c1] + xa4 * sW[256 + c1];
    C[(size_t)d * 64 + c0] = h0;
    C[(size_t)d * 64 + c1] = h1;
    atomicAdd(&ssum[c0], h0); atomicAdd(&ssq[c0], h0 * h0);
    atomicAdd(&ssum[c1], h1); atomicAdd(&ssq[c1], h1 * h1);
    __syncthreads();
    if (tid < 64) {
        atomicAdd(&g_bnsum[tid], ssum[tid]);
        atomicAdd(&g_bnsq[tid], ssq[tid]);
    }
}

// ---------------- TF32 tensor-core GEMM + fused BN-stat epilogue -----------
__device__ __forceinline__ float4 to_tf32_4(float4 v) {
    v.x = wmma::__float_to_tf32(v.x);
    v.y = wmma::__float_to_tf32(v.y);
    v.z = wmma::__float_to_tf32(v.z);
    v.w = wmma::__float_to_tf32(v.w);
    return v;
}

__global__ __launch_bounds__(256, 2) void k_gemm_tf32(
    const float* __restrict__ A,
    const float* __restrict__ W1, const float* __restrict__ W2, int ksplit,
    float* __restrict__ C, int M, int K, int Nn, int gatmode, int statoff)
{
    __shared__ float As[128][20];
    __shared__ float Bs[16][132];
    __shared__ float red[2][128][2];

    int tid = threadIdx.x;
    int warp = tid >> 5;
    int wm = warp >> 2;
    int wn = warp & 3;
    int row0 = blockIdx.y * 128, col0 = blockIdx.x * 128;

    int a_r[2], a_c[2];
#pragma unroll
    for (int i = 0; i < 2; i++) {
        int s = tid * 2 + i;
        a_r[i] = s >> 2;
        a_c[i] = (s & 3) * 4;
    }
    int b_r[2], b_c[2];
#pragma unroll
    for (int i = 0; i < 2; i++) {
        int s = tid + 256 * i;
        b_r[i] = s >> 5;
        b_c[i] = (s & 31) * 4;
    }

    const float* Abase = A + (size_t)row0 * K;

    float4 cA[2], cB[2];
#pragma unroll
    for (int i = 0; i < 2; i++) {
        cA[i] = *(const float4*)(Abase + (size_t)a_r[i] * K + a_c[i]);
        int k = b_r[i];
        const float* wp;
        if (gatmode) wp = W1 + (size_t)(k & 127) * 1024 + (k >> 7) * 256;
        else wp = (k < ksplit) ? (W1 + (size_t)k * Nn)
                               : (W2 + (size_t)(k - ksplit) * Nn);
        cB[i] = *(const float4*)(wp + col0 + b_c[i]);
    }

    wmma::fragment<wmma::accumulator, 16, 16, 8, float> acc[4][2];
#pragma unroll
    for (int i = 0; i < 4; i++)
#pragma unroll
        for (int j = 0; j < 2; j++) wmma::fill_fragment(acc[i][j], 0.f);

    for (int k0 = 0; k0 < K; k0 += 16) {
#pragma unroll
        for (int i = 0; i < 2; i++) {
            *(float4*)&As[a_r[i]][a_c[i]] = to_tf32_4(cA[i]);
            *(float4*)&Bs[b_r[i]][b_c[i]] = to_tf32_4(cB[i]);
        }
        __syncthreads();
        if (k0 + 16 < K) {
#pragma unroll
            for (int i = 0; i < 2; i++) {
                cA[i] = *(const float4*)(Abase + (size_t)a_r[i] * K + (k0 + 16) + a_c[i]);
                int k = k0 + 16 + b_r[i];
                const float* wp;
                if (gatmode) wp = W1 + (size_t)(k & 127) * 1024 + (k >> 7) * 256;
                else wp = (k < ksplit) ? (W1 + (size_t)k * Nn)
                                       : (W2 + (size_t)(k - ksplit) * Nn);
                cB[i] = *(const float4*)(wp + col0 + b_c[i]);
            }
        }
#pragma unroll
        for (int kk = 0; kk < 16; kk += 8) {
            wmma::fragment<wmma::matrix_a, 16, 16, 8, wmma::precision::tf32, wmma::row_major> af[4];
            wmma::fragment<wmma::matrix_b, 16, 16, 8, wmma::precision::tf32, wmma::row_major> bf[2];
#pragma unroll
            for (int i = 0; i < 4; i++)
                wmma::load_matrix_sync(af[i], &As[wm * 64 + i * 16][kk], 20);
#pragma unroll
            for (int j = 0; j < 2; j++)
                wmma::load_matrix_sync(bf[j], &Bs[kk][wn * 32 + j * 16], 132);
#pragma unroll
            for (int i = 0; i < 4; i++)
#pragma unroll
                for (int j = 0; j < 2; j++)
                    wmma::mma_sync(acc[i][j], af[i], bf[j], acc[i][j]);
        }
        __syncthreads();
    }

#pragma unroll
    for (int i = 0; i < 4; i++)
#pragma unroll
        for (int j = 0; j < 2; j++) {
            int gr = row0 + wm * 64 + i * 16;
            int gc = col0 + wn * 32 + j * 16;
            wmma::store_matrix_sync(C + (size_t)gr * Nn + gc, acc[i][j], Nn,
                                    wmma::mem_row_major);
        }

    // fused BN-stat epilogue: reduce this block's own (L2-hot) tile
    if (statoff >= 0) {
        __syncthreads();  // make all tile stores visible block-wide
        int c = tid & 127, rh = tid >> 7;
        const float* cp = C + (size_t)(row0 + rh * 64) * Nn + col0 + c;
        float s = 0.f, q = 0.f;
#pragma unroll 4
        for (int r = 0; r < 64; r++) {
            float v = cp[(size_t)r * Nn];
            s += v;
            q += v * v;
        }
        red[rh][c][0] = s;
        red[rh][c][1] = q;
        __syncthreads();
        if (rh == 0) {
            s += red[1][c][0];
            q += red[1][c][1];
            atomicAdd(&g_bnsum[statoff + col0 + c], s);
            atomicAdd(&g_bnsq[statoff + col0 + c], q);
        }
    }
}

// ---------------- layer-4 GCN gather with fused BN3+ReLU -------------------
__global__ __launch_bounds__(256) void k_gcn_agg4_bn(
    const float* __restrict__ C3,
    const float* __restrict__ gam, const float* __restrict__ bet,
    float* __restrict__ out)
{
    int tid = threadIdx.x;
    int d = blockIdx.x * 4 + (tid >> 6);
    int t = tid & 63;
    int st = g_rowptr[d], deg = g_rowptr[d + 1] - st;
    float disd = g_dis[d];
    float sc[4], sh[4];
    float inv_n = 1.0f / (float)NN;
#pragma unroll
    for (int j = 0; j < 4; j++) {
        int c = t * 4 + j;
        float mean = g_bnsum[1024 + c] * inv_n;
        float var = g_bnsq[1024 + c] * inv_n - mean * mean;
        float s = rsqrtf(var + BN_EPS) * gam[c];
        sc[j] = s;
        sh[j] = bet[c] - mean * s;
    }
    const float4* in4 = (const float4*)C3;
    float4 a = make_float4(0.f, 0.f, 0.f, 0.f);
    int i = 0;
    for (; i + 2 <= deg; i += 2) {
        int s0 = g_csr[st + i], s1 = g_csr[st + i + 1];
        float w0 = g_dis[s0], w1 = g_dis[s1];
        float4 v0 = in4[(size_t)s0 * 64 + t];
        float4 v1 = in4[(size_t)s1 * 64 + t];
        a.x += fmaxf(fmaf(v0.x, sc[0], sh[0]), 0.f) * w0 + fmaxf(fmaf(v1.x, sc[0], sh[0]), 0.f) * w1;
        a.y += fmaxf(fmaf(v0.y, sc[1], sh[1]), 0.f) * w0 + fmaxf(fmaf(v1.y, sc[1], sh[1]), 0.f) * w1;
        a.z += fmaxf(fmaf(v0.z, sc[2], sh[2]), 0.f) * w0 + fmaxf(fmaf(v1.z, sc[2], sh[2]), 0.f) * w1;
        a.w += fmaxf(fmaf(v0.w, sc[3], sh[3]), 0.f) * w0 + fmaxf(fmaf(v1.w, sc[3], sh[3]), 0.f) * w1;
    }
    if (i < deg) {
        int s0 = g_csr[st + i];
        float w0 = g_dis[s0];
        float4 v0 = in4[(size_t)s0 * 64 + t];
        a.x += fmaxf(fmaf(v0.x, sc[0], sh[0]), 0.f) * w0;
        a.y += fmaxf(fmaf(v0.y, sc[1], sh[1]), 0.f) * w0;
        a.z += fmaxf(fmaf(v0.z, sc[2], sh[2]), 0.f) * w0;
        a.w += fmaxf(fmaf(v0.w, sc[3], sh[3]), 0.f) * w0;
    }
    float4 v = in4[(size_t)d * 64 + t];
    a.x += fmaxf(fmaf(v.x, sc[0], sh[0]), 0.f) * disd;
    a.y += fmaxf(fmaf(v.y, sc[1], sh[1]), 0.f) * disd;
    a.z += fmaxf(fmaf(v.z, sc[2], sh[2]), 0.f) * disd;
    a.w += fmaxf(fmaf(v.w, sc[3], sh[3]), 0.f) * disd;
    a.x *= disd; a.y *= disd; a.z *= disd; a.w *= disd;
    ((float4*)out)[(size_t)d * 64 + t] = a;
}

// ---------------- SAGE mean aggregation, warp/node --------------------------
__global__ void k_sage_agg(float* __restrict__ P) {
    int w = threadIdx.x >> 5;
    int d = blockIdx.x * 8 + w;
    int lane = threadIdx.x & 31;
    int st = g_rowptr[d], deg = g_rowptr[d + 1] - st;
    int half = lane >> 4;
    int c4 = (lane & 15) + 16;
    const float4* P4 = (const float4*)P;
    float4 a = make_float4(0.f, 0.f, 0.f, 0.f);
    for (int i = 0; i < deg; i += 2) {
        int idx = i + half;
        if (idx < deg) {
            int s = g_csr[st + idx];
            float4 v = P4[(size_t)s * 32 + c4];
            a.x += v.x; a.y += v.y; a.z += v.z; a.w += v.w;
        }
    }
    a.x += __shfl_xor_sync(0xffffffffu, a.x, 16);
    a.y += __shfl_xor_sync(0xffffffffu, a.y, 16);
    a.z += __shfl_xor_sync(0xffffffffu, a.z, 16);
    a.w += __shfl_xor_sync(0xffffffffu, a.w, 16);
    if (lane < 16) {
        float inv = 1.f / (float)max(deg, 1);
        ((float4*)P)[(size_t)d * 32 + lane] =
            make_float4(a.x * inv, a.y * inv, a.z * inv, a.w * inv);
    }
}

// ---------------- BN apply (layer 1 -> packed) ------------------------------
__global__ void k_bn_apply4(const float* __restrict__ in, const float* __restrict__ gam,
                            const float* __restrict__ bet, float* __restrict__ out,
                            int C4, int statoff, int ostride4, int ooff4)
{
    int idx = blockIdx.x * blockDim.x + threadIdx.x;
    int c4 = idx % C4;
    int row = idx / C4;
    float4 v = ((const float4*)in)[idx];
    float inv_n = 1.0f / (float)NN;
    float r[4] = {v.x, v.y, v.z, v.w};
#pragma unroll
    for (int j = 0; j < 4; j++) {
        int c = c4 * 4 + j;
        float mean = g_bnsum[statoff + c] * inv_n;
        float var = g_bnsq[statoff + c] * inv_n - mean * mean;
        float y = (r[j] - mean) * rsqrtf(var + BN_EPS) * gam[c] + bet[c];
        r[j] = fmaxf(y, 0.f);
    }
    ((float4*)out)[(size_t)row * ostride4 + ooff4 + c4] =
        make_float4(r[0], r[1], r[2], r[3]);
}

// ---------------- BN2 apply + es/ed fused ------------------------------------
// warp = one row (32 lanes x float4 = 128 ch). Writes D and g_es/g_ed.
__global__ __launch_bounds__(256) void k_bn2_esed(
    const float* __restrict__ C2, const float* __restrict__ gam,
    const float* __restrict__ bet, float* __restrict__ D)
{
    __shared__ float swa[1024];
    int tid = threadIdx.x;
    for (int t = tid; t < 1024; t += 256) swa[t] = g_wa[t];
    __syncthreads();
    int w = tid >> 5, lane = tid & 31;
    int n = blockIdx.x * 8 + w;
    float4 v = ((const float4*)C2)[(size_t)n * 32 + lane];
    float inv_n = 1.0f / (float)NN;
    float r[4] = {v.x, v.y, v.z, v.w};
#pragma unroll
    for (int j = 0; j < 4; j++) {
        int c = lane * 4 + j;
        float mean = g_bnsum[512 + c] * inv_n;
        float var = g_bnsq[512 + c] * inv_n - mean * mean;
        float y = (r[j] - mean) * rsqrtf(var + BN_EPS) * gam[c] + bet[c];
        r[j] = fmaxf(y, 0.f);
    }
    ((float4*)D)[(size_t)n * 32 + lane] = make_float4(r[0], r[1], r[2], r[3]);

    float p[8];
#pragma unroll
    for (int s = 0; s < 2; s++)
#pragma unroll
        for (int h = 0; h < 4; h++) {
            float4 wv = ((const float4*)swa)[(s * 512 + h * 128) / 4 + lane];
            p[s * 4 + h] = r[0] * wv.x + r[1] * wv.y + r[2] * wv.z + r[3] * wv.w;
        }
#pragma unroll
    for (int o = 16; o > 0; o >>= 1)
#pragma unroll
        for (int j = 0; j < 8; j++)
            p[j] += __shfl_xor_sync(0xffffffffu, p[j], o);
    if (lane < 4) g_es[n * 4 + lane] = p[lane];
    else if (lane < 8) g_ed[n * 4 + (lane - 4)] = p[lane];
}

__device__ __forceinline__ float leaky02(float x) { return x > 0.f ? x : 0.2f * x; }

// ---------------- warp-autonomous GAT aggregation ----------------------------
__global__ __launch_bounds__(256) void k_gat_agg(const float* __restrict__ D,
                                                 float* __restrict__ agg)
{
    int warp = threadIdx.x >> 5;
    int lane = threadIdx.x & 31;
    int d = blockIdx.x * 2 + (warp >> 2);
    int h = warp & 3;
    int st = g_rowptr[d], deg = g_rowptr[d + 1] - st;
    float edv = g_ed[d * 4 + h];
    float eself = leaky02(g_es[d * 4 + h] + edv);

    float m = eself;
    for (int i = lane; i < deg; i += 32)
        m = fmaxf(m, leaky02(g_es[g_csr[st + i] * 4 + h] + edv));
#pragma unroll
    for (int o = 16; o > 0; o >>= 1) m = fmaxf(m, __shfl_xor_sync(0xffffffffu, m, o));
    float z = (lane == 0) ? __expf(eself - m) : 0.f;
    for (int i = lane; i < deg; i += 32)
        z += __expf(leaky02(g_es[g_csr[st + i] * 4 + h] + edv) - m);
#pragma unroll
    for (int o = 16; o > 0; o >>= 1) z += __shfl_xor_sync(0xffffffffu, z, o);
    float invz = 1.f / z;

    const float4* D4 = (const float4*)D;
    float4 acc = make_float4(0.f, 0.f, 0.f, 0.f);
    int i = 0;
    for (; i + 2 <= deg; i += 2) {
        int s0 = g_csr[st + i], s1 = g_csr[st + i + 1];
        float a0 = __expf(leaky02(g_es[s0 * 4 + h] + edv) - m) * invz;
        float a1 = __expf(leaky02(g_es[s1 * 4 + h] + edv) - m) * invz;
        float4 v0 = D4[(size_t)s0 * 32 + lane];
        float4 v1 = D4[(size_t)s1 * 32 + lane];
        acc.x += v0.x * a0 + v1.x * a1;
        acc.y += v0.y * a0 + v1.y * a1;
        acc.z += v0.z * a0 + v1.z * a1;
        acc.w += v0.w * a0 + v1.w * a1;
    }
    if (i < deg) {
        int s0 = g_csr[st + i];
        float a0 = __expf(leaky02(g_es[s0 * 4 + h] + edv) - m) * invz;
        float4 v0 = D4[(size_t)s0 * 32 + lane];
        acc.x += v0.x * a0; acc.y += v0.y * a0; acc.z += v0.z * a0; acc.w += v0.w * a0;
    }
    {
        float a0 = __expf(eself - m) * invz;
        float4 v0 = D4[(size_t)d * 32 + lane];
        acc.x += v0.x * a0; acc.y += v0.y * a0; acc.z += v0.z * a0; acc.w += v0.w * a0;
    }
    ((float4*)agg)[(size_t)d * 128 + h * 32 + lane] = acc;
}

// ---------------- pooling (fused BN4+ReLU) + FC -----------------------------
__global__ void k_pool_bn(const float* __restrict__ C4buf,
                          const float* __restrict__ gam, const float* __restrict__ bet)
{
    int g = blockIdx.x;
    int c4 = threadIdx.x;  // 128
    int st = g_gstart[g], en = g_gstart[g + 1];
    int cnt = en - st;
    float sc[4], sh[4];
    float inv_n = 1.0f / (float)NN;
#pragma unroll
    for (int j = 0; j < 4; j++) {
        int c = c4 * 4 + j;
        float mean = g_bnsum[1536 + c] * inv_n;
        float var = g_bnsq[1536 + c] * inv_n - mean * mean;
        float s = rsqrtf(var + BN_EPS) * gam[c];
        sc[j] = s;
        sh[j] = bet[c] - mean * s;
    }
    const float4* D4 = (const float4*)C4buf;
    float4 s = make_float4(0.f, 0.f, 0.f, 0.f);
    float4 m = make_float4(-3.4e38f, -3.4e38f, -3.4e38f, -3.4e38f);
    for (int i = st; i < en; i++) {
        float4 v = D4[(size_t)i * 128 + c4];
        v.x = fmaxf(fmaf(v.x, sc[0], sh[0]), 0.f);
        v.y = fmaxf(fmaf(v.y, sc[1], sh[1]), 0.f);
        v.z = fmaxf(fmaf(v.z, sc[2], sh[2]), 0.f);
        v.w = fmaxf(fmaf(v.w, sc[3], sh[3]), 0.f);
        s.x += v.x; s.y += v.y; s.z += v.z; s.w += v.w;
        m.x = fmaxf(m.x, v.x); m.y = fmaxf(m.y, v.y);
        m.z = fmaxf(m.z, v.z); m.w = fmaxf(m.w, v.w);
    }
    float inv = 1.f / (float)max(cnt, 1);
    float4* P4 = (float4*)g_pooled;
    P4[g * 256 + c4] = make_float4(s.x * inv, s.y * inv, s.z * inv, s.w * inv);
    if (cnt <= 0) m = make_float4(0.f, 0.f, 0.f, 0.f);
    P4[g * 256 + 128 + c4] = m;
}

__global__ __launch_bounds__(128) void k_fc(const float* __restrict__ W,
                                            const float* __restrict__ bias,
                                            float* __restrict__ out)
{
    __shared__ float sp[4][1024];
    int tid = threadIdx.x;
    int j = blockIdx.x * 128 + tid;
    int g0 = blockIdx.y * 4;
    for (int t = tid; t < 4 * 1024; t += 128)
        sp[t >> 10][t & 1023] = g_pooled[(g0 + (t >> 10)) * 1024 + (t & 1023)];
    __syncthreads();
    float acc[4] = {0.f, 0.f, 0.f, 0.f};
#pragma unroll 4
    for (int kk = 0; kk < 1024; kk++) {
        float wv = W[(size_t)kk * 1024 + j];
#pragma unroll
        for (int g = 0; g < 4; g++) acc[g] += sp[g][kk] * wv;
    }
    float bv = bias[j];
#pragma unroll
    for (int g = 0; g < 4; g++) out[(size_t)(g0 + g) * 1024 + j] = acc[g] + bv;
}

// ---------------- host orchestration ---------------------------------------
extern "C" void kernel_launch(void* const* d_in, const int* in_sizes, int n_in,
                              void* d_out, int out_size)
{
    const float* x        = (const float*)d_in[0];
    const int*   ei       = (const int*)  d_in[1];
    const int*   batch    = (const int*)  d_in[2];
    const float* gcn1_w   = (const float*)d_in[3];
    const float* sage_wl  = (const float*)d_in[5];
    const float* sage_wr  = (const float*)d_in[6];
    const float* gat_w    = (const float*)d_in[8];
    const float* gat_asrc = (const float*)d_in[9];
    const float* gat_adst = (const float*)d_in[10];
    const float* gcn4_w   = (const float*)d_in[12];
    const float* bn1_g = (const float*)d_in[14]; const float* bn1_b = (const float*)d_in[15];
    const float* bn2_g = (const float*)d_in[16]; const float* bn2_b = (const float*)d_in[17];
    const float* bn3_g = (const float*)d_in[18]; const float* bn3_b = (const float*)d_in[19];
    const float* bn4_g = (const float*)d_in[20]; const float* bn4_b = (const float*)d_in[21];
    const float* fc_w  = (const float*)d_in[22]; const float* fc_b  = (const float*)d_in[23];
    float* out = (float*)d_out;

    const int* src = ei;
    const int* dst = ei + EE;

    float *A, *B, *C, *D;
    cudaGetSymbolAddress((void**)&A, g_bufA);
    cudaGetSymbolAddress((void**)&B, g_bufB);
    cudaGetSymbolAddress((void**)&C, g_bufC);
    cudaGetSymbolAddress((void**)&D, g_bufD);

    // setup (zero + wa + gstart) and graph build
    k_setup<<<69, 256>>>(gat_w, gat_asrc, gat_adst, batch);
    k_deg<<<EE / 256, 256>>>(dst);
    k_scan<<<1, 512>>>();
    k_csr_fill<<<EE / 256, 256>>>(src, dst);

    // ---- layer 1: fused gather + GEMV + BN stats ----
    k_l1<<<NN / 8, 256>>>(x, gcn1_w, C);
    k_bn_apply4<<<NN * 16 / 256, 256>>>(C, bn1_g, bn1_b, B, 16, 0, 32, 16);

    // ---- layer 2: SAGE(64->128), fused single GEMM + stats ----
    k_sage_agg<<<NN / 8, 256>>>(B);
    k_gemm_tf32<<<dim3(1, NN / 128), 256>>>(B, sage_wl, sage_wr, 64, C, NN, 128, 128, 0, 512);
    k_bn2_esed<<<NN / 8, 256>>>(C, bn2_g, bn2_b, D);

    // ---- layer 3: GAT aggregate-then-transform + stats ----
    k_gat_agg<<<NN / 2, 256>>>(D, A);
    k_gemm_tf32<<<dim3(2, NN / 128), 256>>>(A, gat_w, nullptr, 0, C, NN, 512, 256, 1, 1024);

    // ---- layer 4: GCN with fused BN3 gather, GEMM + stats ----
    k_gcn_agg4_bn<<<NN / 4, 256>>>(C, bn3_g, bn3_b, B);
    k_gemm_tf32<<<dim3(4, NN / 128), 256>>>(B, gcn4_w, gcn4_w, 256, C, NN, 256, 512, 0, 1536);

    // ---- pooling (BN4 fused) + FC ----
    k_pool_bn<<<GG, 128>>>(C, bn4_g, bn4_b);
    k_fc<<<dim3(8, 8), 128>>>(fc_w, fc_b, out);
}

// round 10
// speedup vs baseline: 2.1960x; 1.2188x over previous
#include <cuda_runtime.h>
#include <cuda_fp16.h>
#include <mma.h>
#include <math.h>

using namespace nvcuda;

#define NN 16384
#define EE 131072
#define GG 32
#define BN_EPS 1e-5f

// ---------------- scratch (device globals: no allocation allowed) ----------
__device__ float g_bufA[NN * 512];    // GAT per-head agg [N,512] (32 MB)
__device__ float g_bufB[NN * 512];    // xa / packed sage / agg   (32 MB)
__device__ float g_bufC[NN * 512];    // pre-BN buffers           (32 MB)
__device__ float g_bufD[NN * 512];    // post-BN layer2 output    (32 MB)
__device__ float g_es[NN * 4];
__device__ float g_ed[NN * 4];
__device__ int   g_deg[NN];
__device__ int   g_rowptr[NN + 1];
__device__ int   g_cursor[NN];
__device__ int   g_csr[EE];
__device__ float g_dis[NN];
__device__ float g_bnsum[2048];       // layers at offsets 0,512,1024,1536
__device__ float g_bnsq[2048];
__device__ float g_wa[1024];          // [sel(2)][head(4)][k(128)]
__device__ float g_pooled[GG * 1024];
__device__ int   g_gstart[GG + 1];

// ---------------- fused setup: zero + wa projection + gstart ----------------
__global__ void k_setup(const float* __restrict__ gat_w,
                        const float* __restrict__ asrc, const float* __restrict__ adst,
                        const int* __restrict__ batch)
{
    int b = blockIdx.x;
    int tid = threadIdx.x;
    if (b < 64) {
        int i = b * 256 + tid;
        g_deg[i] = 0;
        g_cursor[i] = 0;
        if (i < 2048) { g_bnsum[i] = 0.f; g_bnsq[i] = 0.f; }
    } else if (b < 68) {
        int sub = (b - 64) * 2 + (tid >> 7);   // 0..7
        int k = tid & 127;
        int sel = sub >> 2, h = sub & 3;
        const float* a = (sel == 0) ? asrc : adst;
        float s = 0.f;
        for (int c = 0; c < 256; c++)
            s += gat_w[(size_t)k * 1024 + h * 256 + c] * a[h * 256 + c];
        g_wa[sel * 512 + h * 128 + k] = s;
    } else {
        int g = tid;
        if (g <= GG) {
            int lo = 0, hi = NN;
            while (lo < hi) {
                int mid = (lo + hi) >> 1;
                if (batch[mid] < g) lo = mid + 1;
                else hi = mid;
            }
            g_gstart[g] = lo;
        }
    }
}

__global__ void k_deg(const int* __restrict__ dst) {
    int e = blockIdx.x * blockDim.x + threadIdx.x;
    if (e < EE) atomicAdd(&g_deg[dst[e]], 1);
}

// exclusive scan of g_deg -> g_rowptr ; also writes g_dis (1024 threads)
__global__ void k_scan() {
    __shared__ int sh[1024];
    int tid = threadIdx.x;
    int base = tid * 16;
    int s = 0;
    for (int i = 0; i < 16; i++) s += g_deg[base + i];
    sh[tid] = s;
    __syncthreads();
    for (int off = 1; off < 1024; off <<= 1) {
        int v = (tid >= off) ? sh[tid - off] : 0;
        __syncthreads();
        sh[tid] += v;
        __syncthreads();
    }
    int run = sh[tid] - s;
    for (int i = 0; i < 16; i++) {
        int dg = g_deg[base + i];
        g_rowptr[base + i] = run;
        g_dis[base + i] = rsqrtf((float)dg + 1.0f);
        run += dg;
    }
    if (tid == 1023) g_rowptr[NN] = sh[1023];
}

__global__ void k_csr_fill(const int* __restrict__ src, const int* __restrict__ dst) {
    int e = blockIdx.x * blockDim.x + threadIdx.x;
    if (e < EE) {
        int d = dst[e];
        int pos = g_rowptr[d] + atomicAdd(&g_cursor[d], 1);
        g_csr[pos] = src[e];
    }
}

// ---------------- layer 1 fully fused: gather(5ch) + 5x64 GEMV + BN stats ---
__global__ __launch_bounds__(256) void k_l1(const float* __restrict__ x,
                                            const float* __restrict__ W,
                                            float* __restrict__ C)
{
    __shared__ float sW[320];
    __shared__ float ssum[64], ssq[64];
    int tid = threadIdx.x;
    for (int t = tid; t < 320; t += 256) sW[t] = W[t];
    if (tid < 64) { ssum[tid] = 0.f; ssq[tid] = 0.f; }
    __syncthreads();

    int w = tid >> 5, lane = tid & 31;
    int d = blockIdx.x * 8 + w;
    int st = g_rowptr[d], deg = g_rowptr[d + 1] - st;
    float disd = g_dis[d];
    float a = 0.f;
    for (int i = 0; i < deg; i++) {
        int s = g_csr[st + i];
        float wt = g_dis[s];
        if (lane < 5) a += x[s * 5 + lane] * wt;
    }
    if (lane < 5) a = (a + x[d * 5 + lane] * disd) * disd;
    float xa0 = __shfl_sync(0xffffffffu, a, 0);
    float xa1 = __shfl_sync(0xffffffffu, a, 1);
    float xa2 = __shfl_sync(0xffffffffu, a, 2);
    float xa3 = __shfl_sync(0xffffffffu, a, 3);
    float xa4 = __shfl_sync(0xffffffffu, a, 4);

    int c0 = lane, c1 = lane + 32;
    float h0 = xa0 * sW[c0] + xa1 * sW[64 + c0] + xa2 * sW[128 + c0]
             + xa3 * sW[192 + c0] + xa4 * sW[256 + c0];
    float h1 = xa0 * sW[c1] + xa1 * sW[64 + c1] + xa2 * sW[128 + c1]
             + xa3 * sW[192 + c1] + xa4 * sW[256 + c1];
    C[(size_t)d * 64 + c0] = h0;
    C[(size_t)d * 64 + c1] = h1;
    atomicAdd(&ssum[c0], h0); atomicAdd(&ssq[c0], h0 * h0);
    atomicAdd(&ssum[c1], h1); atomicAdd(&ssq[c1], h1 * h1);
    __syncthreads();
    if (tid < 64) {
        atomicAdd(&g_bnsum[tid], ssum[tid]);
        atomicAdd(&g_bnsq[tid], ssq[tid]);
    }
}

// ---------------- FP16 tensor-core GEMM + fused BN-stat epilogue ------------
// fp16 mantissa (11 bits) == tf32 mantissa; all inputs O(1) -> same accuracy.
// m16n16k16 wmma: half the MMA + frag-load count of the tf32 version.
__device__ __forceinline__ void st_half4(__half* p, float4 v) {
    ((__half2*)p)[0] = __floats2half2_rn(v.x, v.y);
    ((__half2*)p)[1] = __floats2half2_rn(v.z, v.w);
}

__global__ __launch_bounds__(256, 2) void k_gemm_f16(
    const float* __restrict__ A,
    const float* __restrict__ W1, const float* __restrict__ W2, int ksplit,
    float* __restrict__ C, int M, int K, int Nn, int gatmode, int statoff)
{
    __shared__ __half As[128][24];   // 16 k + pad (stride 24 halfs = 48 B)
    __shared__ __half Bs[16][136];   // 128 cols + pad (stride 136 halfs)
    __shared__ float red[2][128][2];

    int tid = threadIdx.x;
    int warp = tid >> 5;
    int wm = warp >> 2;              // 0..1
    int wn = warp & 3;               // 0..3
    int row0 = blockIdx.y * 128, col0 = blockIdx.x * 128;

    int a_r[2], a_c[2];
#pragma unroll
    for (int i = 0; i < 2; i++) {
        int s = tid * 2 + i;
        a_r[i] = s >> 2;
        a_c[i] = (s & 3) * 4;
    }
    int b_r[2], b_c[2];
#pragma unroll
    for (int i = 0; i < 2; i++) {
        int s = tid + 256 * i;
        b_r[i] = s >> 5;
        b_c[i] = (s & 31) * 4;
    }

    const float* Abase = A + (size_t)row0 * K;

    float4 cA[2], cB[2];
#pragma unroll
    for (int i = 0; i < 2; i++) {
        cA[i] = *(const float4*)(Abase + (size_t)a_r[i] * K + a_c[i]);
        int k = b_r[i];
        const float* wp;
        if (gatmode) wp = W1 + (size_t)(k & 127) * 1024 + (k >> 7) * 256;
        else wp = (k < ksplit) ? (W1 + (size_t)k * Nn)
                               : (W2 + (size_t)(k - ksplit) * Nn);
        cB[i] = *(const float4*)(wp + col0 + b_c[i]);
    }

    wmma::fragment<wmma::accumulator, 16, 16, 16, float> acc[4][2];
#pragma unroll
    for (int i = 0; i < 4; i++)
#pragma unroll
        for (int j = 0; j < 2; j++) wmma::fill_fragment(acc[i][j], 0.f);

    for (int k0 = 0; k0 < K; k0 += 16) {
#pragma unroll
        for (int i = 0; i < 2; i++) {
            st_half4(&As[a_r[i]][a_c[i]], cA[i]);
            st_half4(&Bs[b_r[i]][b_c[i]], cB[i]);
        }
        __syncthreads();
        if (k0 + 16 < K) {
#pragma unroll
            for (int i = 0; i < 2; i++) {
                cA[i] = *(const float4*)(Abase + (size_t)a_r[i] * K + (k0 + 16) + a_c[i]);
                int k = k0 + 16 + b_r[i];
                const float* wp;
                if (gatmode) wp = W1 + (size_t)(k & 127) * 1024 + (k >> 7) * 256;
                else wp = (k < ksplit) ? (W1 + (size_t)k * Nn)
                                       : (W2 + (size_t)(k - ksplit) * Nn);
                cB[i] = *(const float4*)(wp + col0 + b_c[i]);
            }
        }
        {
            wmma::fragment<wmma::matrix_a, 16, 16, 16, __half, wmma::row_major> af[4];
            wmma::fragment<wmma::matrix_b, 16, 16, 16, __half, wmma::row_major> bf[2];
#pragma unroll
            for (int i = 0; i < 4; i++)
                wmma::load_matrix_sync(af[i], &As[wm * 64 + i * 16][0], 24);
#pragma unroll
            for (int j = 0; j < 2; j++)
                wmma::load_matrix_sync(bf[j], &Bs[0][wn * 32 + j * 16], 136);
#pragma unroll
            for (int i = 0; i < 4; i++)
#pragma unroll
                for (int j = 0; j < 2; j++)
                    wmma::mma_sync(acc[i][j], af[i], bf[j], acc[i][j]);
        }
        __syncthreads();
    }

#pragma unroll
    for (int i = 0; i < 4; i++)
#pragma unroll
        for (int j = 0; j < 2; j++) {
            int gr = row0 + wm * 64 + i * 16;
            int gc = col0 + wn * 32 + j * 16;
            wmma::store_matrix_sync(C + (size_t)gr * Nn + gc, acc[i][j], Nn,
                                    wmma::mem_row_major);
        }

    // fused BN-stat epilogue: reduce this block's own (L2-hot) tile
    if (statoff >= 0) {
        __syncthreads();  // make all tile stores visible block-wide
        int c = tid & 127, rh = tid >> 7;
        const float* cp = C + (size_t)(row0 + rh * 64) * Nn + col0 + c;
        float s = 0.f, q = 0.f;
#pragma unroll 4
        for (int r = 0; r < 64; r++) {
            float v = cp[(size_t)r * Nn];
            s += v;
            q += v * v;
        }
        red[rh][c][0] = s;
        red[rh][c][1] = q;
        __syncthreads();
        if (rh == 0) {
            s += red[1][c][0];
            q += red[1][c][1];
            atomicAdd(&g_bnsum[statoff + col0 + c], s);
            atomicAdd(&g_bnsq[statoff + col0 + c], q);
        }
    }
}

// ---------------- layer-4 GCN gather with fused BN3+ReLU -------------------
__global__ __launch_bounds__(256) void k_gcn_agg4_bn(
    const float* __restrict__ C3,
    const float* __restrict__ gam, const float* __restrict__ bet,
    float* __restrict__ out)
{
    int tid = threadIdx.x;
    int d = blockIdx.x * 4 + (tid >> 6);
    int t = tid & 63;
    int st = g_rowptr[d], deg = g_rowptr[d + 1] - st;
    float disd = g_dis[d];
    float sc[4], sh[4];
    float inv_n = 1.0f / (float)NN;
#pragma unroll
    for (int j = 0; j < 4; j++) {
        int c = t * 4 + j;
        float mean = g_bnsum[1024 + c] * inv_n;
        float var = g_bnsq[1024 + c] * inv_n - mean * mean;
        float s = rsqrtf(var + BN_EPS) * gam[c];
        sc[j] = s;
        sh[j] = bet[c] - mean * s;
    }
    const float4* in4 = (const float4*)C3;
    float4 a = make_float4(0.f, 0.f, 0.f, 0.f);
    int i = 0;
    for (; i + 2 <= deg; i += 2) {
        int s0 = g_csr[st + i], s1 = g_csr[st + i + 1];
        float w0 = g_dis[s0], w1 = g_dis[s1];
        float4 v0 = in4[(size_t)s0 * 64 + t];
        float4 v1 = in4[(size_t)s1 * 64 + t];
        a.x += fmaxf(fmaf(v0.x, sc[0], sh[0]), 0.f) * w0 + fmaxf(fmaf(v1.x, sc[0], sh[0]), 0.f) * w1;
        a.y += fmaxf(fmaf(v0.y, sc[1], sh[1]), 0.f) * w0 + fmaxf(fmaf(v1.y, sc[1], sh[1]), 0.f) * w1;
        a.z += fmaxf(fmaf(v0.z, sc[2], sh[2]), 0.f) * w0 + fmaxf(fmaf(v1.z, sc[2], sh[2]), 0.f) * w1;
        a.w += fmaxf(fmaf(v0.w, sc[3], sh[3]), 0.f) * w0 + fmaxf(fmaf(v1.w, sc[3], sh[3]), 0.f) * w1;
    }
    if (i < deg) {
        int s0 = g_csr[st + i];
        float w0 = g_dis[s0];
        float4 v0 = in4[(size_t)s0 * 64 + t];
        a.x += fmaxf(fmaf(v0.x, sc[0], sh[0]), 0.f) * w0;
        a.y += fmaxf(fmaf(v0.y, sc[1], sh[1]), 0.f) * w0;
        a.z += fmaxf(fmaf(v0.z, sc[2], sh[2]), 0.f) * w0;
        a.w += fmaxf(fmaf(v0.w, sc[3], sh[3]), 0.f) * w0;
    }
    float4 v = in4[(size_t)d * 64 + t];
    a.x += fmaxf(fmaf(v.x, sc[0], sh[0]), 0.f) * disd;
    a.y += fmaxf(fmaf(v.y, sc[1], sh[1]), 0.f) * disd;
    a.z += fmaxf(fmaf(v.z, sc[2], sh[2]), 0.f) * disd;
    a.w += fmaxf(fmaf(v.w, sc[3], sh[3]), 0.f) * disd;
    a.x *= disd; a.y *= disd; a.z *= disd; a.w *= disd;
    ((float4*)out)[(size_t)d * 64 + t] = a;
}

// ---------------- SAGE mean aggregation, warp/node --------------------------
__global__ void k_sage_agg(float* __restrict__ P) {
    int w = threadIdx.x >> 5;
    int d = blockIdx.x * 8 + w;
    int lane = threadIdx.x & 31;
    int st = g_rowptr[d], deg = g_rowptr[d + 1] - st;
    int half = lane >> 4;
    int c4 = (lane & 15) + 16;
    const float4* P4 = (const float4*)P;
    float4 a = make_float4(0.f, 0.f, 0.f, 0.f);
    for (int i = 0; i < deg; i += 2) {
        int idx = i + half;
        if (idx < deg) {
            int s = g_csr[st + idx];
            float4 v = P4[(size_t)s * 32 + c4];
            a.x += v.x; a.y += v.y; a.z += v.z; a.w += v.w;
        }
    }
    a.x += __shfl_xor_sync(0xffffffffu, a.x, 16);
    a.y += __shfl_xor_sync(0xffffffffu, a.y, 16);
    a.z += __shfl_xor_sync(0xffffffffu, a.z, 16);
    a.w += __shfl_xor_sync(0xffffffffu, a.w, 16);
    if (lane < 16) {
        float inv = 1.f / (float)max(deg, 1);
        ((float4*)P)[(size_t)d * 32 + lane] =
            make_float4(a.x * inv, a.y * inv, a.z * inv, a.w * inv);
    }
}

// ---------------- BN apply (layer 1 -> packed) ------------------------------
__global__ void k_bn_apply4(const float* __restrict__ in, const float* __restrict__ gam,
                            const float* __restrict__ bet, float* __restrict__ out,
                            int C4, int statoff, int ostride4, int ooff4)
{
    int idx = blockIdx.x * blockDim.x + threadIdx.x;
    int c4 = idx % C4;
    int row = idx / C4;
    float4 v = ((const float4*)in)[idx];
    float inv_n = 1.0f / (float)NN;
    float r[4] = {v.x, v.y, v.z, v.w};
#pragma unroll
    for (int j = 0; j < 4; j++) {
        int c = c4 * 4 + j;
        float mean = g_bnsum[statoff + c] * inv_n;
        float var = g_bnsq[statoff + c] * inv_n - mean * mean;
        float y = (r[j] - mean) * rsqrtf(var + BN_EPS) * gam[c] + bet[c];
        r[j] = fmaxf(y, 0.f);
    }
    ((float4*)out)[(size_t)row * ostride4 + ooff4 + c4] =
        make_float4(r[0], r[1], r[2], r[3]);
}

// ---------------- BN2 apply + es/ed fused ------------------------------------
__global__ __launch_bounds__(256) void k_bn2_esed(
    const float* __restrict__ C2, const float* __restrict__ gam,
    const float* __restrict__ bet, float* __restrict__ D)
{
    __shared__ float swa[1024];
    int tid = threadIdx.x;
    for (int t = tid; t < 1024; t += 256) swa[t] = g_wa[t];
    __syncthreads();
    int w = tid >> 5, lane = tid & 31;
    int n = blockIdx.x * 8 + w;
    float4 v = ((const float4*)C2)[(size_t)n * 32 + lane];
    float inv_n = 1.0f / (float)NN;
    float r[4] = {v.x, v.y, v.z, v.w};
#pragma unroll
    for (int j = 0; j < 4; j++) {
        int c = lane * 4 + j;
        float mean = g_bnsum[512 + c] * inv_n;
        float var = g_bnsq[512 + c] * inv_n - mean * mean;
        float y = (r[j] - mean) * rsqrtf(var + BN_EPS) * gam[c] + bet[c];
        r[j] = fmaxf(y, 0.f);
    }
    ((float4*)D)[(size_t)n * 32 + lane] = make_float4(r[0], r[1], r[2], r[3]);

    float p[8];
#pragma unroll
    for (int s = 0; s < 2; s++)
#pragma unroll
        for (int h = 0; h < 4; h++) {
            float4 wv = ((const float4*)swa)[(s * 512 + h * 128) / 4 + lane];
            p[s * 4 + h] = r[0] * wv.x + r[1] * wv.y + r[2] * wv.z + r[3] * wv.w;
        }
#pragma unroll
    for (int o = 16; o > 0; o >>= 1)
#pragma unroll
        for (int j = 0; j < 8; j++)
            p[j] += __shfl_xor_sync(0xffffffffu, p[j], o);
    if (lane < 4) g_es[n * 4 + lane] = p[lane];
    else if (lane < 8) g_ed[n * 4 + (lane - 4)] = p[lane];
}

__device__ __forceinline__ float leaky02(float x) { return x > 0.f ? x : 0.2f * x; }

// ---------------- warp-autonomous GAT aggregation ----------------------------
__global__ __launch_bounds__(256) void k_gat_agg(const float* __restrict__ D,
                                                 float* __restrict__ agg)
{
    int warp = threadIdx.x >> 5;
    int lane = threadIdx.x & 31;
    int d = blockIdx.x * 2 + (warp >> 2);
    int h = warp & 3;
    int st = g_rowptr[d], deg = g_rowptr[d + 1] - st;
    float edv = g_ed[d * 4 + h];
    float eself = leaky02(g_es[d * 4 + h] + edv);

    float m = eself;
    for (int i = lane; i < deg; i += 32)
        m = fmaxf(m, leaky02(g_es[g_csr[st + i] * 4 + h] + edv));
#pragma unroll
    for (int o = 16; o > 0; o >>= 1) m = fmaxf(m, __shfl_xor_sync(0xffffffffu, m, o));
    float z = (lane == 0) ? __expf(eself - m) : 0.f;
    for (int i = lane; i < deg; i += 32)
        z += __expf(leaky02(g_es[g_csr[st + i] * 4 + h] + edv) - m);
#pragma unroll
    for (int o = 16; o > 0; o >>= 1) z += __shfl_xor_sync(0xffffffffu, z, o);
    float invz = 1.f / z;

    const float4* D4 = (const float4*)D;
    float4 acc = make_float4(0.f, 0.f, 0.f, 0.f);
    int i = 0;
    for (; i + 2 <= deg; i += 2) {
        int s0 = g_csr[st + i], s1 = g_csr[st + i + 1];
        float a0 = __expf(leaky02(g_es[s0 * 4 + h] + edv) - m) * invz;
        float a1 = __expf(leaky02(g_es[s1 * 4 + h] + edv) - m) * invz;
        float4 v0 = D4[(size_t)s0 * 32 + lane];
        float4 v1 = D4[(size_t)s1 * 32 + lane];
        acc.x += v0.x * a0 + v1.x * a1;
        acc.y += v0.y * a0 + v1.y * a1;
        acc.z += v0.z * a0 + v1.z * a1;
        acc.w += v0.w * a0 + v1.w * a1;
    }
    if (i < deg) {
        int s0 = g_csr[st + i];
        float a0 = __expf(leaky02(g_es[s0 * 4 + h] + edv) - m) * invz;
        float4 v0 = D4[(size_t)s0 * 32 + lane];
        acc.x += v0.x * a0; acc.y += v0.y * a0; acc.z += v0.z * a0; acc.w += v0.w * a0;
    }
    {
        float a0 = __expf(eself - m) * invz;
        float4 v0 = D4[(size_t)d * 32 + lane];
        acc.x += v0.x * a0; acc.y += v0.y * a0; acc.z += v0.z * a0; acc.w += v0.w * a0;
    }
    ((float4*)agg)[(size_t)d * 128 + h * 32 + lane] = acc;
}

// ---------------- pooling (fused BN4+ReLU) + FC -----------------------------
__global__ void k_pool_bn(const float* __restrict__ C4buf,
                          const float* __restrict__ gam, const float* __restrict__ bet)
{
    int g = blockIdx.x;
    int c4 = threadIdx.x;  // 128
    int st = g_gstart[g], en = g_gstart[g + 1];
    int cnt = en - st;
    float sc[4], sh[4];
    float inv_n = 1.0f / (float)NN;
#pragma unroll
    for (int j = 0; j < 4; j++) {
        int c = c4 * 4 + j;
        float mean = g_bnsum[1536 + c] * inv_n;
        float var = g_bnsq[1536 + c] * inv_n - mean * mean;
        float s = rsqrtf(var + BN_EPS) * gam[c];
        sc[j] = s;
        sh[j] = bet[c] - mean * s;
    }
    const float4* D4 = (const float4*)C4buf;
    float4 s = make_float4(0.f, 0.f, 0.f, 0.f);
    float4 m = make_float4(-3.4e38f, -3.4e38f, -3.4e38f, -3.4e38f);
    for (int i = st; i < en; i++) {
        float4 v = D4[(size_t)i * 128 + c4];
        v.x = fmaxf(fmaf(v.x, sc[0], sh[0]), 0.f);
        v.y = fmaxf(fmaf(v.y, sc[1], sh[1]), 0.f);
        v.z = fmaxf(fmaf(v.z, sc[2], sh[2]), 0.f);
        v.w = fmaxf(fmaf(v.w, sc[3], sh[3]), 0.f);
        s.x += v.x; s.y += v.y; s.z += v.z; s.w += v.w;
        m.x = fmaxf(m.x, v.x); m.y = fmaxf(m.y, v.y);
        m.z = fmaxf(m.z, v.z); m.w = fmaxf(m.w, v.w);
    }
    float inv = 1.f / (float)max(cnt, 1);
    float4* P4 = (float4*)g_pooled;
    P4[g * 256 + c4] = make_float4(s.x * inv, s.y * inv, s.z * inv, s.w * inv);
    if (cnt <= 0) m = make_float4(0.f, 0.f, 0.f, 0.f);
    P4[g * 256 + 128 + c4] = m;
}

__global__ __launch_bounds__(128) void k_fc(const float* __restrict__ W,
                                            const float* __restrict__ bias,
                                            float* __restrict__ out)
{
    __shared__ float sp[4][1024];
    int tid = threadIdx.x;
    int j = blockIdx.x * 128 + tid;
    int g0 = blockIdx.y * 4;
    for (int t = tid; t < 4 * 1024; t += 128)
        sp[t >> 10][t & 1023] = g_pooled[(g0 + (t >> 10)) * 1024 + (t & 1023)];
    __syncthreads();
    float acc[4] = {0.f, 0.f, 0.f, 0.f};
#pragma unroll 4
    for (int kk = 0; kk < 1024; kk++) {
        float wv = W[(size_t)kk * 1024 + j];
#pragma unroll
        for (int g = 0; g < 4; g++) acc[g] += sp[g][kk] * wv;
    }
    float bv = bias[j];
#pragma unroll
    for (int g = 0; g < 4; g++) out[(size_t)(g0 + g) * 1024 + j] = acc[g] + bv;
}

// ---------------- host orchestration ---------------------------------------
extern "C" void kernel_launch(void* const* d_in, const int* in_sizes, int n_in,
                              void* d_out, int out_size)
{
    const float* x        = (const float*)d_in[0];
    const int*   ei       = (const int*)  d_in[1];
    const int*   batch    = (const int*)  d_in[2];
    const float* gcn1_w   = (const float*)d_in[3];
    const float* sage_wl  = (const float*)d_in[5];
    const float* sage_wr  = (const float*)d_in[6];
    const float* gat_w    = (const float*)d_in[8];
    const float* gat_asrc = (const float*)d_in[9];
    const float* gat_adst = (const float*)d_in[10];
    const float* gcn4_w   = (const float*)d_in[12];
    const float* bn1_g = (const float*)d_in[14]; const float* bn1_b = (const float*)d_in[15];
    const float* bn2_g = (const float*)d_in[16]; const float* bn2_b = (const float*)d_in[17];
    const float* bn3_g = (const float*)d_in[18]; const float* bn3_b = (const float*)d_in[19];
    const float* bn4_g = (const float*)d_in[20]; const float* bn4_b = (const float*)d_in[21];
    const float* fc_w  = (const float*)d_in[22]; const float* fc_b  = (const float*)d_in[23];
    float* out = (float*)d_out;

    const int* src = ei;
    const int* dst = ei + EE;

    float *A, *B, *C, *D;
    cudaGetSymbolAddress((void**)&A, g_bufA);
    cudaGetSymbolAddress((void**)&B, g_bufB);
    cudaGetSymbolAddress((void**)&C, g_bufC);
    cudaGetSymbolAddress((void**)&D, g_bufD);

    // setup (zero + wa + gstart) and graph build
    k_setup<<<69, 256>>>(gat_w, gat_asrc, gat_adst, batch);
    k_deg<<<EE / 256, 256>>>(dst);
    k_scan<<<1, 1024>>>();
    k_csr_fill<<<EE / 256, 256>>>(src, dst);

    // ---- layer 1: fused gather + GEMV + BN stats ----
    k_l1<<<NN / 8, 256>>>(x, gcn1_w, C);
    k_bn_apply4<<<NN * 16 / 256, 256>>>(C, bn1_g, bn1_b, B, 16, 0, 32, 16);

    // ---- layer 2: SAGE(64->128), fused single GEMM + stats ----
    k_sage_agg<<<NN / 8, 256>>>(B);
    k_gemm_f16<<<dim3(1, NN / 128), 256>>>(B, sage_wl, sage_wr, 64, C, NN, 128, 128, 0, 512);
    k_bn2_esed<<<NN / 8, 256>>>(C, bn2_g, bn2_b, D);

    // ---- layer 3: GAT aggregate-then-transform + stats ----
    k_gat_agg<<<NN / 2, 256>>>(D, A);
    k_gemm_f16<<<dim3(2, NN / 128), 256>>>(A, gat_w, nullptr, 0, C, NN, 512, 256, 1, 1024);

    // ---- layer 4: GCN with fused BN3 gather, GEMM + stats ----
    k_gcn_agg4_bn<<<NN / 4, 256>>>(C, bn3_g, bn3_b, B);
    k_gemm_f16<<<dim3(4, NN / 128), 256>>>(B, gcn4_w, gcn4_w, 256, C, NN, 256, 512, 0, 1536);

    // ---- pooling (BN4 fused) + FC ----
    k_pool_bn<<<GG, 128>>>(C, bn4_g, bn4_b);
    k_fc<<<dim3(8, 8), 128>>>(fc_w, fc_b, out);
}